// round 4
// baseline (speedup 1.0000x reference)
#include <cuda_runtime.h>
#include <cuda_bf16.h>
#include <cstdint>

#define D    128
#define NGc  10000
#define NUc  100000
#define NIc  20000
#define EGIc 400000
#define EGUc 400000

// ---------------- scratch (device globals; no allocation allowed) -------------
__device__ float4 g_acc_i[NGc * 32];
__device__ float4 g_acc_u[NGc * 32];
__device__ float4 g_acc2_i[NGc * 32];
__device__ float4 g_acc2_u[NGc * 32];
__device__ int    g_cnt_i[NGc];
__device__ int    g_cnt_u[NGc];
__device__ float  g_g1[NGc * D];
__device__ float  g_i1[NIc * D];
__device__ float  g_u1[NUc * D];
// int8 2-limb quantized operands for the final GEMM
__device__ int8_t g_A_hi[NGc * D];
__device__ int8_t g_A_lo[NGc * D];
__device__ float  g_A_rec[NGc];          // amax/16383  (multiply by this to descale)
__device__ int8_t g_B_hi[NIc * D];       // WpT quantized: [n][k]
__device__ int8_t g_B_lo[NIc * D];
__device__ float  g_B_rec[NIc];

// ---------------- scatter-sum: one warp per edge, float4 RED ------------------
__global__ void scatter_kernel(const int* __restrict__ grp, const int* __restrict__ nbr,
                               const float4* __restrict__ feat, float4* __restrict__ acc,
                               int* cnt, int E)
{
    int gw = (blockIdx.x * blockDim.x + threadIdx.x) >> 5;
    if (gw >= E) return;
    int lane = threadIdx.x & 31;
    int g = __ldg(grp + gw);
    int n = __ldg(nbr + gw);
    float4 v = __ldg(feat + (size_t)n * 32 + lane);
    atomicAdd(acc + (size_t)g * 32 + lane, v);
    if (cnt && lane == 0) atomicAdd(cnt + g, 1);
}

// ---------------- out = relu(x @ W + b), x: [M,128], W: [128,128] --------------
template <int R>
__global__ void lin_relu_kernel(const float* __restrict__ x, const float* __restrict__ W,
                                const float* __restrict__ b, float* __restrict__ out, int M)
{
    __shared__ float4 xs[R][32];
    int col = threadIdx.x;
    int r0 = blockIdx.x * R;
#pragma unroll
    for (int r = 0; r < R; r++) {
        int row = r0 + r;
        ((float*)xs[r])[col] = (row < M) ? x[(size_t)row * D + col] : 0.f;
    }
    __syncthreads();
    float acc[R];
#pragma unroll
    for (int r = 0; r < R; r++) acc[r] = 0.f;
#pragma unroll 4
    for (int kq = 0; kq < 32; kq++) {
        float w0 = W[(4 * kq + 0) * D + col];
        float w1 = W[(4 * kq + 1) * D + col];
        float w2 = W[(4 * kq + 2) * D + col];
        float w3 = W[(4 * kq + 3) * D + col];
#pragma unroll
        for (int r = 0; r < R; r++) {
            float4 xv = xs[r][kq];
            acc[r] += xv.x * w0 + xv.y * w1 + xv.z * w2 + xv.w * w3;
        }
    }
    float bb = b[col];
#pragma unroll
    for (int r = 0; r < R; r++) {
        int row = r0 + r;
        if (row < M) out[(size_t)row * D + col] = fmaxf(acc[r] + bb, 0.f);
    }
}

// ------- g1 = relu( (acc_i/cnt_i) @ Wi + (acc_u/cnt_u) @ Wu + bi + bu ) --------
template <int R>
__global__ void g1_kernel(const float* __restrict__ acc_i, const float* __restrict__ acc_u,
                          const int* __restrict__ cnt_i, const int* __restrict__ cnt_u,
                          const float* __restrict__ Wi, const float* __restrict__ Wu,
                          const float* __restrict__ bi, const float* __restrict__ bu,
                          float* __restrict__ out, int M)
{
    __shared__ float4 si[R][32];
    __shared__ float4 su[R][32];
    int col = threadIdx.x;
    int r0 = blockIdx.x * R;
#pragma unroll
    for (int r = 0; r < R; r++) {
        int row = r0 + r;
        int rr = row < M ? row : M - 1;
        float invi = 1.f / (float)max(cnt_i[rr], 1);
        float invu = 1.f / (float)max(cnt_u[rr], 1);
        ((float*)si[r])[col] = acc_i[(size_t)rr * D + col] * invi;
        ((float*)su[r])[col] = acc_u[(size_t)rr * D + col] * invu;
    }
    __syncthreads();
    float acc[R];
#pragma unroll
    for (int r = 0; r < R; r++) acc[r] = 0.f;
#pragma unroll 4
    for (int kq = 0; kq < 32; kq++) {
        float wi0 = Wi[(4 * kq + 0) * D + col], wi1 = Wi[(4 * kq + 1) * D + col];
        float wi2 = Wi[(4 * kq + 2) * D + col], wi3 = Wi[(4 * kq + 3) * D + col];
        float wu0 = Wu[(4 * kq + 0) * D + col], wu1 = Wu[(4 * kq + 1) * D + col];
        float wu2 = Wu[(4 * kq + 2) * D + col], wu3 = Wu[(4 * kq + 3) * D + col];
#pragma unroll
        for (int r = 0; r < R; r++) {
            float4 a = si[r][kq], u = su[r][kq];
            acc[r] += a.x * wi0 + a.y * wi1 + a.z * wi2 + a.w * wi3
                    + u.x * wu0 + u.y * wu1 + u.z * wu2 + u.w * wu3;
        }
    }
    float bb = bi[col] + bu[col];
#pragma unroll
    for (int r = 0; r < R; r++) {
        int row = r0 + r;
        if (row < M) out[(size_t)row * D + col] = fmaxf(acc[r] + bb, 0.f);
    }
}

// g2 = relu(...) -> quantized directly to int8 2-limb (row-max scaled)
template <int R>
__global__ void g2_kernel(const float* __restrict__ acc_i, const float* __restrict__ acc_u,
                          const float* __restrict__ g1,
                          const int* __restrict__ cnt_i, const int* __restrict__ cnt_u,
                          const float* __restrict__ Wi, const float* __restrict__ Wu,
                          const float* __restrict__ Wg1, const float* __restrict__ Wg2,
                          const float* __restrict__ bi, const float* __restrict__ bu,
                          int8_t* __restrict__ a_hi, int8_t* __restrict__ a_lo,
                          float* __restrict__ a_rec, int M)
{
    __shared__ float4 si[R][32];
    __shared__ float4 su[R][32];
    __shared__ float4 sg[R][32];
    __shared__ float red[R][4];
    int col = threadIdx.x;
    int lane = col & 31, wid = col >> 5;
    int r0 = blockIdx.x * R;
#pragma unroll
    for (int r = 0; r < R; r++) {
        int row = r0 + r;
        int rr = row < M ? row : M - 1;
        float invi = 1.f / (float)max(cnt_i[rr], 1);
        float invu = 1.f / (float)max(cnt_u[rr], 1);
        ((float*)si[r])[col] = acc_i[(size_t)rr * D + col] * invi;
        ((float*)su[r])[col] = acc_u[(size_t)rr * D + col] * invu;
        ((float*)sg[r])[col] = g1[(size_t)rr * D + col];
    }
    __syncthreads();
    float acc[R];
#pragma unroll
    for (int r = 0; r < R; r++) acc[r] = 0.f;
#pragma unroll 2
    for (int kq = 0; kq < 32; kq++) {
        float wi0 = Wi[(4 * kq + 0) * D + col], wi1 = Wi[(4 * kq + 1) * D + col];
        float wi2 = Wi[(4 * kq + 2) * D + col], wi3 = Wi[(4 * kq + 3) * D + col];
        float wu0 = Wu[(4 * kq + 0) * D + col], wu1 = Wu[(4 * kq + 1) * D + col];
        float wu2 = Wu[(4 * kq + 2) * D + col], wu3 = Wu[(4 * kq + 3) * D + col];
        float wg0 = Wg1[(4 * kq + 0) * D + col] + Wg2[(4 * kq + 0) * D + col];
        float wg1 = Wg1[(4 * kq + 1) * D + col] + Wg2[(4 * kq + 1) * D + col];
        float wg2 = Wg1[(4 * kq + 2) * D + col] + Wg2[(4 * kq + 2) * D + col];
        float wg3 = Wg1[(4 * kq + 3) * D + col] + Wg2[(4 * kq + 3) * D + col];
#pragma unroll
        for (int r = 0; r < R; r++) {
            float4 a = si[r][kq], u = su[r][kq], g = sg[r][kq];
            acc[r] += a.x * wi0 + a.y * wi1 + a.z * wi2 + a.w * wi3
                    + u.x * wu0 + u.y * wu1 + u.z * wu2 + u.w * wu3
                    + g.x * wg0 + g.y * wg1 + g.z * wg2 + g.w * wg3;
        }
    }
    float bb = bi[col] + bu[col];
    float v[R];
#pragma unroll
    for (int r = 0; r < R; r++) {
        acc[r] = v[r] = fmaxf(acc[r] + bb, 0.f);
        // warp-level max
        float m = v[r];
#pragma unroll
        for (int off = 16; off > 0; off >>= 1)
            m = fmaxf(m, __shfl_xor_sync(0xFFFFFFFF, m, off));
        if (lane == 0) red[r][wid] = m;
    }
    __syncthreads();
#pragma unroll
    for (int r = 0; r < R; r++) {
        int row = r0 + r;
        if (row >= M) continue;
        float mx = fmaxf(fmaxf(red[r][0], red[r][1]), fmaxf(red[r][2], red[r][3]));
        float scale = (mx > 0.f) ? (16383.f / mx) : 0.f;
        int q = __float2int_rn(v[r] * scale);
        int hi = min((q + 64) >> 7, 127);
        int lo = q - (hi << 7);
        a_hi[(size_t)row * D + col] = (int8_t)hi;
        a_lo[(size_t)row * D + col] = (int8_t)lo;
        if (col == 0) a_rec[row] = mx * (1.f / 16383.f);
    }
}

// ---- B path: Wp [128, 20000] -> per-column max, then quantized transpose ------
__global__ void bcolmax_kernel(const float* __restrict__ Wp, float* __restrict__ b_rec)
{
    int n = blockIdx.x * blockDim.x + threadIdx.x;
    if (n >= NIc) return;
    float mx = 0.f;
#pragma unroll 4
    for (int k = 0; k < D; k++)
        mx = fmaxf(mx, fabsf(Wp[(size_t)k * NIc + n]));
    b_rec[n] = mx * (1.f / 16383.f);
}

__global__ void bquant_kernel(const float* __restrict__ Wp, const float* __restrict__ b_rec,
                              int8_t* __restrict__ b_hi, int8_t* __restrict__ b_lo)
{
    __shared__ float t[32][33];
    int n0 = blockIdx.x * 32, k0 = blockIdx.y * 32;
    int tx = threadIdx.x & 31, ty = threadIdx.x >> 5;
#pragma unroll
    for (int r = ty; r < 32; r += 8)
        t[r][tx] = Wp[(size_t)(k0 + r) * NIc + n0 + tx];
    __syncthreads();
#pragma unroll
    for (int r = ty; r < 32; r += 8) {
        int n = n0 + r, k = k0 + tx;
        float rec = b_rec[n];
        float scale = (rec > 0.f) ? (1.f / rec) : 0.f;
        int q = __float2int_rn(t[tx][r] * scale);
        int hi = min((q + 64) >> 7, 127);
        int lo = q - (hi << 7);
        b_hi[(size_t)n * D + k] = (int8_t)hi;
        b_lo[(size_t)n * D + k] = (int8_t)lo;
    }
}

// ============ INT8 IMMA final GEMM: C[M,N] = A @ B^T (descaled) + bias =========
// A: [M,128] int8 hi/lo. B: [N,128] int8 hi/lo (WpT). Exact int32 accumulate of
//   H = Ah*Bh  and  Cx = Ah*Bl + Al*Bh;   out = (16384*H + 128*Cx)*ra*rb + bias.
// CTA tile 128(M) x 64(N), full K=128 in smem, 256 threads (8 warps, 2m x 4n,
// warp tile 64x16). Smem rows: 128 int8 + 16B-chunk XOR swizzle (conflict-free).
#define SM_AH 0
#define SM_AL 16384
#define SM_BH 32768
#define SM_BL 40960
#define SM_S8_TOTAL 49152

__device__ __forceinline__ uint32_t swz8(int row, int t) {
    return (uint32_t)(row * 128 + ((t ^ (row & 7)) << 4));
}

__device__ __forceinline__ void imma16832(int* c, const uint32_t* a, const uint32_t* b)
{
    asm volatile(
        "mma.sync.aligned.m16n8k32.row.col.s32.s8.s8.s32 "
        "{%0,%1,%2,%3}, {%4,%5,%6,%7}, {%8,%9}, {%0,%1,%2,%3};\n"
        : "+r"(c[0]), "+r"(c[1]), "+r"(c[2]), "+r"(c[3])
        : "r"(a[0]), "r"(a[1]), "r"(a[2]), "r"(a[3]), "r"(b[0]), "r"(b[1]));
}

__global__ void __launch_bounds__(256, 1)
gemm_s8(const int8_t* __restrict__ Ahi, const int8_t* __restrict__ Alo,
        const int8_t* __restrict__ Bhi, const int8_t* __restrict__ Blo,
        const float* __restrict__ Arec, const float* __restrict__ Brec,
        const float* __restrict__ bias, float* __restrict__ C, int M, int N)
{
    extern __shared__ char sm[];
    int tid = threadIdx.x;
    int m0 = blockIdx.y * 128, n0 = blockIdx.x * 64;

    uint4 zz = make_uint4(0, 0, 0, 0);
    // A tiles: 128 rows x 8 chunks, hi+lo
#pragma unroll
    for (int it = 0; it < 4; it++) {
        int idx = tid + it * 256;            // 0..1023
        int row = idx >> 3, t = idx & 7;
        int gm = m0 + row;
        uint4 vh = zz, vl = zz;
        if (gm < M) {
            vh = *(const uint4*)(Ahi + (size_t)gm * 128 + t * 16);
            vl = *(const uint4*)(Alo + (size_t)gm * 128 + t * 16);
        }
        uint32_t so = swz8(row, t);
        *(uint4*)(sm + SM_AH + so) = vh;
        *(uint4*)(sm + SM_AL + so) = vl;
    }
    // B tiles: 64 rows x 8 chunks, hi+lo
#pragma unroll
    for (int it = 0; it < 2; it++) {
        int idx = tid + it * 256;            // 0..511
        int row = idx >> 3, t = idx & 7;
        int gn = n0 + row;
        uint4 vh = zz, vl = zz;
        if (gn < N) {
            vh = *(const uint4*)(Bhi + (size_t)gn * 128 + t * 16);
            vl = *(const uint4*)(Blo + (size_t)gn * 128 + t * 16);
        }
        uint32_t so = swz8(row, t);
        *(uint4*)(sm + SM_BH + so) = vh;
        *(uint4*)(sm + SM_BL + so) = vl;
    }
    __syncthreads();

    int lane = tid & 31, w = tid >> 5;
    int wm = w >> 2, wn = w & 3;             // 2 x 4 warps; warp tile 64 x 16
    int r4 = lane >> 2, c4 = (lane & 3) * 4;

    int accH[4][2][4], accC[4][2][4];
#pragma unroll
    for (int i = 0; i < 4; i++)
#pragma unroll
        for (int j = 0; j < 2; j++)
#pragma unroll
            for (int q = 0; q < 4; q++) { accH[i][j][q] = 0; accC[i][j][q] = 0; }

#pragma unroll
    for (int ks = 0; ks < 4; ks++) {
        int kb = ks * 32 + c4;               // byte offset of this thread's 4 int8
        int t0 = kb >> 4, in0 = kb & 15;     // chunk, offset-in-chunk (first 16 of k32)
        uint32_t a[4][4], b[2][2], bl[2][2];
        // A-hi fragments
#pragma unroll
        for (int i = 0; i < 4; i++) {
            int row = wm * 64 + i * 16 + r4;
            const char* p0 = sm + SM_AH;
            a[i][0] = *(const uint32_t*)(p0 + row * 128 + (((t0    ) ^ (row & 7)) << 4) + in0);
            a[i][2] = *(const uint32_t*)(p0 + row * 128 + (((t0 + 1) ^ (row & 7)) << 4) + in0);
            int row8 = row + 8;
            a[i][1] = *(const uint32_t*)(p0 + row8 * 128 + (((t0    ) ^ (row8 & 7)) << 4) + in0);
            a[i][3] = *(const uint32_t*)(p0 + row8 * 128 + (((t0 + 1) ^ (row8 & 7)) << 4) + in0);
        }
        // B-hi / B-lo fragments
#pragma unroll
        for (int j = 0; j < 2; j++) {
            int row = wn * 16 + j * 8 + r4;
            b[j][0]  = *(const uint32_t*)(sm + SM_BH + row * 128 + (((t0    ) ^ (row & 7)) << 4) + in0);
            b[j][1]  = *(const uint32_t*)(sm + SM_BH + row * 128 + (((t0 + 1) ^ (row & 7)) << 4) + in0);
            bl[j][0] = *(const uint32_t*)(sm + SM_BL + row * 128 + (((t0    ) ^ (row & 7)) << 4) + in0);
            bl[j][1] = *(const uint32_t*)(sm + SM_BL + row * 128 + (((t0 + 1) ^ (row & 7)) << 4) + in0);
        }
        // Ah*Bh -> accH ; Ah*Bl -> accC
#pragma unroll
        for (int i = 0; i < 4; i++)
#pragma unroll
            for (int j = 0; j < 2; j++) {
                imma16832(accH[i][j], a[i], b[j]);
                imma16832(accC[i][j], a[i], bl[j]);
            }
        // A-lo fragments (overwrite a), Al*Bh -> accC
#pragma unroll
        for (int i = 0; i < 4; i++) {
            int row = wm * 64 + i * 16 + r4;
            const char* p0 = sm + SM_AL;
            a[i][0] = *(const uint32_t*)(p0 + row * 128 + (((t0    ) ^ (row & 7)) << 4) + in0);
            a[i][2] = *(const uint32_t*)(p0 + row * 128 + (((t0 + 1) ^ (row & 7)) << 4) + in0);
            int row8 = row + 8;
            a[i][1] = *(const uint32_t*)(p0 + row8 * 128 + (((t0    ) ^ (row8 & 7)) << 4) + in0);
            a[i][3] = *(const uint32_t*)(p0 + row8 * 128 + (((t0 + 1) ^ (row8 & 7)) << 4) + in0);
        }
#pragma unroll
        for (int i = 0; i < 4; i++)
#pragma unroll
            for (int j = 0; j < 2; j++)
                imma16832(accC[i][j], a[i], b[j]);
    }

    // epilogue: descale + bias, float2 stores
    int c2 = (lane & 3) * 2;
#pragma unroll
    for (int i = 0; i < 4; i++) {
        int mrow = m0 + wm * 64 + i * 16 + r4;
        float ra0 = (mrow < M)     ? __ldg(Arec + mrow)     : 0.f;
        float ra1 = (mrow + 8 < M) ? __ldg(Arec + mrow + 8) : 0.f;
#pragma unroll
        for (int j = 0; j < 2; j++) {
            int n = n0 + wn * 16 + j * 8 + c2;
            if (n >= N) continue;
            float rb0 = __ldg(Brec + n), rb1 = __ldg(Brec + n + 1);
            float bx = __ldg(bias + n), by = __ldg(bias + n + 1);
            if (mrow < M) {
                float2 o;
                o.x = (16384.f * (float)accH[i][j][0] + 128.f * (float)accC[i][j][0]) * ra0 * rb0 + bx;
                o.y = (16384.f * (float)accH[i][j][1] + 128.f * (float)accC[i][j][1]) * ra0 * rb1 + by;
                *(float2*)(C + (size_t)mrow * N + n) = o;
            }
            if (mrow + 8 < M) {
                float2 o;
                o.x = (16384.f * (float)accH[i][j][2] + 128.f * (float)accC[i][j][2]) * ra1 * rb0 + bx;
                o.y = (16384.f * (float)accH[i][j][3] + 128.f * (float)accC[i][j][3]) * ra1 * rb1 + by;
                *(float2*)(C + (size_t)(mrow + 8) * N + n) = o;
            }
        }
    }
}

// ------------------------------ launcher ---------------------------------------
extern "C" void kernel_launch(void* const* d_in, const int* in_sizes, int n_in,
                              void* d_out, int out_size)
{
    const int*   gi_src  = (const int*)d_in[3];
    const int*   gi_dst  = (const int*)d_in[4];
    const int*   gu_src  = (const int*)d_in[5];
    const int*   gu_dst  = (const int*)d_in[6];
    const float* emb_u   = (const float*)d_in[8];
    const float* emb_i   = (const float*)d_in[9];
    const float* Wl1     = (const float*)d_in[10];
    const float* Wr1     = (const float*)d_in[11];
    const float* b1      = (const float*)d_in[12];
    const float* Wl2     = (const float*)d_in[13];
    const float* Wr2     = (const float*)d_in[14];
    const float* b2      = (const float*)d_in[15];
    const float* Wp      = (const float*)d_in[16];
    const float* bp      = (const float*)d_in[17];
    float*       out     = (float*)d_out;

    float4 *acc_i, *acc_u, *acc2_i, *acc2_u;
    int *cnt_i, *cnt_u;
    float *g1p, *i1p, *u1p, *arec, *brec;
    int8_t *ahi, *alo, *bhi, *blo;
    cudaGetSymbolAddress((void**)&acc_i,  g_acc_i);
    cudaGetSymbolAddress((void**)&acc_u,  g_acc_u);
    cudaGetSymbolAddress((void**)&acc2_i, g_acc2_i);
    cudaGetSymbolAddress((void**)&acc2_u, g_acc2_u);
    cudaGetSymbolAddress((void**)&cnt_i,  g_cnt_i);
    cudaGetSymbolAddress((void**)&cnt_u,  g_cnt_u);
    cudaGetSymbolAddress((void**)&g1p,    g_g1);
    cudaGetSymbolAddress((void**)&i1p,    g_i1);
    cudaGetSymbolAddress((void**)&u1p,    g_u1);
    cudaGetSymbolAddress((void**)&ahi,    g_A_hi);
    cudaGetSymbolAddress((void**)&alo,    g_A_lo);
    cudaGetSymbolAddress((void**)&arec,   g_A_rec);
    cudaGetSymbolAddress((void**)&bhi,    g_B_hi);
    cudaGetSymbolAddress((void**)&blo,    g_B_lo);
    cudaGetSymbolAddress((void**)&brec,   g_B_rec);

    size_t accBytes = (size_t)NGc * D * sizeof(float);
    cudaMemsetAsync(acc_i,  0, accBytes);
    cudaMemsetAsync(acc_u,  0, accBytes);
    cudaMemsetAsync(acc2_i, 0, accBytes);
    cudaMemsetAsync(acc2_u, 0, accBytes);
    cudaMemsetAsync(cnt_i,  0, NGc * sizeof(int));
    cudaMemsetAsync(cnt_u,  0, NGc * sizeof(int));

    // B quantization path (independent of the graph chain)
    bcolmax_kernel<<<(NIc + 511) / 512, 512>>>(Wp, brec);
    bquant_kernel<<<dim3(NIc / 32, D / 32), 256>>>(Wp, brec, bhi, blo);

    // layer 1 scatter (with counts)
    scatter_kernel<<<(EGIc * 32 + 255) / 256, 256>>>(gi_src, gi_dst, (const float4*)emb_i,
                                                     acc_i, cnt_i, EGIc);
    scatter_kernel<<<(EGUc * 32 + 255) / 256, 256>>>(gu_src, gu_dst, (const float4*)emb_u,
                                                     acc_u, cnt_u, EGUc);

    g1_kernel<8><<<(NGc + 7) / 8, 128>>>((const float*)acc_i, (const float*)acc_u,
                                         cnt_i, cnt_u,
                                         Wl1 + 1 * D * D, Wl1 + 3 * D * D,
                                         b1 + 1 * D, b1 + 3 * D, g1p, NGc);

    lin_relu_kernel<32><<<(NIc + 31) / 32, 128>>>(emb_i, Wr1 + 0 * D * D, b1 + 0 * D, i1p, NIc);
    lin_relu_kernel<32><<<(NUc + 31) / 32, 128>>>(emb_u, Wr1 + 2 * D * D, b1 + 2 * D, u1p, NUc);

    scatter_kernel<<<(EGIc * 32 + 255) / 256, 256>>>(gi_src, gi_dst, (const float4*)i1p,
                                                     acc2_i, (int*)nullptr, EGIc);
    scatter_kernel<<<(EGUc * 32 + 255) / 256, 256>>>(gu_src, gu_dst, (const float4*)u1p,
                                                     acc2_u, (int*)nullptr, EGUc);

    g2_kernel<8><<<(NGc + 7) / 8, 128>>>((const float*)acc2_i, (const float*)acc2_u, g1p,
                                         cnt_i, cnt_u,
                                         Wl2 + 1 * D * D, Wl2 + 3 * D * D,
                                         Wr2 + 1 * D * D, Wr2 + 3 * D * D,
                                         b2 + 1 * D, b2 + 3 * D, ahi, alo, arec, NGc);

    // out = g2 @ WpT^T + bp  via 2-limb INT8 IMMA GEMM
    dim3 grid((NIc + 63) / 64, (NGc + 127) / 128);
    gemm_s8<<<grid, 256, SM_S8_TOTAL>>>(ahi, alo, bhi, blo, arec, brec, bp, out, NGc, NIc);
}

// round 5
// speedup vs baseline: 1.8975x; 1.8975x over previous
#include <cuda_runtime.h>
#include <cuda_fp16.h>
#include <cstdint>

#define D    128
#define NGc  10000
#define NUc  100000
#define NIc  20000
#define EGIc 400000
#define EGUc 400000

// ---------------- scratch (device globals; no allocation allowed) -------------
__device__ float4 g_acc_i[NGc * 32];
__device__ float4 g_acc_u[NGc * 32];
__device__ float4 g_acc2_i[NGc * 32];
__device__ float4 g_acc2_u[NGc * 32];
__device__ int    g_cnt_i[NGc];
__device__ int    g_cnt_u[NGc];
__device__ float  g_g1[NGc * D];
__device__ float  g_i1[NIc * D];
__device__ float  g_u1[NUc * D];
__device__ __half g_Af[NGc * D];        // g2 in fp16
__device__ __half g_Bf[NIc * D];        // WpT in fp16: [n][k]

// ---------------- scatter-sum: one warp per 2 edges, float4 RED ----------------
__global__ void scatter_kernel(const int* __restrict__ grp, const int* __restrict__ nbr,
                               const float4* __restrict__ feat, float4* __restrict__ acc,
                               int* cnt, int E)
{
    int warp = (blockIdx.x * blockDim.x + threadIdx.x) >> 5;
    int lane = threadIdx.x & 31;
    int e0 = warp * 2;
    if (e0 >= E) return;
    int g0 = __ldg(grp + e0), n0 = __ldg(nbr + e0);
    bool has2 = (e0 + 1 < E);
    int g1 = 0, n1 = 0;
    if (has2) { g1 = __ldg(grp + e0 + 1); n1 = __ldg(nbr + e0 + 1); }
    float4 v0 = __ldg(feat + (size_t)n0 * 32 + lane);
    float4 v1;
    if (has2) v1 = __ldg(feat + (size_t)n1 * 32 + lane);
    atomicAdd(acc + (size_t)g0 * 32 + lane, v0);
    if (has2) atomicAdd(acc + (size_t)g1 * 32 + lane, v1);
    if (cnt && lane == 0) {
        atomicAdd(cnt + g0, 1);
        if (has2) atomicAdd(cnt + g1, 1);
    }
}

// ---------------- out = relu(x @ W + b), x: [M,128], W: [128,128] --------------
template <int R>
__global__ void lin_relu_kernel(const float* __restrict__ x, const float* __restrict__ W,
                                const float* __restrict__ b, float* __restrict__ out, int M)
{
    __shared__ float4 xs[R][32];
    int col = threadIdx.x;
    int r0 = blockIdx.x * R;
#pragma unroll
    for (int r = 0; r < R; r++) {
        int row = r0 + r;
        ((float*)xs[r])[col] = (row < M) ? x[(size_t)row * D + col] : 0.f;
    }
    __syncthreads();
    float acc[R];
#pragma unroll
    for (int r = 0; r < R; r++) acc[r] = 0.f;
#pragma unroll 4
    for (int kq = 0; kq < 32; kq++) {
        float w0 = W[(4 * kq + 0) * D + col];
        float w1 = W[(4 * kq + 1) * D + col];
        float w2 = W[(4 * kq + 2) * D + col];
        float w3 = W[(4 * kq + 3) * D + col];
#pragma unroll
        for (int r = 0; r < R; r++) {
            float4 xv = xs[r][kq];
            acc[r] += xv.x * w0 + xv.y * w1 + xv.z * w2 + xv.w * w3;
        }
    }
    float bb = b[col];
#pragma unroll
    for (int r = 0; r < R; r++) {
        int row = r0 + r;
        if (row < M) out[(size_t)row * D + col] = fmaxf(acc[r] + bb, 0.f);
    }
}

// ------- g1 = relu( (acc_i/cnt_i) @ Wi + (acc_u/cnt_u) @ Wu + bi + bu ) --------
template <int R>
__global__ void g1_kernel(const float* __restrict__ acc_i, const float* __restrict__ acc_u,
                          const int* __restrict__ cnt_i, const int* __restrict__ cnt_u,
                          const float* __restrict__ Wi, const float* __restrict__ Wu,
                          const float* __restrict__ bi, const float* __restrict__ bu,
                          float* __restrict__ out, int M)
{
    __shared__ float4 si[R][32];
    __shared__ float4 su[R][32];
    int col = threadIdx.x;
    int r0 = blockIdx.x * R;
#pragma unroll
    for (int r = 0; r < R; r++) {
        int row = r0 + r;
        int rr = row < M ? row : M - 1;
        float invi = 1.f / (float)max(cnt_i[rr], 1);
        float invu = 1.f / (float)max(cnt_u[rr], 1);
        ((float*)si[r])[col] = acc_i[(size_t)rr * D + col] * invi;
        ((float*)su[r])[col] = acc_u[(size_t)rr * D + col] * invu;
    }
    __syncthreads();
    float acc[R];
#pragma unroll
    for (int r = 0; r < R; r++) acc[r] = 0.f;
#pragma unroll 4
    for (int kq = 0; kq < 32; kq++) {
        float wi0 = Wi[(4 * kq + 0) * D + col], wi1 = Wi[(4 * kq + 1) * D + col];
        float wi2 = Wi[(4 * kq + 2) * D + col], wi3 = Wi[(4 * kq + 3) * D + col];
        float wu0 = Wu[(4 * kq + 0) * D + col], wu1 = Wu[(4 * kq + 1) * D + col];
        float wu2 = Wu[(4 * kq + 2) * D + col], wu3 = Wu[(4 * kq + 3) * D + col];
#pragma unroll
        for (int r = 0; r < R; r++) {
            float4 a = si[r][kq], u = su[r][kq];
            acc[r] += a.x * wi0 + a.y * wi1 + a.z * wi2 + a.w * wi3
                    + u.x * wu0 + u.y * wu1 + u.z * wu2 + u.w * wu3;
        }
    }
    float bb = bi[col] + bu[col];
#pragma unroll
    for (int r = 0; r < R; r++) {
        int row = r0 + r;
        if (row < M) out[(size_t)row * D + col] = fmaxf(acc[r] + bb, 0.f);
    }
}

// g2 = relu(...) -> emitted directly as fp16 for the tensor GEMM
template <int R>
__global__ void g2_kernel(const float* __restrict__ acc_i, const float* __restrict__ acc_u,
                          const float* __restrict__ g1,
                          const int* __restrict__ cnt_i, const int* __restrict__ cnt_u,
                          const float* __restrict__ Wi, const float* __restrict__ Wu,
                          const float* __restrict__ Wg1, const float* __restrict__ Wg2,
                          const float* __restrict__ bi, const float* __restrict__ bu,
                          __half* __restrict__ af, int M)
{
    __shared__ float4 si[R][32];
    __shared__ float4 su[R][32];
    __shared__ float4 sg[R][32];
    int col = threadIdx.x;
    int r0 = blockIdx.x * R;
#pragma unroll
    for (int r = 0; r < R; r++) {
        int row = r0 + r;
        int rr = row < M ? row : M - 1;
        float invi = 1.f / (float)max(cnt_i[rr], 1);
        float invu = 1.f / (float)max(cnt_u[rr], 1);
        ((float*)si[r])[col] = acc_i[(size_t)rr * D + col] * invi;
        ((float*)su[r])[col] = acc_u[(size_t)rr * D + col] * invu;
        ((float*)sg[r])[col] = g1[(size_t)rr * D + col];
    }
    __syncthreads();
    float acc[R];
#pragma unroll
    for (int r = 0; r < R; r++) acc[r] = 0.f;
#pragma unroll 2
    for (int kq = 0; kq < 32; kq++) {
        float wi0 = Wi[(4 * kq + 0) * D + col], wi1 = Wi[(4 * kq + 1) * D + col];
        float wi2 = Wi[(4 * kq + 2) * D + col], wi3 = Wi[(4 * kq + 3) * D + col];
        float wu0 = Wu[(4 * kq + 0) * D + col], wu1 = Wu[(4 * kq + 1) * D + col];
        float wu2 = Wu[(4 * kq + 2) * D + col], wu3 = Wu[(4 * kq + 3) * D + col];
        float wg0 = Wg1[(4 * kq + 0) * D + col] + Wg2[(4 * kq + 0) * D + col];
        float wg1 = Wg1[(4 * kq + 1) * D + col] + Wg2[(4 * kq + 1) * D + col];
        float wg2 = Wg1[(4 * kq + 2) * D + col] + Wg2[(4 * kq + 2) * D + col];
        float wg3 = Wg1[(4 * kq + 3) * D + col] + Wg2[(4 * kq + 3) * D + col];
#pragma unroll
        for (int r = 0; r < R; r++) {
            float4 a = si[r][kq], u = su[r][kq], g = sg[r][kq];
            acc[r] += a.x * wi0 + a.y * wi1 + a.z * wi2 + a.w * wi3
                    + u.x * wu0 + u.y * wu1 + u.z * wu2 + u.w * wu3
                    + g.x * wg0 + g.y * wg1 + g.z * wg2 + g.w * wg3;
        }
    }
    float bb = bi[col] + bu[col];
#pragma unroll
    for (int r = 0; r < R; r++) {
        int row = r0 + r;
        if (row < M)
            af[(size_t)row * D + col] = __float2half_rn(fmaxf(acc[r] + bb, 0.f));
    }
}

// ------- Wp [128,20000] fp32 -> WpT [20000,128] fp16 (tiled transpose) ---------
__global__ void conv_wp_kernel(const float* __restrict__ Wp, __half* __restrict__ bf)
{
    __shared__ float t[32][33];
    int n0 = blockIdx.x * 32, k0 = blockIdx.y * 32;
    int tx = threadIdx.x & 31, ty = threadIdx.x >> 5;
#pragma unroll
    for (int r = ty; r < 32; r += 8)
        t[r][tx] = Wp[(size_t)(k0 + r) * NIc + n0 + tx];
    __syncthreads();
#pragma unroll
    for (int r = ty; r < 32; r += 8) {
        int n = n0 + r, k = k0 + tx;
        bf[(size_t)n * D + k] = __float2half_rn(t[tx][r]);
    }
}

// ---------------- fp16 tensor-core final GEMM: C = A @ B^T + bias --------------
// A: [M,128] fp16 row-major (k-contig), B: [N,128] fp16 row-major (= WpT).
#define SMSTRIDE 136   // halves per smem row (padded: conflict-free frag LDS)

__device__ __forceinline__ void mma16816(float* c, const uint32_t* a, const uint32_t* b)
{
    asm volatile(
        "mma.sync.aligned.m16n8k16.row.col.f32.f16.f16.f32 "
        "{%0,%1,%2,%3}, {%4,%5,%6,%7}, {%8,%9}, {%0,%1,%2,%3};\n"
        : "+f"(c[0]), "+f"(c[1]), "+f"(c[2]), "+f"(c[3])
        : "r"(a[0]), "r"(a[1]), "r"(a[2]), "r"(a[3]), "r"(b[0]), "r"(b[1]));
}

__global__ void __launch_bounds__(256, 1)
gemm_f16(const __half* __restrict__ A, const __half* __restrict__ B,
         const float* __restrict__ bias, float* __restrict__ C, int M, int N)
{
    extern __shared__ __half sm[];
    __half* As = sm;
    __half* Bs = As + 128 * SMSTRIDE;

    int tid = threadIdx.x;
    int m0 = blockIdx.y * 128, n0 = blockIdx.x * 128;

    uint4 zz = make_uint4(0, 0, 0, 0);
    for (int idx = tid; idx < 2048; idx += 256) {
        int row = idx >> 4;
        int c8 = (idx & 15) << 3;
        int gm = m0 + row;
        uint4 va = zz;
        if (gm < M) va = *(const uint4*)(A + (size_t)gm * 128 + c8);
        *(uint4*)(As + row * SMSTRIDE + c8) = va;
        int gn = n0 + row;
        uint4 vb = zz;
        if (gn < N) vb = *(const uint4*)(B + (size_t)gn * 128 + c8);
        *(uint4*)(Bs + row * SMSTRIDE + c8) = vb;
    }
    __syncthreads();

    int lane = tid & 31, w = tid >> 5;
    int wm = w >> 2, wn = w & 3;               // 2 x 4 warp grid, warp tile 64x32
    int r = lane >> 2, c2 = (lane & 3) * 2;

    float acc[4][4][4];
#pragma unroll
    for (int i = 0; i < 4; i++)
#pragma unroll
        for (int j = 0; j < 4; j++)
#pragma unroll
            for (int q = 0; q < 4; q++) acc[i][j][q] = 0.f;

#pragma unroll
    for (int ks = 0; ks < 8; ks++) {
        int kb = ks * 16 + c2;
        uint32_t a[4][4], b[4][2];
#pragma unroll
        for (int i = 0; i < 4; i++) {
            const __half* pa = As + (wm * 64 + i * 16 + r) * SMSTRIDE + kb;
            a[i][0] = *(const uint32_t*)(pa);
            a[i][1] = *(const uint32_t*)(pa + 8 * SMSTRIDE);
            a[i][2] = *(const uint32_t*)(pa + 8);
            a[i][3] = *(const uint32_t*)(pa + 8 * SMSTRIDE + 8);
        }
#pragma unroll
        for (int j = 0; j < 4; j++) {
            const __half* pb = Bs + (wn * 32 + j * 8 + r) * SMSTRIDE + kb;
            b[j][0] = *(const uint32_t*)(pb);
            b[j][1] = *(const uint32_t*)(pb + 8);
        }
#pragma unroll
        for (int i = 0; i < 4; i++)
#pragma unroll
            for (int j = 0; j < 4; j++)
                mma16816(acc[i][j], a[i], b[j]);
    }

#pragma unroll
    for (int i = 0; i < 4; i++) {
#pragma unroll
        for (int j = 0; j < 4; j++) {
            int m = m0 + wm * 64 + i * 16 + r;
            int n = n0 + wn * 32 + j * 8 + c2;
            if (n < N) {
                float bx = __ldg(bias + n), by = __ldg(bias + n + 1);
                if (m < M) {
                    float2 o = make_float2(acc[i][j][0] + bx, acc[i][j][1] + by);
                    *(float2*)(C + (size_t)m * N + n) = o;
                }
                if (m + 8 < M) {
                    float2 o = make_float2(acc[i][j][2] + bx, acc[i][j][3] + by);
                    *(float2*)(C + (size_t)(m + 8) * N + n) = o;
                }
            }
        }
    }
}

// ------------------------------ launcher ---------------------------------------
extern "C" void kernel_launch(void* const* d_in, const int* in_sizes, int n_in,
                              void* d_out, int out_size)
{
    const int*   gi_src  = (const int*)d_in[3];
    const int*   gi_dst  = (const int*)d_in[4];
    const int*   gu_src  = (const int*)d_in[5];
    const int*   gu_dst  = (const int*)d_in[6];
    const float* emb_u   = (const float*)d_in[8];
    const float* emb_i   = (const float*)d_in[9];
    const float* Wl1     = (const float*)d_in[10];
    const float* Wr1     = (const float*)d_in[11];
    const float* b1      = (const float*)d_in[12];
    const float* Wl2     = (const float*)d_in[13];
    const float* Wr2     = (const float*)d_in[14];
    const float* b2      = (const float*)d_in[15];
    const float* Wp      = (const float*)d_in[16];
    const float* bp      = (const float*)d_in[17];
    float*       out     = (float*)d_out;

    float4 *acc_i, *acc_u, *acc2_i, *acc2_u;
    int *cnt_i, *cnt_u;
    float *g1p, *i1p, *u1p;
    __half *af, *bf;
    cudaGetSymbolAddress((void**)&acc_i,  g_acc_i);
    cudaGetSymbolAddress((void**)&acc_u,  g_acc_u);
    cudaGetSymbolAddress((void**)&acc2_i, g_acc2_i);
    cudaGetSymbolAddress((void**)&acc2_u, g_acc2_u);
    cudaGetSymbolAddress((void**)&cnt_i,  g_cnt_i);
    cudaGetSymbolAddress((void**)&cnt_u,  g_cnt_u);
    cudaGetSymbolAddress((void**)&g1p,    g_g1);
    cudaGetSymbolAddress((void**)&i1p,    g_i1);
    cudaGetSymbolAddress((void**)&u1p,    g_u1);
    cudaGetSymbolAddress((void**)&af,     g_Af);
    cudaGetSymbolAddress((void**)&bf,     g_Bf);

    size_t accBytes = (size_t)NGc * D * sizeof(float);
    cudaMemsetAsync(acc_i,  0, accBytes);
    cudaMemsetAsync(acc_u,  0, accBytes);
    cudaMemsetAsync(acc2_i, 0, accBytes);
    cudaMemsetAsync(acc2_u, 0, accBytes);
    cudaMemsetAsync(cnt_i,  0, NGc * sizeof(int));
    cudaMemsetAsync(cnt_u,  0, NGc * sizeof(int));

    // Wp transpose + fp16 convert (independent of the graph chain)
    conv_wp_kernel<<<dim3(NIc / 32, D / 32), 256>>>(Wp, bf);

    // layer 1 scatter (with counts); one warp per 2 edges
    scatter_kernel<<<(EGIc / 2 * 32 + 255) / 256, 256>>>(gi_src, gi_dst, (const float4*)emb_i,
                                                         acc_i, cnt_i, EGIc);
    scatter_kernel<<<(EGUc / 2 * 32 + 255) / 256, 256>>>(gu_src, gu_dst, (const float4*)emb_u,
                                                         acc_u, cnt_u, EGUc);

    g1_kernel<8><<<(NGc + 7) / 8, 128>>>((const float*)acc_i, (const float*)acc_u,
                                         cnt_i, cnt_u,
                                         Wl1 + 1 * D * D, Wl1 + 3 * D * D,
                                         b1 + 1 * D, b1 + 3 * D, g1p, NGc);

    lin_relu_kernel<32><<<(NIc + 31) / 32, 128>>>(emb_i, Wr1 + 0 * D * D, b1 + 0 * D, i1p, NIc);
    lin_relu_kernel<32><<<(NUc + 31) / 32, 128>>>(emb_u, Wr1 + 2 * D * D, b1 + 2 * D, u1p, NUc);

    scatter_kernel<<<(EGIc / 2 * 32 + 255) / 256, 256>>>(gi_src, gi_dst, (const float4*)i1p,
                                                         acc2_i, (int*)nullptr, EGIc);
    scatter_kernel<<<(EGUc / 2 * 32 + 255) / 256, 256>>>(gu_src, gu_dst, (const float4*)u1p,
                                                         acc2_u, (int*)nullptr, EGUc);

    g2_kernel<8><<<(NGc + 7) / 8, 128>>>((const float*)acc2_i, (const float*)acc2_u, g1p,
                                         cnt_i, cnt_u,
                                         Wl2 + 1 * D * D, Wl2 + 3 * D * D,
                                         Wr2 + 1 * D * D, Wr2 + 3 * D * D,
                                         b2 + 1 * D, b2 + 3 * D, af, NGc);

    // out = g2 @ WpT^T + bp  via fp16 tensor GEMM
    int smemBytes = 2 * 128 * SMSTRIDE * sizeof(__half);
    cudaFuncSetAttribute(gemm_f16, cudaFuncAttributeMaxDynamicSharedMemorySize, smemBytes);
    dim3 grid((NIc + 127) / 128, (NGc + 127) / 128);
    gemm_f16<<<grid, 256, smemBytes>>>(af, bf, bp, out, NGc, NIc);
}

// round 6
// speedup vs baseline: 2.0915x; 1.1022x over previous
#include <cuda_runtime.h>
#include <cuda_fp16.h>
#include <cstdint>

#define D    128
#define NGc  10000
#define NUc  100000
#define NIc  20000
#define EGIc 400000
#define EGUc 400000

// ---------------- scratch (device globals; no allocation allowed) -------------
__device__ float4 g_acc_i[NGc * 32];
__device__ float4 g_acc_u[NGc * 32];
__device__ float4 g_acc2_i[NGc * 32];
__device__ float4 g_acc2_u[NGc * 32];
__device__ int    g_cnt_i[NGc];
__device__ int    g_cnt_u[NGc];
__device__ float  g_g1[NGc * D];
__device__ __half g_embih[NIc * D];     // emb_item fp16
__device__ __half g_embuh[NUc * D];     // emb_user fp16
__device__ __half g_Wt[2 * D * D];      // Wr1[0]^T, Wr1[2]^T fp16
__device__ __half g_i1h[NIc * D];       // i1 fp16
__device__ __half g_u1h[NUc * D];       // u1 fp16
__device__ __half g_Af[NGc * D];        // g2 fp16
__device__ __half g_Bf[NIc * D];        // WpT fp16: [n][k]

// ---------------- fp32 -> fp16 elementwise (float4 -> half4) -------------------
__global__ void conv_h_kernel(const float4* __restrict__ x, uint2* __restrict__ y, int n4)
{
    int i = blockIdx.x * blockDim.x + threadIdx.x;
    if (i >= n4) return;
    float4 v = x[i];
    __half2 a = __floats2half2_rn(v.x, v.y);
    __half2 b = __floats2half2_rn(v.z, v.w);
    uint2 r;
    r.x = *(uint32_t*)&a;
    r.y = *(uint32_t*)&b;
    y[i] = r;
}

// ---------------- W [128,128] fp32 -> W^T [128,128] fp16 -----------------------
__global__ void conv_w128_kernel(const float* __restrict__ W, __half* __restrict__ Wt)
{
    __shared__ float t[32][33];
    int c0 = blockIdx.x * 32, k0 = blockIdx.y * 32;
    int tx = threadIdx.x & 31, ty = threadIdx.x >> 5;
#pragma unroll
    for (int r = ty; r < 32; r += 8)
        t[r][tx] = W[(k0 + r) * D + c0 + tx];
    __syncthreads();
#pragma unroll
    for (int r = ty; r < 32; r += 8)
        Wt[(size_t)(c0 + r) * D + k0 + tx] = __float2half_rn(t[tx][r]);
}

// ------- Wp [128,20000] fp32 -> WpT [20000,128] fp16 (tiled transpose) ---------
__global__ void conv_wp_kernel(const float* __restrict__ Wp, __half* __restrict__ bf)
{
    __shared__ float t[32][33];
    int n0 = blockIdx.x * 32, k0 = blockIdx.y * 32;
    int tx = threadIdx.x & 31, ty = threadIdx.x >> 5;
#pragma unroll
    for (int r = ty; r < 32; r += 8)
        t[r][tx] = Wp[(size_t)(k0 + r) * NIc + n0 + tx];
    __syncthreads();
#pragma unroll
    for (int r = ty; r < 32; r += 8) {
        int n = n0 + r, k = k0 + tx;
        bf[(size_t)n * D + k] = __float2half_rn(t[tx][r]);
    }
}

// ------- merged layer-1 scatter: fp32 feats, counts; 2 edges / warp ------------
__global__ void scatter1_kernel(const int* __restrict__ gi_s, const int* __restrict__ gi_d,
                                const float4* __restrict__ fi,
                                const int* __restrict__ gu_s, const int* __restrict__ gu_d,
                                const float4* __restrict__ fu,
                                float4* __restrict__ acc_i, float4* __restrict__ acc_u,
                                int* __restrict__ cnt_i, int* __restrict__ cnt_u)
{
    int warp = (blockIdx.x * blockDim.x + threadIdx.x) >> 5;
    int lane = threadIdx.x & 31;
    const int WI = EGIc / 2;
    const int WU = EGUc / 2;
    if (warp < WI) {
        int e0 = warp * 2;
        int g0 = __ldg(gi_s + e0), n0 = __ldg(gi_d + e0);
        int g1 = __ldg(gi_s + e0 + 1), n1 = __ldg(gi_d + e0 + 1);
        float4 v0 = __ldg(fi + (size_t)n0 * 32 + lane);
        float4 v1 = __ldg(fi + (size_t)n1 * 32 + lane);
        atomicAdd(acc_i + (size_t)g0 * 32 + lane, v0);
        atomicAdd(acc_i + (size_t)g1 * 32 + lane, v1);
        if (lane == 0) { atomicAdd(cnt_i + g0, 1); atomicAdd(cnt_i + g1, 1); }
    } else if (warp < WI + WU) {
        int e0 = (warp - WI) * 2;
        int g0 = __ldg(gu_s + e0), n0 = __ldg(gu_d + e0);
        int g1 = __ldg(gu_s + e0 + 1), n1 = __ldg(gu_d + e0 + 1);
        float4 v0 = __ldg(fu + (size_t)n0 * 32 + lane);
        float4 v1 = __ldg(fu + (size_t)n1 * 32 + lane);
        atomicAdd(acc_u + (size_t)g0 * 32 + lane, v0);
        atomicAdd(acc_u + (size_t)g1 * 32 + lane, v1);
        if (lane == 0) { atomicAdd(cnt_u + g0, 1); atomicAdd(cnt_u + g1, 1); }
    }
}

// ------- merged layer-2 scatter: fp16 feats (half4 / lane), no counts ----------
__device__ __forceinline__ float4 h4_to_f4(uint2 r)
{
    __half2 a = *(__half2*)&r.x;
    __half2 b = *(__half2*)&r.y;
    float2 fa = __half22float2(a), fb = __half22float2(b);
    return make_float4(fa.x, fa.y, fb.x, fb.y);
}

__global__ void scatter2_kernel(const int* __restrict__ gi_s, const int* __restrict__ gi_d,
                                const uint2* __restrict__ fi,
                                const int* __restrict__ gu_s, const int* __restrict__ gu_d,
                                const uint2* __restrict__ fu,
                                float4* __restrict__ acc_i, float4* __restrict__ acc_u)
{
    int warp = (blockIdx.x * blockDim.x + threadIdx.x) >> 5;
    int lane = threadIdx.x & 31;
    const int WI = EGIc / 2;
    const int WU = EGUc / 2;
    if (warp < WI) {
        int e0 = warp * 2;
        int g0 = __ldg(gi_s + e0), n0 = __ldg(gi_d + e0);
        int g1 = __ldg(gi_s + e0 + 1), n1 = __ldg(gi_d + e0 + 1);
        uint2 r0 = __ldg(fi + (size_t)n0 * 32 + lane);
        uint2 r1 = __ldg(fi + (size_t)n1 * 32 + lane);
        atomicAdd(acc_i + (size_t)g0 * 32 + lane, h4_to_f4(r0));
        atomicAdd(acc_i + (size_t)g1 * 32 + lane, h4_to_f4(r1));
    } else if (warp < WI + WU) {
        int e0 = (warp - WI) * 2;
        int g0 = __ldg(gu_s + e0), n0 = __ldg(gu_d + e0);
        int g1 = __ldg(gu_s + e0 + 1), n1 = __ldg(gu_d + e0 + 1);
        uint2 r0 = __ldg(fu + (size_t)n0 * 32 + lane);
        uint2 r1 = __ldg(fu + (size_t)n1 * 32 + lane);
        atomicAdd(acc_u + (size_t)g0 * 32 + lane, h4_to_f4(r0));
        atomicAdd(acc_u + (size_t)g1 * 32 + lane, h4_to_f4(r1));
    }
}

// ================= fp16 HMMA building block ====================================
__device__ __forceinline__ void mma16816(float* c, const uint32_t* a, const uint32_t* b)
{
    asm volatile(
        "mma.sync.aligned.m16n8k16.row.col.f32.f16.f16.f32 "
        "{%0,%1,%2,%3}, {%4,%5,%6,%7}, {%8,%9}, {%0,%1,%2,%3};\n"
        : "+f"(c[0]), "+f"(c[1]), "+f"(c[2]), "+f"(c[3])
        : "r"(a[0]), "r"(a[1]), "r"(a[2]), "r"(a[3]), "r"(b[0]), "r"(b[1]));
}

#define SMSTRIDE 136   // halves per smem row (padded: conflict-free frag LDS)

// ------- out[M,128] = relu(fp16 X[M,128] @ Wt^T + b) in fp16 --------------------
__global__ void __launch_bounds__(256, 1)
lin_gemm_f16(const __half* __restrict__ X, const __half* __restrict__ Wt,
             const float* __restrict__ b, __half* __restrict__ out, int M)
{
    extern __shared__ __half sm[];
    __half* As = sm;
    __half* Bs = As + 128 * SMSTRIDE;

    int tid = threadIdx.x;
    int m0 = blockIdx.x * 128;

    uint4 zz = make_uint4(0, 0, 0, 0);
    for (int idx = tid; idx < 2048; idx += 256) {
        int row = idx >> 4;
        int c8 = (idx & 15) << 3;
        int gm = m0 + row;
        uint4 va = zz;
        if (gm < M) va = *(const uint4*)(X + (size_t)gm * 128 + c8);
        *(uint4*)(As + row * SMSTRIDE + c8) = va;
        *(uint4*)(Bs + row * SMSTRIDE + c8) = *(const uint4*)(Wt + (size_t)row * 128 + c8);
    }
    __syncthreads();

    int lane = tid & 31, w = tid >> 5;
    int wm = w >> 2, wn = w & 3;
    int r = lane >> 2, c2 = (lane & 3) * 2;

    float acc[4][4][4];
#pragma unroll
    for (int i = 0; i < 4; i++)
#pragma unroll
        for (int j = 0; j < 4; j++)
#pragma unroll
            for (int q = 0; q < 4; q++) acc[i][j][q] = 0.f;

#pragma unroll
    for (int ks = 0; ks < 8; ks++) {
        int kb = ks * 16 + c2;
        uint32_t a[4][4], bb[4][2];
#pragma unroll
        for (int i = 0; i < 4; i++) {
            const __half* pa = As + (wm * 64 + i * 16 + r) * SMSTRIDE + kb;
            a[i][0] = *(const uint32_t*)(pa);
            a[i][1] = *(const uint32_t*)(pa + 8 * SMSTRIDE);
            a[i][2] = *(const uint32_t*)(pa + 8);
            a[i][3] = *(const uint32_t*)(pa + 8 * SMSTRIDE + 8);
        }
#pragma unroll
        for (int j = 0; j < 4; j++) {
            const __half* pb = Bs + (wn * 32 + j * 8 + r) * SMSTRIDE + kb;
            bb[j][0] = *(const uint32_t*)(pb);
            bb[j][1] = *(const uint32_t*)(pb + 8);
        }
#pragma unroll
        for (int i = 0; i < 4; i++)
#pragma unroll
            for (int j = 0; j < 4; j++)
                mma16816(acc[i][j], a[i], bb[j]);
    }

#pragma unroll
    for (int i = 0; i < 4; i++) {
#pragma unroll
        for (int j = 0; j < 4; j++) {
            int m = m0 + wm * 64 + i * 16 + r;
            int n = wn * 32 + j * 8 + c2;
            float bx = __ldg(b + n), by = __ldg(b + n + 1);
            if (m < M) {
                __half2 h = __floats2half2_rn(fmaxf(acc[i][j][0] + bx, 0.f),
                                              fmaxf(acc[i][j][1] + by, 0.f));
                *(__half2*)(out + (size_t)m * 128 + n) = h;
            }
            if (m + 8 < M) {
                __half2 h = __floats2half2_rn(fmaxf(acc[i][j][2] + bx, 0.f),
                                              fmaxf(acc[i][j][3] + by, 0.f));
                *(__half2*)(out + (size_t)(m + 8) * 128 + n) = h;
            }
        }
    }
}

// ------- g1 = relu( (acc_i/cnt_i) @ Wi + (acc_u/cnt_u) @ Wu + bi + bu ) --------
template <int R>
__global__ void g1_kernel(const float* __restrict__ acc_i, const float* __restrict__ acc_u,
                          const int* __restrict__ cnt_i, const int* __restrict__ cnt_u,
                          const float* __restrict__ Wi, const float* __restrict__ Wu,
                          const float* __restrict__ bi, const float* __restrict__ bu,
                          float* __restrict__ out, int M)
{
    __shared__ float4 si[R][32];
    __shared__ float4 su[R][32];
    int col = threadIdx.x;
    int r0 = blockIdx.x * R;
#pragma unroll
    for (int r = 0; r < R; r++) {
        int row = r0 + r;
        int rr = row < M ? row : M - 1;
        float invi = 1.f / (float)max(cnt_i[rr], 1);
        float invu = 1.f / (float)max(cnt_u[rr], 1);
        ((float*)si[r])[col] = acc_i[(size_t)rr * D + col] * invi;
        ((float*)su[r])[col] = acc_u[(size_t)rr * D + col] * invu;
    }
    __syncthreads();
    float acc[R];
#pragma unroll
    for (int r = 0; r < R; r++) acc[r] = 0.f;
#pragma unroll 4
    for (int kq = 0; kq < 32; kq++) {
        float wi0 = Wi[(4 * kq + 0) * D + col], wi1 = Wi[(4 * kq + 1) * D + col];
        float wi2 = Wi[(4 * kq + 2) * D + col], wi3 = Wi[(4 * kq + 3) * D + col];
        float wu0 = Wu[(4 * kq + 0) * D + col], wu1 = Wu[(4 * kq + 1) * D + col];
        float wu2 = Wu[(4 * kq + 2) * D + col], wu3 = Wu[(4 * kq + 3) * D + col];
#pragma unroll
        for (int r = 0; r < R; r++) {
            float4 a = si[r][kq], u = su[r][kq];
            acc[r] += a.x * wi0 + a.y * wi1 + a.z * wi2 + a.w * wi3
                    + u.x * wu0 + u.y * wu1 + u.z * wu2 + u.w * wu3;
        }
    }
    float bb = bi[col] + bu[col];
#pragma unroll
    for (int r = 0; r < R; r++) {
        int row = r0 + r;
        if (row < M) out[(size_t)row * D + col] = fmaxf(acc[r] + bb, 0.f);
    }
}

// g2 = relu(...) -> emitted directly as fp16 for the tensor GEMM
template <int R>
__global__ void g2_kernel(const float* __restrict__ acc_i, const float* __restrict__ acc_u,
                          const float* __restrict__ g1,
                          const int* __restrict__ cnt_i, const int* __restrict__ cnt_u,
                          const float* __restrict__ Wi, const float* __restrict__ Wu,
                          const float* __restrict__ Wg1, const float* __restrict__ Wg2,
                          const float* __restrict__ bi, const float* __restrict__ bu,
                          __half* __restrict__ af, int M)
{
    __shared__ float4 si[R][32];
    __shared__ float4 su[R][32];
    __shared__ float4 sg[R][32];
    int col = threadIdx.x;
    int r0 = blockIdx.x * R;
#pragma unroll
    for (int r = 0; r < R; r++) {
        int row = r0 + r;
        int rr = row < M ? row : M - 1;
        float invi = 1.f / (float)max(cnt_i[rr], 1);
        float invu = 1.f / (float)max(cnt_u[rr], 1);
        ((float*)si[r])[col] = acc_i[(size_t)rr * D + col] * invi;
        ((float*)su[r])[col] = acc_u[(size_t)rr * D + col] * invu;
        ((float*)sg[r])[col] = g1[(size_t)rr * D + col];
    }
    __syncthreads();
    float acc[R];
#pragma unroll
    for (int r = 0; r < R; r++) acc[r] = 0.f;
#pragma unroll 2
    for (int kq = 0; kq < 32; kq++) {
        float wi0 = Wi[(4 * kq + 0) * D + col], wi1 = Wi[(4 * kq + 1) * D + col];
        float wi2 = Wi[(4 * kq + 2) * D + col], wi3 = Wi[(4 * kq + 3) * D + col];
        float wu0 = Wu[(4 * kq + 0) * D + col], wu1 = Wu[(4 * kq + 1) * D + col];
        float wu2 = Wu[(4 * kq + 2) * D + col], wu3 = Wu[(4 * kq + 3) * D + col];
        float wg0 = Wg1[(4 * kq + 0) * D + col] + Wg2[(4 * kq + 0) * D + col];
        float wg1 = Wg1[(4 * kq + 1) * D + col] + Wg2[(4 * kq + 1) * D + col];
        float wg2 = Wg1[(4 * kq + 2) * D + col] + Wg2[(4 * kq + 2) * D + col];
        float wg3 = Wg1[(4 * kq + 3) * D + col] + Wg2[(4 * kq + 3) * D + col];
#pragma unroll
        for (int r = 0; r < R; r++) {
            float4 a = si[r][kq], u = su[r][kq], g = sg[r][kq];
            acc[r] += a.x * wi0 + a.y * wi1 + a.z * wi2 + a.w * wi3
                    + u.x * wu0 + u.y * wu1 + u.z * wu2 + u.w * wu3
                    + g.x * wg0 + g.y * wg1 + g.z * wg2 + g.w * wg3;
        }
    }
    float bb = bi[col] + bu[col];
#pragma unroll
    for (int r = 0; r < R; r++) {
        int row = r0 + r;
        if (row < M)
            af[(size_t)row * D + col] = __float2half_rn(fmaxf(acc[r] + bb, 0.f));
    }
}

// ---------------- fp16 tensor-core final GEMM: C = A @ B^T + bias --------------
__global__ void __launch_bounds__(256, 1)
gemm_f16(const __half* __restrict__ A, const __half* __restrict__ B,
         const float* __restrict__ bias, float* __restrict__ C, int M, int N)
{
    extern __shared__ __half sm[];
    __half* As = sm;
    __half* Bs = As + 128 * SMSTRIDE;

    int tid = threadIdx.x;
    int m0 = blockIdx.y * 128, n0 = blockIdx.x * 128;

    uint4 zz = make_uint4(0, 0, 0, 0);
    for (int idx = tid; idx < 2048; idx += 256) {
        int row = idx >> 4;
        int c8 = (idx & 15) << 3;
        int gm = m0 + row;
        uint4 va = zz;
        if (gm < M) va = *(const uint4*)(A + (size_t)gm * 128 + c8);
        *(uint4*)(As + row * SMSTRIDE + c8) = va;
        int gn = n0 + row;
        uint4 vb = zz;
        if (gn < N) vb = *(const uint4*)(B + (size_t)gn * 128 + c8);
        *(uint4*)(Bs + row * SMSTRIDE + c8) = vb;
    }
    __syncthreads();

    int lane = tid & 31, w = tid >> 5;
    int wm = w >> 2, wn = w & 3;
    int r = lane >> 2, c2 = (lane & 3) * 2;

    float acc[4][4][4];
#pragma unroll
    for (int i = 0; i < 4; i++)
#pragma unroll
        for (int j = 0; j < 4; j++)
#pragma unroll
            for (int q = 0; q < 4; q++) acc[i][j][q] = 0.f;

#pragma unroll
    for (int ks = 0; ks < 8; ks++) {
        int kb = ks * 16 + c2;
        uint32_t a[4][4], b[4][2];
#pragma unroll
        for (int i = 0; i < 4; i++) {
            const __half* pa = As + (wm * 64 + i * 16 + r) * SMSTRIDE + kb;
            a[i][0] = *(const uint32_t*)(pa);
            a[i][1] = *(const uint32_t*)(pa + 8 * SMSTRIDE);
            a[i][2] = *(const uint32_t*)(pa + 8);
            a[i][3] = *(const uint32_t*)(pa + 8 * SMSTRIDE + 8);
        }
#pragma unroll
        for (int j = 0; j < 4; j++) {
            const __half* pb = Bs + (wn * 32 + j * 8 + r) * SMSTRIDE + kb;
            b[j][0] = *(const uint32_t*)(pb);
            b[j][1] = *(const uint32_t*)(pb + 8);
        }
#pragma unroll
        for (int i = 0; i < 4; i++)
#pragma unroll
            for (int j = 0; j < 4; j++)
                mma16816(acc[i][j], a[i], b[j]);
    }

#pragma unroll
    for (int i = 0; i < 4; i++) {
#pragma unroll
        for (int j = 0; j < 4; j++) {
            int m = m0 + wm * 64 + i * 16 + r;
            int n = n0 + wn * 32 + j * 8 + c2;
            if (n < N) {
                float bx = __ldg(bias + n), by = __ldg(bias + n + 1);
                if (m < M) {
                    float2 o = make_float2(acc[i][j][0] + bx, acc[i][j][1] + by);
                    *(float2*)(C + (size_t)m * N + n) = o;
                }
                if (m + 8 < M) {
                    float2 o = make_float2(acc[i][j][2] + bx, acc[i][j][3] + by);
                    *(float2*)(C + (size_t)(m + 8) * N + n) = o;
                }
            }
        }
    }
}

// ------------------------------ launcher ---------------------------------------
extern "C" void kernel_launch(void* const* d_in, const int* in_sizes, int n_in,
                              void* d_out, int out_size)
{
    const int*   gi_src  = (const int*)d_in[3];
    const int*   gi_dst  = (const int*)d_in[4];
    const int*   gu_src  = (const int*)d_in[5];
    const int*   gu_dst  = (const int*)d_in[6];
    const float* emb_u   = (const float*)d_in[8];
    const float* emb_i   = (const float*)d_in[9];
    const float* Wl1     = (const float*)d_in[10];
    const float* Wr1     = (const float*)d_in[11];
    const float* b1      = (const float*)d_in[12];
    const float* Wl2     = (const float*)d_in[13];
    const float* Wr2     = (const float*)d_in[14];
    const float* b2      = (const float*)d_in[15];
    const float* Wp      = (const float*)d_in[16];
    const float* bp      = (const float*)d_in[17];
    float*       out     = (float*)d_out;

    float4 *acc_i, *acc_u, *acc2_i, *acc2_u;
    int *cnt_i, *cnt_u;
    float *g1p;
    __half *embih, *embuh, *wt, *i1h, *u1h, *af, *bf;
    cudaGetSymbolAddress((void**)&acc_i,  g_acc_i);
    cudaGetSymbolAddress((void**)&acc_u,  g_acc_u);
    cudaGetSymbolAddress((void**)&acc2_i, g_acc2_i);
    cudaGetSymbolAddress((void**)&acc2_u, g_acc2_u);
    cudaGetSymbolAddress((void**)&cnt_i,  g_cnt_i);
    cudaGetSymbolAddress((void**)&cnt_u,  g_cnt_u);
    cudaGetSymbolAddress((void**)&g1p,    g_g1);
    cudaGetSymbolAddress((void**)&embih,  g_embih);
    cudaGetSymbolAddress((void**)&embuh,  g_embuh);
    cudaGetSymbolAddress((void**)&wt,     g_Wt);
    cudaGetSymbolAddress((void**)&i1h,    g_i1h);
    cudaGetSymbolAddress((void**)&u1h,    g_u1h);
    cudaGetSymbolAddress((void**)&af,     g_Af);
    cudaGetSymbolAddress((void**)&bf,     g_Bf);

    size_t accBytes = (size_t)NGc * D * sizeof(float);
    cudaMemsetAsync(acc_i,  0, accBytes);
    cudaMemsetAsync(acc_u,  0, accBytes);
    cudaMemsetAsync(acc2_i, 0, accBytes);
    cudaMemsetAsync(acc2_u, 0, accBytes);
    cudaMemsetAsync(cnt_i,  0, NGc * sizeof(int));
    cudaMemsetAsync(cnt_u,  0, NGc * sizeof(int));

    int smemBytes = 2 * 128 * SMSTRIDE * sizeof(__half);
    cudaFuncSetAttribute(lin_gemm_f16, cudaFuncAttributeMaxDynamicSharedMemorySize, smemBytes);
    cudaFuncSetAttribute(gemm_f16,     cudaFuncAttributeMaxDynamicSharedMemorySize, smemBytes);

    // conversions (off the dependency chain where possible)
    conv_wp_kernel<<<dim3(NIc / 32, D / 32), 256>>>(Wp, bf);
    conv_h_kernel<<<(NIc * 32 + 255) / 256, 256>>>((const float4*)emb_i, (uint2*)embih, NIc * 32);
    conv_h_kernel<<<(NUc * 32 + 255) / 256, 256>>>((const float4*)emb_u, (uint2*)embuh, NUc * 32);
    conv_w128_kernel<<<dim3(4, 4), 256>>>(Wr1 + 0 * D * D, wt);           // Wr1[0]^T
    conv_w128_kernel<<<dim3(4, 4), 256>>>(Wr1 + 2 * D * D, wt + D * D);   // Wr1[2]^T

    // layer-1 scatter (merged, fp32 feats, counts)
    scatter1_kernel<<<50000, 256>>>(gi_src, gi_dst, (const float4*)emb_i,
                                    gu_src, gu_dst, (const float4*)emb_u,
                                    acc_i, acc_u, cnt_i, cnt_u);

    g1_kernel<8><<<(NGc + 7) / 8, 128>>>((const float*)acc_i, (const float*)acc_u,
                                         cnt_i, cnt_u,
                                         Wl1 + 1 * D * D, Wl1 + 3 * D * D,
                                         b1 + 1 * D, b1 + 3 * D, g1p, NGc);

    // i1 / u1 via fp16 tensor GEMMs (relu fused, fp16 out)
    lin_gemm_f16<<<(NIc + 127) / 128, 256, smemBytes>>>(embih, wt,         b1 + 0 * D, i1h, NIc);
    lin_gemm_f16<<<(NUc + 127) / 128, 256, smemBytes>>>(embuh, wt + D * D, b1 + 2 * D, u1h, NUc);

    // layer-2 scatter (merged, fp16 feats)
    scatter2_kernel<<<50000, 256>>>(gi_src, gi_dst, (const uint2*)i1h,
                                    gu_src, gu_dst, (const uint2*)u1h,
                                    acc2_i, acc2_u);

    g2_kernel<8><<<(NGc + 7) / 8, 128>>>((const float*)acc2_i, (const float*)acc2_u, g1p,
                                         cnt_i, cnt_u,
                                         Wl2 + 1 * D * D, Wl2 + 3 * D * D,
                                         Wr2 + 1 * D * D, Wr2 + 3 * D * D,
                                         b2 + 1 * D, b2 + 3 * D, af, NGc);

    // out = g2 @ WpT^T + bp  via fp16 tensor GEMM
    dim3 grid((NIc + 127) / 128, (NGc + 127) / 128);
    gemm_f16<<<grid, 256, smemBytes>>>(af, bf, bp, out, NGc, NIc);
}

// round 7
// speedup vs baseline: 2.2654x; 1.0832x over previous
#include <cuda_runtime.h>
#include <cuda_fp16.h>
#include <cstdint>

#define D    128
#define NGc  10000
#define NUc  100000
#define NIc  20000
#define EGIc 400000
#define EGUc 400000

// ---------------- scratch (device globals; no allocation allowed) -------------
__device__ float4 g_acc_i[NGc * 32];
__device__ float4 g_acc_u[NGc * 32];
__device__ float4 g_acc2_i[NGc * 32];
__device__ float4 g_acc2_u[NGc * 32];
__device__ int    g_cnt_i[NGc];
__device__ int    g_cnt_u[NGc];
__device__ __half g_embih[NIc * D];     // emb_item fp16
__device__ __half g_embuh[NUc * D];     // emb_user fp16
__device__ __half g_Wt[2 * D * D];      // Wr1[0]^T, Wr1[2]^T fp16
__device__ __half g_W1c[D * 256];       // [Wl1[1];Wl1[3]]^T cat  [n][k] k=256
__device__ __half g_W2c[D * 384];       // [Wl2[1];Wl2[3];Wr2[1]+Wr2[3]]^T cat k=384
__device__ uint2  g_X1[NGc * 64];       // [aggI/c, aggU/c] fp16, 256 cols
__device__ uint2  g_X2[NGc * 96];       // [agg2I/c, agg2U/c, g1] fp16, 384 cols
__device__ __half g_i1h[NIc * D];       // i1 fp16
__device__ __half g_u1h[NUc * D];       // u1 fp16
__device__ __half g_Af[NGc * D];        // g2 fp16
__device__ __half g_Bf[NIc * D];        // WpT fp16: [n][k]

// ---------------- helpers -------------------------------------------------------
__device__ __forceinline__ float4 h4_to_f4(uint2 r)
{
    __half2 a = *(__half2*)&r.x;
    __half2 b = *(__half2*)&r.y;
    float2 fa = __half22float2(a), fb = __half22float2(b);
    return make_float4(fa.x, fa.y, fb.x, fb.y);
}
__device__ __forceinline__ uint2 f4_to_h4(float4 v)
{
    __half2 a = __floats2half2_rn(v.x, v.y);
    __half2 b = __floats2half2_rn(v.z, v.w);
    uint2 r;
    r.x = *(uint32_t*)&a;
    r.y = *(uint32_t*)&b;
    return r;
}

// ---------------- fp32 -> fp16 elementwise --------------------------------------
__global__ void conv_h_kernel(const float4* __restrict__ x, uint2* __restrict__ y, int n4)
{
    int i = blockIdx.x * blockDim.x + threadIdx.x;
    if (i >= n4) return;
    y[i] = f4_to_h4(x[i]);
}

// -------- W [128,128] k-major fp32 -> fp16 transpose into slice -----------------
__global__ void conv_w128_slice(const float* __restrict__ W, __half* __restrict__ Wt,
                                int ldw, int koff)
{
    __shared__ float t[32][33];
    int c0 = blockIdx.x * 32, k0 = blockIdx.y * 32;
    int tx = threadIdx.x & 31, ty = threadIdx.x >> 5;
#pragma unroll
    for (int r = ty; r < 32; r += 8)
        t[r][tx] = W[(k0 + r) * D + c0 + tx];
    __syncthreads();
#pragma unroll
    for (int r = ty; r < 32; r += 8)
        Wt[(size_t)(c0 + r) * ldw + koff + k0 + tx] = __float2half_rn(t[tx][r]);
}

__global__ void conv_w128_slice_sum(const float* __restrict__ Wa, const float* __restrict__ Wb,
                                    __half* __restrict__ Wt, int ldw, int koff)
{
    __shared__ float t[32][33];
    int c0 = blockIdx.x * 32, k0 = blockIdx.y * 32;
    int tx = threadIdx.x & 31, ty = threadIdx.x >> 5;
#pragma unroll
    for (int r = ty; r < 32; r += 8)
        t[r][tx] = Wa[(k0 + r) * D + c0 + tx] + Wb[(k0 + r) * D + c0 + tx];
    __syncthreads();
#pragma unroll
    for (int r = ty; r < 32; r += 8)
        Wt[(size_t)(c0 + r) * ldw + koff + k0 + tx] = __float2half_rn(t[tx][r]);
}

// ------- Wp [128,20000] fp32 -> WpT [20000,128] fp16 (tiled transpose) ----------
__global__ void conv_wp_kernel(const float* __restrict__ Wp, __half* __restrict__ bf)
{
    __shared__ float t[32][33];
    int n0 = blockIdx.x * 32, k0 = blockIdx.y * 32;
    int tx = threadIdx.x & 31, ty = threadIdx.x >> 5;
#pragma unroll
    for (int r = ty; r < 32; r += 8)
        t[r][tx] = Wp[(size_t)(k0 + r) * NIc + n0 + tx];
    __syncthreads();
#pragma unroll
    for (int r = ty; r < 32; r += 8) {
        int n = n0 + r, k = k0 + tx;
        bf[(size_t)n * D + k] = __float2half_rn(t[tx][r]);
    }
}

// ------- merged layer-1 scatter: fp16 gathers, fp32 atomics, counts -------------
__global__ void scatter1_kernel(const int* __restrict__ gi_s, const int* __restrict__ gi_d,
                                const uint2* __restrict__ fi,
                                const int* __restrict__ gu_s, const int* __restrict__ gu_d,
                                const uint2* __restrict__ fu,
                                float4* __restrict__ acc_i, float4* __restrict__ acc_u,
                                int* __restrict__ cnt_i, int* __restrict__ cnt_u)
{
    int warp = (blockIdx.x * blockDim.x + threadIdx.x) >> 5;
    int lane = threadIdx.x & 31;
    const int WI = EGIc / 2;
    const int WU = EGUc / 2;
    if (warp < WI) {
        int e0 = warp * 2;
        int g0 = __ldg(gi_s + e0), n0 = __ldg(gi_d + e0);
        int g1 = __ldg(gi_s + e0 + 1), n1 = __ldg(gi_d + e0 + 1);
        uint2 r0 = __ldg(fi + (size_t)n0 * 32 + lane);
        uint2 r1 = __ldg(fi + (size_t)n1 * 32 + lane);
        atomicAdd(acc_i + (size_t)g0 * 32 + lane, h4_to_f4(r0));
        atomicAdd(acc_i + (size_t)g1 * 32 + lane, h4_to_f4(r1));
        if (lane == 0) { atomicAdd(cnt_i + g0, 1); atomicAdd(cnt_i + g1, 1); }
    } else if (warp < WI + WU) {
        int e0 = (warp - WI) * 2;
        int g0 = __ldg(gu_s + e0), n0 = __ldg(gu_d + e0);
        int g1 = __ldg(gu_s + e0 + 1), n1 = __ldg(gu_d + e0 + 1);
        uint2 r0 = __ldg(fu + (size_t)n0 * 32 + lane);
        uint2 r1 = __ldg(fu + (size_t)n1 * 32 + lane);
        atomicAdd(acc_u + (size_t)g0 * 32 + lane, h4_to_f4(r0));
        atomicAdd(acc_u + (size_t)g1 * 32 + lane, h4_to_f4(r1));
        if (lane == 0) { atomicAdd(cnt_u + g0, 1); atomicAdd(cnt_u + g1, 1); }
    }
}

// ------- merged layer-2 scatter: fp16 gathers, no counts ------------------------
__global__ void scatter2_kernel(const int* __restrict__ gi_s, const int* __restrict__ gi_d,
                                const uint2* __restrict__ fi,
                                const int* __restrict__ gu_s, const int* __restrict__ gu_d,
                                const uint2* __restrict__ fu,
                                float4* __restrict__ acc_i, float4* __restrict__ acc_u)
{
    int warp = (blockIdx.x * blockDim.x + threadIdx.x) >> 5;
    int lane = threadIdx.x & 31;
    const int WI = EGIc / 2;
    const int WU = EGUc / 2;
    if (warp < WI) {
        int e0 = warp * 2;
        int g0 = __ldg(gi_s + e0), n0 = __ldg(gi_d + e0);
        int g1 = __ldg(gi_s + e0 + 1), n1 = __ldg(gi_d + e0 + 1);
        uint2 r0 = __ldg(fi + (size_t)n0 * 32 + lane);
        uint2 r1 = __ldg(fi + (size_t)n1 * 32 + lane);
        atomicAdd(acc_i + (size_t)g0 * 32 + lane, h4_to_f4(r0));
        atomicAdd(acc_i + (size_t)g1 * 32 + lane, h4_to_f4(r1));
    } else if (warp < WI + WU) {
        int e0 = (warp - WI) * 2;
        int g0 = __ldg(gu_s + e0), n0 = __ldg(gu_d + e0);
        int g1 = __ldg(gu_s + e0 + 1), n1 = __ldg(gu_d + e0 + 1);
        uint2 r0 = __ldg(fu + (size_t)n0 * 32 + lane);
        uint2 r1 = __ldg(fu + (size_t)n1 * 32 + lane);
        atomicAdd(acc_u + (size_t)g0 * 32 + lane, h4_to_f4(r0));
        atomicAdd(acc_u + (size_t)g1 * 32 + lane, h4_to_f4(r1));
    }
}

// ------- prep: build fp16 concat [acc_i/c, acc_u/c] rows (64 uint2 cols) --------
__global__ void prep_cat_kernel(const float4* __restrict__ acc_i, const float4* __restrict__ acc_u,
                                const int* __restrict__ ci, const int* __restrict__ cu,
                                uint2* __restrict__ X, int ldx, int M)
{
    int idx = blockIdx.x * blockDim.x + threadIdx.x;
    int row = idx >> 6, q = idx & 63;
    if (row >= M) return;
    float4 v;
    float inv;
    if (q < 32) {
        v = acc_i[(size_t)row * 32 + q];
        inv = 1.f / (float)max(ci[row], 1);
    } else {
        v = acc_u[(size_t)row * 32 + q - 32];
        inv = 1.f / (float)max(cu[row], 1);
    }
    v.x *= inv; v.y *= inv; v.z *= inv; v.w *= inv;
    X[(size_t)row * ldx + q] = f4_to_h4(v);
}

// ================= fp16 HMMA building block =====================================
__device__ __forceinline__ void mma16816(float* c, const uint32_t* a, const uint32_t* b)
{
    asm volatile(
        "mma.sync.aligned.m16n8k16.row.col.f32.f16.f16.f32 "
        "{%0,%1,%2,%3}, {%4,%5,%6,%7}, {%8,%9}, {%0,%1,%2,%3};\n"
        : "+f"(c[0]), "+f"(c[1]), "+f"(c[2]), "+f"(c[3])
        : "r"(a[0]), "r"(a[1]), "r"(a[2]), "r"(a[3]), "r"(b[0]), "r"(b[1]));
}

#define SMSTRIDE 136   // halves per smem row (padded)

// ------ generic: out[M,128] = relu(X[M,K] @ Wt[128,K]^T + ba + bb) in fp16 ------
// 64-row M-tile, full N=128, K-loop in chunks of 128. 8 warps (1m x 8n).
__global__ void __launch_bounds__(256, 1)
gcat_gemm(const __half* __restrict__ X, int ldx, int K,
          const __half* __restrict__ Wt,
          const float* __restrict__ ba, const float* __restrict__ bb,
          __half* __restrict__ out, int ldo, int M)
{
    extern __shared__ __half sm[];
    __half* As = sm;                       // 64 x SMSTRIDE
    __half* Bs = As + 64 * SMSTRIDE;       // 128 x SMSTRIDE

    int tid = threadIdx.x;
    int m0 = blockIdx.x * 64;
    int lane = tid & 31, w = tid >> 5;
    int r = lane >> 2, c2 = (lane & 3) * 2;

    float acc[4][2][4];
#pragma unroll
    for (int i = 0; i < 4; i++)
#pragma unroll
        for (int j = 0; j < 2; j++)
#pragma unroll
            for (int q = 0; q < 4; q++) acc[i][j][q] = 0.f;

    uint4 zz = make_uint4(0, 0, 0, 0);
    for (int k0 = 0; k0 < K; k0 += 128) {
        __syncthreads();
#pragma unroll
        for (int it = 0; it < 4; it++) {           // A: 64 rows x 16 chunks
            int idx = tid + it * 256;
            int row = idx >> 4, c8 = (idx & 15) << 3;
            int gm = m0 + row;
            uint4 v = zz;
            if (gm < M) v = *(const uint4*)(X + (size_t)gm * ldx + k0 + c8);
            *(uint4*)(As + row * SMSTRIDE + c8) = v;
        }
#pragma unroll
        for (int it = 0; it < 8; it++) {           // B: 128 rows x 16 chunks
            int idx = tid + it * 256;
            int row = idx >> 4, c8 = (idx & 15) << 3;
            *(uint4*)(Bs + row * SMSTRIDE + c8) = *(const uint4*)(Wt + (size_t)row * K + k0 + c8);
        }
        __syncthreads();

#pragma unroll
        for (int ks = 0; ks < 8; ks++) {
            int kb = ks * 16 + c2;
            uint32_t a[4][4], b[2][2];
#pragma unroll
            for (int i = 0; i < 4; i++) {
                const __half* pa = As + (i * 16 + r) * SMSTRIDE + kb;
                a[i][0] = *(const uint32_t*)(pa);
                a[i][1] = *(const uint32_t*)(pa + 8 * SMSTRIDE);
                a[i][2] = *(const uint32_t*)(pa + 8);
                a[i][3] = *(const uint32_t*)(pa + 8 * SMSTRIDE + 8);
            }
#pragma unroll
            for (int j = 0; j < 2; j++) {
                const __half* pb = Bs + (w * 16 + j * 8 + r) * SMSTRIDE + kb;
                b[j][0] = *(const uint32_t*)(pb);
                b[j][1] = *(const uint32_t*)(pb + 8);
            }
#pragma unroll
            for (int i = 0; i < 4; i++)
#pragma unroll
                for (int j = 0; j < 2; j++)
                    mma16816(acc[i][j], a[i], b[j]);
        }
    }

#pragma unroll
    for (int i = 0; i < 4; i++) {
#pragma unroll
        for (int j = 0; j < 2; j++) {
            int m = m0 + i * 16 + r;
            int n = w * 16 + j * 8 + c2;
            float bx = __ldg(ba + n) + (bb ? __ldg(bb + n) : 0.f);
            float by = __ldg(ba + n + 1) + (bb ? __ldg(bb + n + 1) : 0.f);
            if (m < M) {
                __half2 h = __floats2half2_rn(fmaxf(acc[i][j][0] + bx, 0.f),
                                              fmaxf(acc[i][j][1] + by, 0.f));
                *(__half2*)(out + (size_t)m * ldo + n) = h;
            }
            if (m + 8 < M) {
                __half2 h = __floats2half2_rn(fmaxf(acc[i][j][2] + bx, 0.f),
                                              fmaxf(acc[i][j][3] + by, 0.f));
                *(__half2*)(out + (size_t)(m + 8) * ldo + n) = h;
            }
        }
    }
}

// ------- out[M,128] = relu(fp16 X[M,128] @ Wt^T + b) fp16, 128-row tiles --------
__global__ void __launch_bounds__(256, 1)
lin_gemm_f16(const __half* __restrict__ X, const __half* __restrict__ Wt,
             const float* __restrict__ b, __half* __restrict__ out, int M)
{
    extern __shared__ __half sm[];
    __half* As = sm;
    __half* Bs = As + 128 * SMSTRIDE;

    int tid = threadIdx.x;
    int m0 = blockIdx.x * 128;

    uint4 zz = make_uint4(0, 0, 0, 0);
    for (int idx = tid; idx < 2048; idx += 256) {
        int row = idx >> 4;
        int c8 = (idx & 15) << 3;
        int gm = m0 + row;
        uint4 va = zz;
        if (gm < M) va = *(const uint4*)(X + (size_t)gm * 128 + c8);
        *(uint4*)(As + row * SMSTRIDE + c8) = va;
        *(uint4*)(Bs + row * SMSTRIDE + c8) = *(const uint4*)(Wt + (size_t)row * 128 + c8);
    }
    __syncthreads();

    int lane = tid & 31, w = tid >> 5;
    int wm = w >> 2, wn = w & 3;
    int r = lane >> 2, c2 = (lane & 3) * 2;

    float acc[4][4][4];
#pragma unroll
    for (int i = 0; i < 4; i++)
#pragma unroll
        for (int j = 0; j < 4; j++)
#pragma unroll
            for (int q = 0; q < 4; q++) acc[i][j][q] = 0.f;

#pragma unroll
    for (int ks = 0; ks < 8; ks++) {
        int kb = ks * 16 + c2;
        uint32_t a[4][4], bb[4][2];
#pragma unroll
        for (int i = 0; i < 4; i++) {
            const __half* pa = As + (wm * 64 + i * 16 + r) * SMSTRIDE + kb;
            a[i][0] = *(const uint32_t*)(pa);
            a[i][1] = *(const uint32_t*)(pa + 8 * SMSTRIDE);
            a[i][2] = *(const uint32_t*)(pa + 8);
            a[i][3] = *(const uint32_t*)(pa + 8 * SMSTRIDE + 8);
        }
#pragma unroll
        for (int j = 0; j < 4; j++) {
            const __half* pb = Bs + (wn * 32 + j * 8 + r) * SMSTRIDE + kb;
            bb[j][0] = *(const uint32_t*)(pb);
            bb[j][1] = *(const uint32_t*)(pb + 8);
        }
#pragma unroll
        for (int i = 0; i < 4; i++)
#pragma unroll
            for (int j = 0; j < 4; j++)
                mma16816(acc[i][j], a[i], bb[j]);
    }

#pragma unroll
    for (int i = 0; i < 4; i++) {
#pragma unroll
        for (int j = 0; j < 4; j++) {
            int m = m0 + wm * 64 + i * 16 + r;
            int n = wn * 32 + j * 8 + c2;
            float bx = __ldg(b + n), by = __ldg(b + n + 1);
            if (m < M) {
                __half2 h = __floats2half2_rn(fmaxf(acc[i][j][0] + bx, 0.f),
                                              fmaxf(acc[i][j][1] + by, 0.f));
                *(__half2*)(out + (size_t)m * 128 + n) = h;
            }
            if (m + 8 < M) {
                __half2 h = __floats2half2_rn(fmaxf(acc[i][j][2] + bx, 0.f),
                                              fmaxf(acc[i][j][3] + by, 0.f));
                *(__half2*)(out + (size_t)(m + 8) * 128 + n) = h;
            }
        }
    }
}

// ---------------- fp16 tensor-core final GEMM: C = A @ B^T + bias ---------------
__global__ void __launch_bounds__(256, 1)
gemm_f16(const __half* __restrict__ A, const __half* __restrict__ B,
         const float* __restrict__ bias, float* __restrict__ C, int M, int N)
{
    extern __shared__ __half sm[];
    __half* As = sm;
    __half* Bs = As + 128 * SMSTRIDE;

    int tid = threadIdx.x;
    int m0 = blockIdx.y * 128, n0 = blockIdx.x * 128;

    uint4 zz = make_uint4(0, 0, 0, 0);
    for (int idx = tid; idx < 2048; idx += 256) {
        int row = idx >> 4;
        int c8 = (idx & 15) << 3;
        int gm = m0 + row;
        uint4 va = zz;
        if (gm < M) va = *(const uint4*)(A + (size_t)gm * 128 + c8);
        *(uint4*)(As + row * SMSTRIDE + c8) = va;
        int gn = n0 + row;
        uint4 vb = zz;
        if (gn < N) vb = *(const uint4*)(B + (size_t)gn * 128 + c8);
        *(uint4*)(Bs + row * SMSTRIDE + c8) = vb;
    }
    __syncthreads();

    int lane = tid & 31, w = tid >> 5;
    int wm = w >> 2, wn = w & 3;
    int r = lane >> 2, c2 = (lane & 3) * 2;

    float acc[4][4][4];
#pragma unroll
    for (int i = 0; i < 4; i++)
#pragma unroll
        for (int j = 0; j < 4; j++)
#pragma unroll
            for (int q = 0; q < 4; q++) acc[i][j][q] = 0.f;

#pragma unroll
    for (int ks = 0; ks < 8; ks++) {
        int kb = ks * 16 + c2;
        uint32_t a[4][4], b[4][2];
#pragma unroll
        for (int i = 0; i < 4; i++) {
            const __half* pa = As + (wm * 64 + i * 16 + r) * SMSTRIDE + kb;
            a[i][0] = *(const uint32_t*)(pa);
            a[i][1] = *(const uint32_t*)(pa + 8 * SMSTRIDE);
            a[i][2] = *(const uint32_t*)(pa + 8);
            a[i][3] = *(const uint32_t*)(pa + 8 * SMSTRIDE + 8);
        }
#pragma unroll
        for (int j = 0; j < 4; j++) {
            const __half* pb = Bs + (wn * 32 + j * 8 + r) * SMSTRIDE + kb;
            b[j][0] = *(const uint32_t*)(pb);
            b[j][1] = *(const uint32_t*)(pb + 8);
        }
#pragma unroll
        for (int i = 0; i < 4; i++)
#pragma unroll
            for (int j = 0; j < 4; j++)
                mma16816(acc[i][j], a[i], b[j]);
    }

#pragma unroll
    for (int i = 0; i < 4; i++) {
#pragma unroll
        for (int j = 0; j < 4; j++) {
            int m = m0 + wm * 64 + i * 16 + r;
            int n = n0 + wn * 32 + j * 8 + c2;
            if (n < N) {
                float bx = __ldg(bias + n), by = __ldg(bias + n + 1);
                if (m < M) {
                    float2 o = make_float2(acc[i][j][0] + bx, acc[i][j][1] + by);
                    *(float2*)(C + (size_t)m * N + n) = o;
                }
                if (m + 8 < M) {
                    float2 o = make_float2(acc[i][j][2] + bx, acc[i][j][3] + by);
                    *(float2*)(C + (size_t)(m + 8) * N + n) = o;
                }
            }
        }
    }
}

// ------------------------------ launcher ----------------------------------------
extern "C" void kernel_launch(void* const* d_in, const int* in_sizes, int n_in,
                              void* d_out, int out_size)
{
    const int*   gi_src  = (const int*)d_in[3];
    const int*   gi_dst  = (const int*)d_in[4];
    const int*   gu_src  = (const int*)d_in[5];
    const int*   gu_dst  = (const int*)d_in[6];
    const float* emb_u   = (const float*)d_in[8];
    const float* emb_i   = (const float*)d_in[9];
    const float* Wl1     = (const float*)d_in[10];
    const float* Wr1     = (const float*)d_in[11];
    const float* b1      = (const float*)d_in[12];
    const float* Wl2     = (const float*)d_in[13];
    const float* Wr2     = (const float*)d_in[14];
    const float* b2      = (const float*)d_in[15];
    const float* Wp      = (const float*)d_in[16];
    const float* bp      = (const float*)d_in[17];
    float*       out     = (float*)d_out;

    float4 *acc_i, *acc_u, *acc2_i, *acc2_u;
    int *cnt_i, *cnt_u;
    __half *embih, *embuh, *wt, *w1c, *w2c, *i1h, *u1h, *af, *bf;
    uint2 *x1, *x2;
    cudaGetSymbolAddress((void**)&acc_i,  g_acc_i);
    cudaGetSymbolAddress((void**)&acc_u,  g_acc_u);
    cudaGetSymbolAddress((void**)&acc2_i, g_acc2_i);
    cudaGetSymbolAddress((void**)&acc2_u, g_acc2_u);
    cudaGetSymbolAddress((void**)&cnt_i,  g_cnt_i);
    cudaGetSymbolAddress((void**)&cnt_u,  g_cnt_u);
    cudaGetSymbolAddress((void**)&embih,  g_embih);
    cudaGetSymbolAddress((void**)&embuh,  g_embuh);
    cudaGetSymbolAddress((void**)&wt,     g_Wt);
    cudaGetSymbolAddress((void**)&w1c,    g_W1c);
    cudaGetSymbolAddress((void**)&w2c,    g_W2c);
    cudaGetSymbolAddress((void**)&x1,     g_X1);
    cudaGetSymbolAddress((void**)&x2,     g_X2);
    cudaGetSymbolAddress((void**)&i1h,    g_i1h);
    cudaGetSymbolAddress((void**)&u1h,    g_u1h);
    cudaGetSymbolAddress((void**)&af,     g_Af);
    cudaGetSymbolAddress((void**)&bf,     g_Bf);

    size_t accBytes = (size_t)NGc * D * sizeof(float);
    cudaMemsetAsync(acc_i,  0, accBytes);
    cudaMemsetAsync(acc_u,  0, accBytes);
    cudaMemsetAsync(acc2_i, 0, accBytes);
    cudaMemsetAsync(acc2_u, 0, accBytes);
    cudaMemsetAsync(cnt_i,  0, NGc * sizeof(int));
    cudaMemsetAsync(cnt_u,  0, NGc * sizeof(int));

    int smemLin  = 2 * 128 * SMSTRIDE * sizeof(__half);
    int smemGcat = (64 + 128) * SMSTRIDE * sizeof(__half);
    cudaFuncSetAttribute(lin_gemm_f16, cudaFuncAttributeMaxDynamicSharedMemorySize, smemLin);
    cudaFuncSetAttribute(gemm_f16,     cudaFuncAttributeMaxDynamicSharedMemorySize, smemLin);
    cudaFuncSetAttribute(gcat_gemm,    cudaFuncAttributeMaxDynamicSharedMemorySize, smemGcat);

    // conversions / weight prep (off the critical dependency chain)
    conv_h_kernel<<<(NIc * 32 + 255) / 256, 256>>>((const float4*)emb_i, (uint2*)embih, NIc * 32);
    conv_h_kernel<<<(NUc * 32 + 255) / 256, 256>>>((const float4*)emb_u, (uint2*)embuh, NUc * 32);
    conv_wp_kernel<<<dim3(NIc / 32, D / 32), 256>>>(Wp, bf);
    conv_w128_slice<<<dim3(4, 4), 256>>>(Wr1 + 0 * D * D, wt, 128, 0);
    conv_w128_slice<<<dim3(4, 4), 256>>>(Wr1 + 2 * D * D, wt + D * D, 128, 0);
    conv_w128_slice<<<dim3(4, 4), 256>>>(Wl1 + 1 * D * D, w1c, 256, 0);
    conv_w128_slice<<<dim3(4, 4), 256>>>(Wl1 + 3 * D * D, w1c, 256, 128);
    conv_w128_slice<<<dim3(4, 4), 256>>>(Wl2 + 1 * D * D, w2c, 384, 0);
    conv_w128_slice<<<dim3(4, 4), 256>>>(Wl2 + 3 * D * D, w2c, 384, 128);
    conv_w128_slice_sum<<<dim3(4, 4), 256>>>(Wr2 + 1 * D * D, Wr2 + 3 * D * D, w2c, 384, 256);

    // layer-1 scatter (fp16 gathers, fp32 atomics, counts)
    scatter1_kernel<<<50000, 256>>>(gi_src, gi_dst, (const uint2*)embih,
                                    gu_src, gu_dst, (const uint2*)embuh,
                                    acc_i, acc_u, cnt_i, cnt_u);

    // i1 / u1 via fp16 tensor GEMMs
    lin_gemm_f16<<<(NIc + 127) / 128, 256, smemLin>>>(embih, wt,         b1 + 0 * D, i1h, NIc);
    lin_gemm_f16<<<(NUc + 127) / 128, 256, smemLin>>>(embuh, wt + D * D, b1 + 2 * D, u1h, NUc);

    // X1 = [aggI/c, aggU/c] fp16; g1 = relu(X1 @ W1c^T + b) -> X2 cols 256..383
    prep_cat_kernel<<<(NGc * 64 + 255) / 256, 256>>>(acc_i, acc_u, cnt_i, cnt_u, x1, 64, NGc);
    gcat_gemm<<<(NGc + 63) / 64, 256, smemGcat>>>((const __half*)x1, 256, 256, w1c,
                                                  b1 + 1 * D, b1 + 3 * D,
                                                  (__half*)x2 + 256, 384, NGc);

    // layer-2 scatter (fp16 gathers)
    scatter2_kernel<<<50000, 256>>>(gi_src, gi_dst, (const uint2*)i1h,
                                    gu_src, gu_dst, (const uint2*)u1h,
                                    acc2_i, acc2_u);

    // X2 cols 0..255 = [agg2I/c, agg2U/c]; g2 = relu(X2 @ W2c^T + b) -> af
    prep_cat_kernel<<<(NGc * 64 + 255) / 256, 256>>>(acc2_i, acc2_u, cnt_i, cnt_u, x2, 96, NGc);
    gcat_gemm<<<(NGc + 63) / 64, 256, smemGcat>>>((const __half*)x2, 384, 384, w2c,
                                                  b2 + 1 * D, b2 + 3 * D,
                                                  af, 128, NGc);

    // out = g2 @ WpT^T + bp  via fp16 tensor GEMM
    dim3 grid((NIc + 127) / 128, (NGc + 127) / 128);
    gemm_f16<<<grid, 256, smemLin>>>(af, bf, bp, out, NGc, NIc);
}

// round 8
// speedup vs baseline: 2.4075x; 1.0627x over previous
#include <cuda_runtime.h>
#include <cuda_fp16.h>
#include <cstdint>

#define D    128
#define NGc  10000
#define NUc  100000
#define NIc  20000
#define EGIc 400000
#define EGUc 400000

// ---------------- scratch (device globals; no allocation allowed) -------------
struct ZeroRegion {
    float4 acc_i[NGc * 32];
    float4 acc_u[NGc * 32];
    float4 acc2_i[NGc * 32];
    float4 acc2_u[NGc * 32];
    int    cnt_i[NGc];
    int    cnt_u[NGc];
};
__device__ ZeroRegion g_zr;

__device__ __half g_embih[NIc * D];     // emb_item fp16
__device__ __half g_embuh[NUc * D];     // emb_user fp16
__device__ __half g_Wt[2 * D * D];      // Wr1[0]^T, Wr1[2]^T fp16
__device__ __half g_W1c[D * 256];       // [Wl1[1];Wl1[3]]^T cat  [n][k] k=256
__device__ __half g_W2c[D * 384];       // [Wl2[1];Wl2[3];Wr2[1]+Wr2[3]]^T cat k=384
__device__ __half g_g1h[NGc * D];       // g1 fp16
__device__ __half g_i1h[NIc * D];       // i1 fp16
__device__ __half g_u1h[NUc * D];       // u1 fp16
__device__ __half g_Af[NGc * D];        // g2 fp16
__device__ __half g_Bf[NIc * D];        // WpT fp16: [n][k]

// ---------------- helpers -------------------------------------------------------
__device__ __forceinline__ float4 h4_to_f4(uint2 r)
{
    __half2 a = *(__half2*)&r.x;
    __half2 b = *(__half2*)&r.y;
    float2 fa = __half22float2(a), fb = __half22float2(b);
    return make_float4(fa.x, fa.y, fb.x, fb.y);
}
__device__ __forceinline__ uint2 f4_to_h4(float4 v)
{
    __half2 a = __floats2half2_rn(v.x, v.y);
    __half2 b = __floats2half2_rn(v.z, v.w);
    uint2 r;
    r.x = *(uint32_t*)&a;
    r.y = *(uint32_t*)&b;
    return r;
}

// ---------------- merged emb fp32 -> fp16 ----------------------------------------
__global__ void conv_emb_kernel(const float4* __restrict__ xi, const float4* __restrict__ xu,
                                uint2* __restrict__ yi, uint2* __restrict__ yu)
{
    int i = blockIdx.x * blockDim.x + threadIdx.x;
    const int NI4 = NIc * 32;
    const int NU4 = NUc * 32;
    if (i < NI4) {
        yi[i] = f4_to_h4(xi[i]);
    } else if (i < NI4 + NU4) {
        int j = i - NI4;
        yu[j] = f4_to_h4(xu[j]);
    }
}

// -------- batched 128x128 weight transposes: 7 jobs in one launch ----------------
__global__ void conv_wbatch_kernel(const float* __restrict__ Wr1, const float* __restrict__ Wl1,
                                   const float* __restrict__ Wl2, const float* __restrict__ Wr2,
                                   __half* __restrict__ wt, __half* __restrict__ w1c,
                                   __half* __restrict__ w2c)
{
    __shared__ float t[32][33];
    int job = blockIdx.z;
    const float* src = nullptr;
    const float* src2 = nullptr;
    __half* dst = nullptr;
    int ldw = 128, koff = 0;
    switch (job) {
        case 0: src = Wr1;               dst = wt;          ldw = 128; koff = 0;   break;
        case 1: src = Wr1 + 2 * D * D;   dst = wt + D * D;  ldw = 128; koff = 0;   break;
        case 2: src = Wl1 + 1 * D * D;   dst = w1c;         ldw = 256; koff = 0;   break;
        case 3: src = Wl1 + 3 * D * D;   dst = w1c;         ldw = 256; koff = 128; break;
        case 4: src = Wl2 + 1 * D * D;   dst = w2c;         ldw = 384; koff = 0;   break;
        case 5: src = Wl2 + 3 * D * D;   dst = w2c;         ldw = 384; koff = 128; break;
        default: src = Wr2 + 1 * D * D;  src2 = Wr2 + 3 * D * D; dst = w2c; ldw = 384; koff = 256; break;
    }
    int c0 = blockIdx.x * 32, k0 = blockIdx.y * 32;
    int tx = threadIdx.x & 31, ty = threadIdx.x >> 5;
#pragma unroll
    for (int r = ty; r < 32; r += 8) {
        float v = src[(k0 + r) * D + c0 + tx];
        if (src2) v += src2[(k0 + r) * D + c0 + tx];
        t[r][tx] = v;
    }
    __syncthreads();
#pragma unroll
    for (int r = ty; r < 32; r += 8)
        dst[(size_t)(c0 + r) * ldw + koff + k0 + tx] = __float2half_rn(t[tx][r]);
}

// ------- Wp [128,20000] fp32 -> WpT [20000,128] fp16 (tiled transpose) ----------
__global__ void conv_wp_kernel(const float* __restrict__ Wp, __half* __restrict__ bf)
{
    __shared__ float t[32][33];
    int n0 = blockIdx.x * 32, k0 = blockIdx.y * 32;
    int tx = threadIdx.x & 31, ty = threadIdx.x >> 5;
#pragma unroll
    for (int r = ty; r < 32; r += 8)
        t[r][tx] = Wp[(size_t)(k0 + r) * NIc + n0 + tx];
    __syncthreads();
#pragma unroll
    for (int r = ty; r < 32; r += 8) {
        int n = n0 + r, k = k0 + tx;
        bf[(size_t)n * D + k] = __float2half_rn(t[tx][r]);
    }
}

// ------- merged layer-1 scatter: fp16 gathers, fp32 atomics, counts; 4 e/warp ---
__global__ void scatter1_kernel(const int* __restrict__ gi_s, const int* __restrict__ gi_d,
                                const uint2* __restrict__ fi,
                                const int* __restrict__ gu_s, const int* __restrict__ gu_d,
                                const uint2* __restrict__ fu,
                                float4* __restrict__ acc_i, float4* __restrict__ acc_u,
                                int* __restrict__ cnt_i, int* __restrict__ cnt_u)
{
    int warp = (blockIdx.x * blockDim.x + threadIdx.x) >> 5;
    int lane = threadIdx.x & 31;
    const int WI = EGIc / 4;
    const int WU = EGUc / 4;
    if (warp < WI) {
        int e0 = warp * 4;
        int g[4], n[4];
#pragma unroll
        for (int t = 0; t < 4; t++) { g[t] = __ldg(gi_s + e0 + t); n[t] = __ldg(gi_d + e0 + t); }
        uint2 r[4];
#pragma unroll
        for (int t = 0; t < 4; t++) r[t] = __ldg(fi + (size_t)n[t] * 32 + lane);
#pragma unroll
        for (int t = 0; t < 4; t++) atomicAdd(acc_i + (size_t)g[t] * 32 + lane, h4_to_f4(r[t]));
        if (lane == 0) {
#pragma unroll
            for (int t = 0; t < 4; t++) atomicAdd(cnt_i + g[t], 1);
        }
    } else if (warp < WI + WU) {
        int e0 = (warp - WI) * 4;
        int g[4], n[4];
#pragma unroll
        for (int t = 0; t < 4; t++) { g[t] = __ldg(gu_s + e0 + t); n[t] = __ldg(gu_d + e0 + t); }
        uint2 r[4];
#pragma unroll
        for (int t = 0; t < 4; t++) r[t] = __ldg(fu + (size_t)n[t] * 32 + lane);
#pragma unroll
        for (int t = 0; t < 4; t++) atomicAdd(acc_u + (size_t)g[t] * 32 + lane, h4_to_f4(r[t]));
        if (lane == 0) {
#pragma unroll
            for (int t = 0; t < 4; t++) atomicAdd(cnt_u + g[t], 1);
        }
    }
}

// ------- merged layer-2 scatter: fp16 gathers, no counts; 4 e/warp --------------
__global__ void scatter2_kernel(const int* __restrict__ gi_s, const int* __restrict__ gi_d,
                                const uint2* __restrict__ fi,
                                const int* __restrict__ gu_s, const int* __restrict__ gu_d,
                                const uint2* __restrict__ fu,
                                float4* __restrict__ acc_i, float4* __restrict__ acc_u)
{
    int warp = (blockIdx.x * blockDim.x + threadIdx.x) >> 5;
    int lane = threadIdx.x & 31;
    const int WI = EGIc / 4;
    const int WU = EGUc / 4;
    if (warp < WI) {
        int e0 = warp * 4;
        int g[4], n[4];
#pragma unroll
        for (int t = 0; t < 4; t++) { g[t] = __ldg(gi_s + e0 + t); n[t] = __ldg(gi_d + e0 + t); }
        uint2 r[4];
#pragma unroll
        for (int t = 0; t < 4; t++) r[t] = __ldg(fi + (size_t)n[t] * 32 + lane);
#pragma unroll
        for (int t = 0; t < 4; t++) atomicAdd(acc_i + (size_t)g[t] * 32 + lane, h4_to_f4(r[t]));
    } else if (warp < WI + WU) {
        int e0 = (warp - WI) * 4;
        int g[4], n[4];
#pragma unroll
        for (int t = 0; t < 4; t++) { g[t] = __ldg(gu_s + e0 + t); n[t] = __ldg(gu_d + e0 + t); }
        uint2 r[4];
#pragma unroll
        for (int t = 0; t < 4; t++) r[t] = __ldg(fu + (size_t)n[t] * 32 + lane);
#pragma unroll
        for (int t = 0; t < 4; t++) atomicAdd(acc_u + (size_t)g[t] * 32 + lane, h4_to_f4(r[t]));
    }
}

// ================= fp16 HMMA building block =====================================
__device__ __forceinline__ void mma16816(float* c, const uint32_t* a, const uint32_t* b)
{
    asm volatile(
        "mma.sync.aligned.m16n8k16.row.col.f32.f16.f16.f32 "
        "{%0,%1,%2,%3}, {%4,%5,%6,%7}, {%8,%9}, {%0,%1,%2,%3};\n"
        : "+f"(c[0]), "+f"(c[1]), "+f"(c[2]), "+f"(c[3])
        : "r"(a[0]), "r"(a[1]), "r"(a[2]), "r"(a[3]), "r"(b[0]), "r"(b[1]));
}

#define SMSTRIDE 136   // halves per smem row (padded)

// ----- fused concat GEMM core: 64-row M-tile, N=128, chunked K ------------------
// Chunk sources: fp32 acc (scaled by 1/cnt) or fp16 dense. Shared by g1/g2.
struct ChunkAccF32 { const float4* acc; const int* cnt; };

__device__ __forceinline__ void load_chunk_f32(__half* As, const float4* acc, const int* cnt,
                                               int m0, int M, int tid)
{
#pragma unroll
    for (int it = 0; it < 8; it++) {
        int idx = tid + it * 256;            // 0..2047
        int row = idx >> 5, q = idx & 31;    // row 0..63, q = float4 idx 0..31
        int gm = m0 + row;
        float4 v = make_float4(0.f, 0.f, 0.f, 0.f);
        if (gm < M) {
            v = __ldg(acc + (size_t)gm * 32 + q);
            float inv = 1.f / (float)max(__ldg(cnt + gm), 1);
            v.x *= inv; v.y *= inv; v.z *= inv; v.w *= inv;
        }
        *(uint2*)(As + row * SMSTRIDE + q * 4) = f4_to_h4(v);
    }
}

__device__ __forceinline__ void load_chunk_f16(__half* As, const __half* X,
                                               int m0, int M, int tid)
{
    uint4 zz = make_uint4(0, 0, 0, 0);
#pragma unroll
    for (int it = 0; it < 4; it++) {
        int idx = tid + it * 256;            // 0..1023
        int row = idx >> 4, c8 = (idx & 15) << 3;
        int gm = m0 + row;
        uint4 v = zz;
        if (gm < M) v = *(const uint4*)(X + (size_t)gm * 128 + c8);
        *(uint4*)(As + row * SMSTRIDE + c8) = v;
    }
}

__device__ __forceinline__ void load_chunk_B(__half* Bs, const __half* Wt, int K, int k0, int tid)
{
#pragma unroll
    for (int it = 0; it < 8; it++) {
        int idx = tid + it * 256;
        int row = idx >> 4, c8 = (idx & 15) << 3;
        *(uint4*)(Bs + row * SMSTRIDE + c8) = *(const uint4*)(Wt + (size_t)row * K + k0 + c8);
    }
}

__device__ __forceinline__ void mma_chunk(const __half* As, const __half* Bs,
                                          float acc[4][2][4], int w, int r, int c2)
{
#pragma unroll
    for (int ks = 0; ks < 8; ks++) {
        int kb = ks * 16 + c2;
        uint32_t a[4][4], b[2][2];
#pragma unroll
        for (int i = 0; i < 4; i++) {
            const __half* pa = As + (i * 16 + r) * SMSTRIDE + kb;
            a[i][0] = *(const uint32_t*)(pa);
            a[i][1] = *(const uint32_t*)(pa + 8 * SMSTRIDE);
            a[i][2] = *(const uint32_t*)(pa + 8);
            a[i][3] = *(const uint32_t*)(pa + 8 * SMSTRIDE + 8);
        }
#pragma unroll
        for (int j = 0; j < 2; j++) {
            const __half* pb = Bs + (w * 16 + j * 8 + r) * SMSTRIDE + kb;
            b[j][0] = *(const uint32_t*)(pb);
            b[j][1] = *(const uint32_t*)(pb + 8);
        }
#pragma unroll
        for (int i = 0; i < 4; i++)
#pragma unroll
            for (int j = 0; j < 2; j++)
                mma16816(acc[i][j], a[i], b[j]);
    }
}

__device__ __forceinline__ void epilogue_relu_h(float acc[4][2][4], const float* ba,
                                                const float* bb, __half* out, int ldo,
                                                int m0, int M, int w, int r, int c2)
{
#pragma unroll
    for (int i = 0; i < 4; i++) {
#pragma unroll
        for (int j = 0; j < 2; j++) {
            int m = m0 + i * 16 + r;
            int n = w * 16 + j * 8 + c2;
            float bx = __ldg(ba + n) + __ldg(bb + n);
            float by = __ldg(ba + n + 1) + __ldg(bb + n + 1);
            if (m < M) {
                __half2 h = __floats2half2_rn(fmaxf(acc[i][j][0] + bx, 0.f),
                                              fmaxf(acc[i][j][1] + by, 0.f));
                *(__half2*)(out + (size_t)m * ldo + n) = h;
            }
            if (m + 8 < M) {
                __half2 h = __floats2half2_rn(fmaxf(acc[i][j][2] + bx, 0.f),
                                              fmaxf(acc[i][j][3] + by, 0.f));
                *(__half2*)(out + (size_t)(m + 8) * ldo + n) = h;
            }
        }
    }
}

// g1 = relu([aggI/c, aggU/c] @ W1c^T + b1[1]+b1[3])  K=256
__global__ void __launch_bounds__(256, 2)
g1_gemm(const float4* __restrict__ acc_i, const float4* __restrict__ acc_u,
        const int* __restrict__ cnt_i, const int* __restrict__ cnt_u,
        const __half* __restrict__ W1c, const float* __restrict__ ba,
        const float* __restrict__ bb, __half* __restrict__ out, int M)
{
    extern __shared__ __half sm[];
    __half* As = sm;
    __half* Bs = As + 64 * SMSTRIDE;
    int tid = threadIdx.x;
    int m0 = blockIdx.x * 64;
    int lane = tid & 31, w = tid >> 5;
    int r = lane >> 2, c2 = (lane & 3) * 2;

    float acc[4][2][4];
#pragma unroll
    for (int i = 0; i < 4; i++)
#pragma unroll
        for (int j = 0; j < 2; j++)
#pragma unroll
            for (int q = 0; q < 4; q++) acc[i][j][q] = 0.f;

#pragma unroll
    for (int ch = 0; ch < 2; ch++) {
        __syncthreads();
        load_chunk_f32(As, ch == 0 ? acc_i : acc_u, ch == 0 ? cnt_i : cnt_u, m0, M, tid);
        load_chunk_B(Bs, W1c, 256, ch * 128, tid);
        __syncthreads();
        mma_chunk(As, Bs, acc, w, r, c2);
    }
    epilogue_relu_h(acc, ba, bb, out, 128, m0, M, w, r, c2);
}

// g2 = relu([agg2I/c, agg2U/c, g1] @ W2c^T + b2[1]+b2[3])  K=384
__global__ void __launch_bounds__(256, 2)
g2_gemm(const float4* __restrict__ acc_i, const float4* __restrict__ acc_u,
        const int* __restrict__ cnt_i, const int* __restrict__ cnt_u,
        const __half* __restrict__ g1h,
        const __half* __restrict__ W2c, const float* __restrict__ ba,
        const float* __restrict__ bb, __half* __restrict__ out, int M)
{
    extern __shared__ __half sm[];
    __half* As = sm;
    __half* Bs = As + 64 * SMSTRIDE;
    int tid = threadIdx.x;
    int m0 = blockIdx.x * 64;
    int lane = tid & 31, w = tid >> 5;
    int r = lane >> 2, c2 = (lane & 3) * 2;

    float acc[4][2][4];
#pragma unroll
    for (int i = 0; i < 4; i++)
#pragma unroll
        for (int j = 0; j < 2; j++)
#pragma unroll
            for (int q = 0; q < 4; q++) acc[i][j][q] = 0.f;

#pragma unroll
    for (int ch = 0; ch < 3; ch++) {
        __syncthreads();
        if (ch == 0)      load_chunk_f32(As, acc_i, cnt_i, m0, M, tid);
        else if (ch == 1) load_chunk_f32(As, acc_u, cnt_u, m0, M, tid);
        else              load_chunk_f16(As, g1h, m0, M, tid);
        load_chunk_B(Bs, W2c, 384, ch * 128, tid);
        __syncthreads();
        mma_chunk(As, Bs, acc, w, r, c2);
    }
    epilogue_relu_h(acc, ba, bb, out, 128, m0, M, w, r, c2);
}

// ------- out[M,128] = relu(fp16 X[M,128] @ Wt^T + b) fp16, 128-row tiles --------
__global__ void __launch_bounds__(256, 2)
lin_gemm_f16(const __half* __restrict__ X, const __half* __restrict__ Wt,
             const float* __restrict__ b, __half* __restrict__ out, int M)
{
    extern __shared__ __half sm[];
    __half* As = sm;
    __half* Bs = As + 128 * SMSTRIDE;

    int tid = threadIdx.x;
    int m0 = blockIdx.x * 128;

    uint4 zz = make_uint4(0, 0, 0, 0);
    for (int idx = tid; idx < 2048; idx += 256) {
        int row = idx >> 4;
        int c8 = (idx & 15) << 3;
        int gm = m0 + row;
        uint4 va = zz;
        if (gm < M) va = *(const uint4*)(X + (size_t)gm * 128 + c8);
        *(uint4*)(As + row * SMSTRIDE + c8) = va;
        *(uint4*)(Bs + row * SMSTRIDE + c8) = *(const uint4*)(Wt + (size_t)row * 128 + c8);
    }
    __syncthreads();

    int lane = tid & 31, w = tid >> 5;
    int wm = w >> 2, wn = w & 3;
    int r = lane >> 2, c2 = (lane & 3) * 2;

    float acc[4][4][4];
#pragma unroll
    for (int i = 0; i < 4; i++)
#pragma unroll
        for (int j = 0; j < 4; j++)
#pragma unroll
            for (int q = 0; q < 4; q++) acc[i][j][q] = 0.f;

#pragma unroll
    for (int ks = 0; ks < 8; ks++) {
        int kb = ks * 16 + c2;
        uint32_t a[4][4], bb[4][2];
#pragma unroll
        for (int i = 0; i < 4; i++) {
            const __half* pa = As + (wm * 64 + i * 16 + r) * SMSTRIDE + kb;
            a[i][0] = *(const uint32_t*)(pa);
            a[i][1] = *(const uint32_t*)(pa + 8 * SMSTRIDE);
            a[i][2] = *(const uint32_t*)(pa + 8);
            a[i][3] = *(const uint32_t*)(pa + 8 * SMSTRIDE + 8);
        }
#pragma unroll
        for (int j = 0; j < 4; j++) {
            const __half* pb = Bs + (wn * 32 + j * 8 + r) * SMSTRIDE + kb;
            bb[j][0] = *(const uint32_t*)(pb);
            bb[j][1] = *(const uint32_t*)(pb + 8);
        }
#pragma unroll
        for (int i = 0; i < 4; i++)
#pragma unroll
            for (int j = 0; j < 4; j++)
                mma16816(acc[i][j], a[i], bb[j]);
    }

#pragma unroll
    for (int i = 0; i < 4; i++) {
#pragma unroll
        for (int j = 0; j < 4; j++) {
            int m = m0 + wm * 64 + i * 16 + r;
            int n = wn * 32 + j * 8 + c2;
            float bx = __ldg(b + n), by = __ldg(b + n + 1);
            if (m < M) {
                __half2 h = __floats2half2_rn(fmaxf(acc[i][j][0] + bx, 0.f),
                                              fmaxf(acc[i][j][1] + by, 0.f));
                *(__half2*)(out + (size_t)m * 128 + n) = h;
            }
            if (m + 8 < M) {
                __half2 h = __floats2half2_rn(fmaxf(acc[i][j][2] + bx, 0.f),
                                              fmaxf(acc[i][j][3] + by, 0.f));
                *(__half2*)(out + (size_t)(m + 8) * 128 + n) = h;
            }
        }
    }
}

// ---------------- fp16 tensor-core final GEMM: C = A @ B^T + bias ---------------
__global__ void __launch_bounds__(256, 2)
gemm_f16(const __half* __restrict__ A, const __half* __restrict__ B,
         const float* __restrict__ bias, float* __restrict__ C, int M, int N)
{
    extern __shared__ __half sm[];
    __half* As = sm;
    __half* Bs = As + 128 * SMSTRIDE;

    int tid = threadIdx.x;
    int m0 = blockIdx.y * 128, n0 = blockIdx.x * 128;

    uint4 zz = make_uint4(0, 0, 0, 0);
    for (int idx = tid; idx < 2048; idx += 256) {
        int row = idx >> 4;
        int c8 = (idx & 15) << 3;
        int gm = m0 + row;
        uint4 va = zz;
        if (gm < M) va = *(const uint4*)(A + (size_t)gm * 128 + c8);
        *(uint4*)(As + row * SMSTRIDE + c8) = va;
        int gn = n0 + row;
        uint4 vb = zz;
        if (gn < N) vb = *(const uint4*)(B + (size_t)gn * 128 + c8);
        *(uint4*)(Bs + row * SMSTRIDE + c8) = vb;
    }
    __syncthreads();

    int lane = tid & 31, w = tid >> 5;
    int wm = w >> 2, wn = w & 3;
    int r = lane >> 2, c2 = (lane & 3) * 2;

    float acc[4][4][4];
#pragma unroll
    for (int i = 0; i < 4; i++)
#pragma unroll
        for (int j = 0; j < 4; j++)
#pragma unroll
            for (int q = 0; q < 4; q++) acc[i][j][q] = 0.f;

#pragma unroll
    for (int ks = 0; ks < 8; ks++) {
        int kb = ks * 16 + c2;
        uint32_t a[4][4], b[4][2];
#pragma unroll
        for (int i = 0; i < 4; i++) {
            const __half* pa = As + (wm * 64 + i * 16 + r) * SMSTRIDE + kb;
            a[i][0] = *(const uint32_t*)(pa);
            a[i][1] = *(const uint32_t*)(pa + 8 * SMSTRIDE);
            a[i][2] = *(const uint32_t*)(pa + 8);
            a[i][3] = *(const uint32_t*)(pa + 8 * SMSTRIDE + 8);
        }
#pragma unroll
        for (int j = 0; j < 4; j++) {
            const __half* pb = Bs + (wn * 32 + j * 8 + r) * SMSTRIDE + kb;
            b[j][0] = *(const uint32_t*)(pb);
            b[j][1] = *(const uint32_t*)(pb + 8);
        }
#pragma unroll
        for (int i = 0; i < 4; i++)
#pragma unroll
            for (int j = 0; j < 4; j++)
                mma16816(acc[i][j], a[i], b[j]);
    }

#pragma unroll
    for (int i = 0; i < 4; i++) {
#pragma unroll
        for (int j = 0; j < 4; j++) {
            int m = m0 + wm * 64 + i * 16 + r;
            int n = n0 + wn * 32 + j * 8 + c2;
            if (n < N) {
                float bx = __ldg(bias + n), by = __ldg(bias + n + 1);
                if (m < M) {
                    float2 o = make_float2(acc[i][j][0] + bx, acc[i][j][1] + by);
                    *(float2*)(C + (size_t)m * N + n) = o;
                }
                if (m + 8 < M) {
                    float2 o = make_float2(acc[i][j][2] + bx, acc[i][j][3] + by);
                    *(float2*)(C + (size_t)(m + 8) * N + n) = o;
                }
            }
        }
    }
}

// ------------------------------ launcher ----------------------------------------
extern "C" void kernel_launch(void* const* d_in, const int* in_sizes, int n_in,
                              void* d_out, int out_size)
{
    const int*   gi_src  = (const int*)d_in[3];
    const int*   gi_dst  = (const int*)d_in[4];
    const int*   gu_src  = (const int*)d_in[5];
    const int*   gu_dst  = (const int*)d_in[6];
    const float* emb_u   = (const float*)d_in[8];
    const float* emb_i   = (const float*)d_in[9];
    const float* Wl1     = (const float*)d_in[10];
    const float* Wr1     = (const float*)d_in[11];
    const float* b1      = (const float*)d_in[12];
    const float* Wl2     = (const float*)d_in[13];
    const float* Wr2     = (const float*)d_in[14];
    const float* b2      = (const float*)d_in[15];
    const float* Wp      = (const float*)d_in[16];
    const float* bp      = (const float*)d_in[17];
    float*       out     = (float*)d_out;

    ZeroRegion* zr;
    __half *embih, *embuh, *wt, *w1c, *w2c, *g1h, *i1h, *u1h, *af, *bf;
    cudaGetSymbolAddress((void**)&zr,     g_zr);
    cudaGetSymbolAddress((void**)&embih,  g_embih);
    cudaGetSymbolAddress((void**)&embuh,  g_embuh);
    cudaGetSymbolAddress((void**)&wt,     g_Wt);
    cudaGetSymbolAddress((void**)&w1c,    g_W1c);
    cudaGetSymbolAddress((void**)&w2c,    g_W2c);
    cudaGetSymbolAddress((void**)&g1h,    g_g1h);
    cudaGetSymbolAddress((void**)&i1h,    g_i1h);
    cudaGetSymbolAddress((void**)&u1h,    g_u1h);
    cudaGetSymbolAddress((void**)&af,     g_Af);
    cudaGetSymbolAddress((void**)&bf,     g_Bf);

    float4* acc_i  = zr->acc_i;
    float4* acc_u  = zr->acc_u;
    float4* acc2_i = zr->acc2_i;
    float4* acc2_u = zr->acc2_u;
    int*    cnt_i  = zr->cnt_i;
    int*    cnt_u  = zr->cnt_u;

    // one memset for all accumulators + counts
    cudaMemsetAsync(zr, 0, sizeof(ZeroRegion));

    int smemLin  = 2 * 128 * SMSTRIDE * sizeof(__half);
    int smemGcat = (64 + 128) * SMSTRIDE * sizeof(__half);
    cudaFuncSetAttribute(lin_gemm_f16, cudaFuncAttributeMaxDynamicSharedMemorySize, smemLin);
    cudaFuncSetAttribute(gemm_f16,     cudaFuncAttributeMaxDynamicSharedMemorySize, smemLin);
    cudaFuncSetAttribute(g1_gemm,      cudaFuncAttributeMaxDynamicSharedMemorySize, smemGcat);
    cudaFuncSetAttribute(g2_gemm,      cudaFuncAttributeMaxDynamicSharedMemorySize, smemGcat);

    // conversions / weight prep
    conv_emb_kernel<<<((NIc + NUc) * 32 + 255) / 256, 256>>>((const float4*)emb_i,
                                                             (const float4*)emb_u,
                                                             (uint2*)embih, (uint2*)embuh);
    conv_wp_kernel<<<dim3(NIc / 32, D / 32), 256>>>(Wp, bf);
    conv_wbatch_kernel<<<dim3(4, 4, 7), 256>>>(Wr1, Wl1, Wl2, Wr2, wt, w1c, w2c);

    // layer-1 scatter (fp16 gathers, fp32 atomics, counts); 4 edges/warp
    scatter1_kernel<<<((EGIc + EGUc) / 4 * 32 + 255) / 256, 256>>>(
        gi_src, gi_dst, (const uint2*)embih,
        gu_src, gu_dst, (const uint2*)embuh,
        acc_i, acc_u, cnt_i, cnt_u);

    // i1 / u1 via fp16 tensor GEMMs
    lin_gemm_f16<<<(NIc + 127) / 128, 256, smemLin>>>(embih, wt,         b1 + 0 * D, i1h, NIc);
    lin_gemm_f16<<<(NUc + 127) / 128, 256, smemLin>>>(embuh, wt + D * D, b1 + 2 * D, u1h, NUc);

    // g1 = relu([aggI/c, aggU/c] @ W1c^T + b)
    g1_gemm<<<(NGc + 63) / 64, 256, smemGcat>>>(acc_i, acc_u, cnt_i, cnt_u, w1c,
                                                b1 + 1 * D, b1 + 3 * D, g1h, NGc);

    // layer-2 scatter (fp16 gathers); 4 edges/warp
    scatter2_kernel<<<((EGIc + EGUc) / 4 * 32 + 255) / 256, 256>>>(
        gi_src, gi_dst, (const uint2*)i1h,
        gu_src, gu_dst, (const uint2*)u1h,
        acc2_i, acc2_u);

    // g2 = relu([agg2I/c, agg2U/c, g1] @ W2c^T + b) -> af
    g2_gemm<<<(NGc + 63) / 64, 256, smemGcat>>>(acc2_i, acc2_u, cnt_i, cnt_u, g1h, w2c,
                                                b2 + 1 * D, b2 + 3 * D, af, NGc);

    // out = g2 @ WpT^T + bp  via fp16 tensor GEMM
    dim3 grid((NIc + 127) / 128, (NGc + 127) / 128);
    gemm_f16<<<grid, 256, smemLin>>>(af, bf, bp, out, NGc, NIc);
}

// round 9
// speedup vs baseline: 2.6414x; 1.0971x over previous
#include <cuda_runtime.h>
#include <cuda_fp16.h>
#include <cstdint>

#define D    128
#define NGc  10000
#define NUc  100000
#define NIc  20000
#define EGIc 400000
#define EGUc 400000

// ---------------- scratch (device globals; no allocation allowed) -------------
struct ZeroRegion {
    int cnt_i[NGc];
    int cnt_u[NGc];
    int pos_i[NGc];
    int pos_u[NGc];
};
__device__ ZeroRegion g_zr;

__device__ int    g_off_i[NGc];
__device__ int    g_off_u[NGc];
__device__ int    g_nbr_i[EGIc];
__device__ int    g_nbr_u[EGUc];
__device__ __half g_embih[NIc * D];
__device__ __half g_embuh[NUc * D];
__device__ __half g_Wt[2 * D * D];      // Wr1[0]^T, Wr1[2]^T fp16
__device__ __half g_W1c[D * 256];       // [Wl1[1];Wl1[3]]^T
__device__ __half g_W2c[D * 384];       // [Wl2[1];Wl2[3];Wr2[1]+Wr2[3]]^T
__device__ __half g_X1[NGc * 256];      // [aggI, aggU] fp16
__device__ __half g_X2[NGc * 384];      // [agg2I, agg2U, g1] fp16
__device__ __half g_i1h[NIc * D];
__device__ __half g_u1h[NUc * D];
__device__ __half g_Af[NGc * D];        // g2 fp16
__device__ __half g_Bf[NIc * D];        // WpT fp16: [n][k]

// ---------------- helpers -------------------------------------------------------
__device__ __forceinline__ float4 h4_to_f4(uint2 r)
{
    __half2 a = *(__half2*)&r.x;
    __half2 b = *(__half2*)&r.y;
    float2 fa = __half22float2(a), fb = __half22float2(b);
    return make_float4(fa.x, fa.y, fb.x, fb.y);
}
__device__ __forceinline__ uint2 f4_to_h4(float4 v)
{
    __half2 a = __floats2half2_rn(v.x, v.y);
    __half2 b = __floats2half2_rn(v.z, v.w);
    uint2 r;
    r.x = *(uint32_t*)&a;
    r.y = *(uint32_t*)&b;
    return r;
}

// ---------------- merged emb fp32 -> fp16 ----------------------------------------
__global__ void conv_emb_kernel(const float4* __restrict__ xi, const float4* __restrict__ xu,
                                uint2* __restrict__ yi, uint2* __restrict__ yu)
{
    int i = blockIdx.x * blockDim.x + threadIdx.x;
    const int NI4 = NIc * 32;
    const int NU4 = NUc * 32;
    if (i < NI4) {
        yi[i] = f4_to_h4(xi[i]);
    } else if (i < NI4 + NU4) {
        int j = i - NI4;
        yu[j] = f4_to_h4(xu[j]);
    }
}

// -------- batched 128x128 weight transposes: 7 jobs in one launch ----------------
__global__ void conv_wbatch_kernel(const float* __restrict__ Wr1, const float* __restrict__ Wl1,
                                   const float* __restrict__ Wl2, const float* __restrict__ Wr2,
                                   __half* __restrict__ wt, __half* __restrict__ w1c,
                                   __half* __restrict__ w2c)
{
    __shared__ float t[32][33];
    int job = blockIdx.z;
    const float* src = nullptr;
    const float* src2 = nullptr;
    __half* dst = nullptr;
    int ldw = 128, koff = 0;
    switch (job) {
        case 0: src = Wr1;               dst = wt;          ldw = 128; koff = 0;   break;
        case 1: src = Wr1 + 2 * D * D;   dst = wt + D * D;  ldw = 128; koff = 0;   break;
        case 2: src = Wl1 + 1 * D * D;   dst = w1c;         ldw = 256; koff = 0;   break;
        case 3: src = Wl1 + 3 * D * D;   dst = w1c;         ldw = 256; koff = 128; break;
        case 4: src = Wl2 + 1 * D * D;   dst = w2c;         ldw = 384; koff = 0;   break;
        case 5: src = Wl2 + 3 * D * D;   dst = w2c;         ldw = 384; koff = 128; break;
        default: src = Wr2 + 1 * D * D;  src2 = Wr2 + 3 * D * D; dst = w2c; ldw = 384; koff = 256; break;
    }
    int c0 = blockIdx.x * 32, k0 = blockIdx.y * 32;
    int tx = threadIdx.x & 31, ty = threadIdx.x >> 5;
#pragma unroll
    for (int r = ty; r < 32; r += 8) {
        float v = src[(k0 + r) * D + c0 + tx];
        if (src2) v += src2[(k0 + r) * D + c0 + tx];
        t[r][tx] = v;
    }
    __syncthreads();
#pragma unroll
    for (int r = ty; r < 32; r += 8)
        dst[(size_t)(c0 + r) * ldw + koff + k0 + tx] = __float2half_rn(t[tx][r]);
}

// ------- Wp [128,20000] fp32 -> WpT [20000,128] fp16 (tiled transpose) ----------
__global__ void conv_wp_kernel(const float* __restrict__ Wp, __half* __restrict__ bf)
{
    __shared__ float t[32][33];
    int n0 = blockIdx.x * 32, k0 = blockIdx.y * 32;
    int tx = threadIdx.x & 31, ty = threadIdx.x >> 5;
#pragma unroll
    for (int r = ty; r < 32; r += 8)
        t[r][tx] = Wp[(size_t)(k0 + r) * NIc + n0 + tx];
    __syncthreads();
#pragma unroll
    for (int r = ty; r < 32; r += 8) {
        int n = n0 + r, k = k0 + tx;
        bf[(size_t)n * D + k] = __float2half_rn(t[tx][r]);
    }
}

// ================= CSR build (shared by both layers) ============================
__global__ void hist_kernel(const int* __restrict__ gi_s, const int* __restrict__ gu_s,
                            int* __restrict__ cnt_i, int* __restrict__ cnt_u)
{
    int i = blockIdx.x * blockDim.x + threadIdx.x;
    if (i < EGIc) atomicAdd(cnt_i + __ldg(gi_s + i), 1);
    else if (i < EGIc + EGUc) atomicAdd(cnt_u + __ldg(gu_s + i - EGIc), 1);
}

// single-block exclusive scan (n <= a few 100k); blockIdx.x picks relation
__global__ void __launch_bounds__(1024, 1)
scan_kernel(const int* __restrict__ cnt_i, int* __restrict__ off_i,
            const int* __restrict__ cnt_u, int* __restrict__ off_u, int n)
{
    const int* cnt = blockIdx.x == 0 ? cnt_i : cnt_u;
    int* off = blockIdx.x == 0 ? off_i : off_u;
    __shared__ int sdata[1024];
    __shared__ int carry;
    int tid = threadIdx.x;
    if (tid == 0) carry = 0;
    __syncthreads();
    for (int base = 0; base < n; base += 1024) {
        int i = base + tid;
        int v = (i < n) ? cnt[i] : 0;
        sdata[tid] = v;
        __syncthreads();
        for (int s = 1; s < 1024; s <<= 1) {
            int t = (tid >= s) ? sdata[tid - s] : 0;
            __syncthreads();
            sdata[tid] += t;
            __syncthreads();
        }
        if (i < n) off[i] = carry + sdata[tid] - v;
        __syncthreads();
        if (tid == 1023) carry += sdata[1023];
        __syncthreads();
    }
}

__global__ void fill_kernel(const int* __restrict__ gi_s, const int* __restrict__ gi_d,
                            const int* __restrict__ gu_s, const int* __restrict__ gu_d,
                            const int* __restrict__ off_i, const int* __restrict__ off_u,
                            int* __restrict__ pos_i, int* __restrict__ pos_u,
                            int* __restrict__ nbr_i, int* __restrict__ nbr_u)
{
    int i = blockIdx.x * blockDim.x + threadIdx.x;
    if (i < EGIc) {
        int g = __ldg(gi_s + i);
        int p = atomicAdd(pos_i + g, 1);
        nbr_i[__ldg(off_i + g) + p] = __ldg(gi_d + i);
    } else if (i < EGIc + EGUc) {
        int e = i - EGIc;
        int g = __ldg(gu_s + e);
        int p = atomicAdd(pos_u + g, 1);
        nbr_u[__ldg(off_u + g) + p] = __ldg(gu_d + e);
    }
}

// ===== gather-aggregate: one warp per (group, relation); mean -> fp16 into X ====
__global__ void aggregate_kernel(const int* __restrict__ off_i, const int* __restrict__ nbr_i,
                                 const int* __restrict__ cnt_i, const uint2* __restrict__ fi,
                                 const int* __restrict__ off_u, const int* __restrict__ nbr_u,
                                 const int* __restrict__ cnt_u, const uint2* __restrict__ fu,
                                 __half* __restrict__ X, int ldx)
{
    int gw = (blockIdx.x * blockDim.x + threadIdx.x) >> 5;
    int lane = threadIdx.x & 31;
    if (gw >= 2 * NGc) return;
    bool isU = gw >= NGc;
    int g = isU ? gw - NGc : gw;
    const int* off = isU ? off_u : off_i;
    const int* nbr = isU ? nbr_u : nbr_i;
    const int* cnt = isU ? cnt_u : cnt_i;
    const uint2* f = isU ? fu : fi;

    int base = __ldg(off + g);
    int deg = __ldg(cnt + g);
    float4 acc = make_float4(0.f, 0.f, 0.f, 0.f);
    int j = 0;
    for (; j + 4 <= deg; j += 4) {
        int i0 = __ldg(nbr + base + j);
        int i1 = __ldg(nbr + base + j + 1);
        int i2 = __ldg(nbr + base + j + 2);
        int i3 = __ldg(nbr + base + j + 3);
        uint2 r0 = __ldg(f + (size_t)i0 * 32 + lane);
        uint2 r1 = __ldg(f + (size_t)i1 * 32 + lane);
        uint2 r2 = __ldg(f + (size_t)i2 * 32 + lane);
        uint2 r3 = __ldg(f + (size_t)i3 * 32 + lane);
        float4 v0 = h4_to_f4(r0), v1 = h4_to_f4(r1), v2 = h4_to_f4(r2), v3 = h4_to_f4(r3);
        acc.x += (v0.x + v1.x) + (v2.x + v3.x);
        acc.y += (v0.y + v1.y) + (v2.y + v3.y);
        acc.z += (v0.z + v1.z) + (v2.z + v3.z);
        acc.w += (v0.w + v1.w) + (v2.w + v3.w);
    }
    for (; j < deg; j++) {
        int i0 = __ldg(nbr + base + j);
        float4 v0 = h4_to_f4(__ldg(f + (size_t)i0 * 32 + lane));
        acc.x += v0.x; acc.y += v0.y; acc.z += v0.z; acc.w += v0.w;
    }
    float inv = 1.f / (float)max(deg, 1);
    acc.x *= inv; acc.y *= inv; acc.z *= inv; acc.w *= inv;
    *(uint2*)(X + (size_t)g * ldx + (isU ? 128 : 0) + lane * 4) = f4_to_h4(acc);
}

// ================= fp16 HMMA building block =====================================
__device__ __forceinline__ void mma16816(float* c, const uint32_t* a, const uint32_t* b)
{
    asm volatile(
        "mma.sync.aligned.m16n8k16.row.col.f32.f16.f16.f32 "
        "{%0,%1,%2,%3}, {%4,%5,%6,%7}, {%8,%9}, {%0,%1,%2,%3};\n"
        : "+f"(c[0]), "+f"(c[1]), "+f"(c[2]), "+f"(c[3])
        : "r"(a[0]), "r"(a[1]), "r"(a[2]), "r"(a[3]), "r"(b[0]), "r"(b[1]));
}

#define SMSTRIDE 136   // halves per smem row (padded)

// ------ generic: out[M,128] = relu(X[M,K] @ Wt[128,K]^T + ba + bb) in fp16 ------
__global__ void __launch_bounds__(256, 2)
gcat_gemm(const __half* __restrict__ X, int ldx, int K,
          const __half* __restrict__ Wt,
          const float* __restrict__ ba, const float* __restrict__ bb,
          __half* __restrict__ out, int ldo, int M)
{
    extern __shared__ __half sm[];
    __half* As = sm;                       // 64 x SMSTRIDE
    __half* Bs = As + 64 * SMSTRIDE;       // 128 x SMSTRIDE

    int tid = threadIdx.x;
    int m0 = blockIdx.x * 64;
    int lane = tid & 31, w = tid >> 5;
    int r = lane >> 2, c2 = (lane & 3) * 2;

    float acc[4][2][4];
#pragma unroll
    for (int i = 0; i < 4; i++)
#pragma unroll
        for (int j = 0; j < 2; j++)
#pragma unroll
            for (int q = 0; q < 4; q++) acc[i][j][q] = 0.f;

    uint4 zz = make_uint4(0, 0, 0, 0);
    for (int k0 = 0; k0 < K; k0 += 128) {
        __syncthreads();
#pragma unroll
        for (int it = 0; it < 4; it++) {           // A: 64 rows x 16 chunks
            int idx = tid + it * 256;
            int row = idx >> 4, c8 = (idx & 15) << 3;
            int gm = m0 + row;
            uint4 v = zz;
            if (gm < M) v = *(const uint4*)(X + (size_t)gm * ldx + k0 + c8);
            *(uint4*)(As + row * SMSTRIDE + c8) = v;
        }
#pragma unroll
        for (int it = 0; it < 8; it++) {           // B: 128 rows x 16 chunks
            int idx = tid + it * 256;
            int row = idx >> 4, c8 = (idx & 15) << 3;
            *(uint4*)(Bs + row * SMSTRIDE + c8) = *(const uint4*)(Wt + (size_t)row * K + k0 + c8);
        }
        __syncthreads();

#pragma unroll
        for (int ks = 0; ks < 8; ks++) {
            int kb = ks * 16 + c2;
            uint32_t a[4][4], b[2][2];
#pragma unroll
            for (int i = 0; i < 4; i++) {
                const __half* pa = As + (i * 16 + r) * SMSTRIDE + kb;
                a[i][0] = *(const uint32_t*)(pa);
                a[i][1] = *(const uint32_t*)(pa + 8 * SMSTRIDE);
                a[i][2] = *(const uint32_t*)(pa + 8);
                a[i][3] = *(const uint32_t*)(pa + 8 * SMSTRIDE + 8);
            }
#pragma unroll
            for (int j = 0; j < 2; j++) {
                const __half* pb = Bs + (w * 16 + j * 8 + r) * SMSTRIDE + kb;
                b[j][0] = *(const uint32_t*)(pb);
                b[j][1] = *(const uint32_t*)(pb + 8);
            }
#pragma unroll
            for (int i = 0; i < 4; i++)
#pragma unroll
                for (int j = 0; j < 2; j++)
                    mma16816(acc[i][j], a[i], b[j]);
        }
    }

#pragma unroll
    for (int i = 0; i < 4; i++) {
#pragma unroll
        for (int j = 0; j < 2; j++) {
            int m = m0 + i * 16 + r;
            int n = w * 16 + j * 8 + c2;
            float bx = __ldg(ba + n) + __ldg(bb + n);
            float by = __ldg(ba + n + 1) + __ldg(bb + n + 1);
            if (m < M) {
                __half2 h = __floats2half2_rn(fmaxf(acc[i][j][0] + bx, 0.f),
                                              fmaxf(acc[i][j][1] + by, 0.f));
                *(__half2*)(out + (size_t)m * ldo + n) = h;
            }
            if (m + 8 < M) {
                __half2 h = __floats2half2_rn(fmaxf(acc[i][j][2] + bx, 0.f),
                                              fmaxf(acc[i][j][3] + by, 0.f));
                *(__half2*)(out + (size_t)(m + 8) * ldo + n) = h;
            }
        }
    }
}

// ------- out[M,128] = relu(fp16 X[M,128] @ Wt^T + b) fp16, 128-row tiles --------
__global__ void __launch_bounds__(256, 2)
lin_gemm_f16(const __half* __restrict__ X, const __half* __restrict__ Wt,
             const float* __restrict__ b, __half* __restrict__ out, int M)
{
    extern __shared__ __half sm[];
    __half* As = sm;
    __half* Bs = As + 128 * SMSTRIDE;

    int tid = threadIdx.x;
    int m0 = blockIdx.x * 128;

    uint4 zz = make_uint4(0, 0, 0, 0);
    for (int idx = tid; idx < 2048; idx += 256) {
        int row = idx >> 4;
        int c8 = (idx & 15) << 3;
        int gm = m0 + row;
        uint4 va = zz;
        if (gm < M) va = *(const uint4*)(X + (size_t)gm * 128 + c8);
        *(uint4*)(As + row * SMSTRIDE + c8) = va;
        *(uint4*)(Bs + row * SMSTRIDE + c8) = *(const uint4*)(Wt + (size_t)row * 128 + c8);
    }
    __syncthreads();

    int lane = tid & 31, w = tid >> 5;
    int wm = w >> 2, wn = w & 3;
    int r = lane >> 2, c2 = (lane & 3) * 2;

    float acc[4][4][4];
#pragma unroll
    for (int i = 0; i < 4; i++)
#pragma unroll
        for (int j = 0; j < 4; j++)
#pragma unroll
            for (int q = 0; q < 4; q++) acc[i][j][q] = 0.f;

#pragma unroll
    for (int ks = 0; ks < 8; ks++) {
        int kb = ks * 16 + c2;
        uint32_t a[4][4], bb[4][2];
#pragma unroll
        for (int i = 0; i < 4; i++) {
            const __half* pa = As + (wm * 64 + i * 16 + r) * SMSTRIDE + kb;
            a[i][0] = *(const uint32_t*)(pa);
            a[i][1] = *(const uint32_t*)(pa + 8 * SMSTRIDE);
            a[i][2] = *(const uint32_t*)(pa + 8);
            a[i][3] = *(const uint32_t*)(pa + 8 * SMSTRIDE + 8);
        }
#pragma unroll
        for (int j = 0; j < 4; j++) {
            const __half* pb = Bs + (wn * 32 + j * 8 + r) * SMSTRIDE + kb;
            bb[j][0] = *(const uint32_t*)(pb);
            bb[j][1] = *(const uint32_t*)(pb + 8);
        }
#pragma unroll
        for (int i = 0; i < 4; i++)
#pragma unroll
            for (int j = 0; j < 4; j++)
                mma16816(acc[i][j], a[i], bb[j]);
    }

#pragma unroll
    for (int i = 0; i < 4; i++) {
#pragma unroll
        for (int j = 0; j < 4; j++) {
            int m = m0 + wm * 64 + i * 16 + r;
            int n = wn * 32 + j * 8 + c2;
            float bx = __ldg(b + n), by = __ldg(b + n + 1);
            if (m < M) {
                __half2 h = __floats2half2_rn(fmaxf(acc[i][j][0] + bx, 0.f),
                                              fmaxf(acc[i][j][1] + by, 0.f));
                *(__half2*)(out + (size_t)m * 128 + n) = h;
            }
            if (m + 8 < M) {
                __half2 h = __floats2half2_rn(fmaxf(acc[i][j][2] + bx, 0.f),
                                              fmaxf(acc[i][j][3] + by, 0.f));
                *(__half2*)(out + (size_t)(m + 8) * 128 + n) = h;
            }
        }
    }
}

// ---------------- fp16 tensor-core final GEMM: C = A @ B^T + bias ---------------
__global__ void __launch_bounds__(256, 2)
gemm_f16(const __half* __restrict__ A, const __half* __restrict__ B,
         const float* __restrict__ bias, float* __restrict__ C, int M, int N)
{
    extern __shared__ __half sm[];
    __half* As = sm;
    __half* Bs = As + 128 * SMSTRIDE;

    int tid = threadIdx.x;
    int m0 = blockIdx.y * 128, n0 = blockIdx.x * 128;

    uint4 zz = make_uint4(0, 0, 0, 0);
    for (int idx = tid; idx < 2048; idx += 256) {
        int row = idx >> 4;
        int c8 = (idx & 15) << 3;
        int gm = m0 + row;
        uint4 va = zz;
        if (gm < M) va = *(const uint4*)(A + (size_t)gm * 128 + c8);
        *(uint4*)(As + row * SMSTRIDE + c8) = va;
        int gn = n0 + row;
        uint4 vb = zz;
        if (gn < N) vb = *(const uint4*)(B + (size_t)gn * 128 + c8);
        *(uint4*)(Bs + row * SMSTRIDE + c8) = vb;
    }
    __syncthreads();

    int lane = tid & 31, w = tid >> 5;
    int wm = w >> 2, wn = w & 3;
    int r = lane >> 2, c2 = (lane & 3) * 2;

    float acc[4][4][4];
#pragma unroll
    for (int i = 0; i < 4; i++)
#pragma unroll
        for (int j = 0; j < 4; j++)
#pragma unroll
            for (int q = 0; q < 4; q++) acc[i][j][q] = 0.f;

#pragma unroll
    for (int ks = 0; ks < 8; ks++) {
        int kb = ks * 16 + c2;
        uint32_t a[4][4], b[4][2];
#pragma unroll
        for (int i = 0; i < 4; i++) {
            const __half* pa = As + (wm * 64 + i * 16 + r) * SMSTRIDE + kb;
            a[i][0] = *(const uint32_t*)(pa);
            a[i][1] = *(const uint32_t*)(pa + 8 * SMSTRIDE);
            a[i][2] = *(const uint32_t*)(pa + 8);
            a[i][3] = *(const uint32_t*)(pa + 8 * SMSTRIDE + 8);
        }
#pragma unroll
        for (int j = 0; j < 4; j++) {
            const __half* pb = Bs + (wn * 32 + j * 8 + r) * SMSTRIDE + kb;
            b[j][0] = *(const uint32_t*)(pb);
            b[j][1] = *(const uint32_t*)(pb + 8);
        }
#pragma unroll
        for (int i = 0; i < 4; i++)
#pragma unroll
            for (int j = 0; j < 4; j++)
                mma16816(acc[i][j], a[i], b[j]);
    }

#pragma unroll
    for (int i = 0; i < 4; i++) {
#pragma unroll
        for (int j = 0; j < 4; j++) {
            int m = m0 + wm * 64 + i * 16 + r;
            int n = n0 + wn * 32 + j * 8 + c2;
            if (n < N) {
                float bx = __ldg(bias + n), by = __ldg(bias + n + 1);
                if (m < M) {
                    float2 o = make_float2(acc[i][j][0] + bx, acc[i][j][1] + by);
                    *(float2*)(C + (size_t)m * N + n) = o;
                }
                if (m + 8 < M) {
                    float2 o = make_float2(acc[i][j][2] + bx, acc[i][j][3] + by);
                    *(float2*)(C + (size_t)(m + 8) * N + n) = o;
                }
            }
        }
    }
}

// ------------------------------ launcher ----------------------------------------
extern "C" void kernel_launch(void* const* d_in, const int* in_sizes, int n_in,
                              void* d_out, int out_size)
{
    const int*   gi_src  = (const int*)d_in[3];
    const int*   gi_dst  = (const int*)d_in[4];
    const int*   gu_src  = (const int*)d_in[5];
    const int*   gu_dst  = (const int*)d_in[6];
    const float* emb_u   = (const float*)d_in[8];
    const float* emb_i   = (const float*)d_in[9];
    const float* Wl1     = (const float*)d_in[10];
    const float* Wr1     = (const float*)d_in[11];
    const float* b1      = (const float*)d_in[12];
    const float* Wl2     = (const float*)d_in[13];
    const float* Wr2     = (const float*)d_in[14];
    const float* b2      = (const float*)d_in[15];
    const float* Wp      = (const float*)d_in[16];
    const float* bp      = (const float*)d_in[17];
    float*       out     = (float*)d_out;

    ZeroRegion* zr;
    int *off_i, *off_u, *nbr_i, *nbr_u;
    __half *embih, *embuh, *wt, *w1c, *w2c, *x1, *x2, *i1h, *u1h, *af, *bf;
    cudaGetSymbolAddress((void**)&zr,     g_zr);
    cudaGetSymbolAddress((void**)&off_i,  g_off_i);
    cudaGetSymbolAddress((void**)&off_u,  g_off_u);
    cudaGetSymbolAddress((void**)&nbr_i,  g_nbr_i);
    cudaGetSymbolAddress((void**)&nbr_u,  g_nbr_u);
    cudaGetSymbolAddress((void**)&embih,  g_embih);
    cudaGetSymbolAddress((void**)&embuh,  g_embuh);
    cudaGetSymbolAddress((void**)&wt,     g_Wt);
    cudaGetSymbolAddress((void**)&w1c,    g_W1c);
    cudaGetSymbolAddress((void**)&w2c,    g_W2c);
    cudaGetSymbolAddress((void**)&x1,     g_X1);
    cudaGetSymbolAddress((void**)&x2,     g_X2);
    cudaGetSymbolAddress((void**)&i1h,    g_i1h);
    cudaGetSymbolAddress((void**)&u1h,    g_u1h);
    cudaGetSymbolAddress((void**)&af,     g_Af);
    cudaGetSymbolAddress((void**)&bf,     g_Bf);

    int* cnt_i = zr->cnt_i;
    int* cnt_u = zr->cnt_u;
    int* pos_i = zr->pos_i;
    int* pos_u = zr->pos_u;

    cudaMemsetAsync(zr, 0, sizeof(ZeroRegion));

    int smemLin  = 2 * 128 * SMSTRIDE * sizeof(__half);
    int smemGcat = (64 + 128) * SMSTRIDE * sizeof(__half);
    cudaFuncSetAttribute(lin_gemm_f16, cudaFuncAttributeMaxDynamicSharedMemorySize, smemLin);
    cudaFuncSetAttribute(gemm_f16,     cudaFuncAttributeMaxDynamicSharedMemorySize, smemLin);
    cudaFuncSetAttribute(gcat_gemm,    cudaFuncAttributeMaxDynamicSharedMemorySize, smemGcat);

    // conversions / weight prep
    conv_emb_kernel<<<((NIc + NUc) * 32 + 255) / 256, 256>>>((const float4*)emb_i,
                                                             (const float4*)emb_u,
                                                             (uint2*)embih, (uint2*)embuh);
    conv_wp_kernel<<<dim3(NIc / 32, D / 32), 256>>>(Wp, bf);
    conv_wbatch_kernel<<<dim3(4, 4, 7), 256>>>(Wr1, Wl1, Wl2, Wr2, wt, w1c, w2c);

    // CSR build (once; reused by both layers)
    hist_kernel<<<(EGIc + EGUc + 255) / 256, 256>>>(gi_src, gu_src, cnt_i, cnt_u);
    scan_kernel<<<2, 1024>>>(cnt_i, off_i, cnt_u, off_u, NGc);
    fill_kernel<<<(EGIc + EGUc + 255) / 256, 256>>>(gi_src, gi_dst, gu_src, gu_dst,
                                                    off_i, off_u, pos_i, pos_u, nbr_i, nbr_u);

    // layer-1 aggregate -> X1
    aggregate_kernel<<<(2 * NGc * 32 + 255) / 256, 256>>>(off_i, nbr_i, cnt_i, (const uint2*)embih,
                                                          off_u, nbr_u, cnt_u, (const uint2*)embuh,
                                                          x1, 256);

    // g1 = relu(X1 @ W1c^T + b) -> X2 cols 256..383
    gcat_gemm<<<(NGc + 63) / 64, 256, smemGcat>>>(x1, 256, 256, w1c,
                                                  b1 + 1 * D, b1 + 3 * D, x2 + 256, 384, NGc);

    // i1 / u1 via fp16 tensor GEMMs
    lin_gemm_f16<<<(NIc + 127) / 128, 256, smemLin>>>(embih, wt,         b1 + 0 * D, i1h, NIc);
    lin_gemm_f16<<<(NUc + 127) / 128, 256, smemLin>>>(embuh, wt + D * D, b1 + 2 * D, u1h, NUc);

    // layer-2 aggregate -> X2 cols 0..255
    aggregate_kernel<<<(2 * NGc * 32 + 255) / 256, 256>>>(off_i, nbr_i, cnt_i, (const uint2*)i1h,
                                                          off_u, nbr_u, cnt_u, (const uint2*)u1h,
                                                          x2, 384);

    // g2 = relu(X2 @ W2c^T + b) -> af
    gcat_gemm<<<(NGc + 63) / 64, 256, smemGcat>>>(x2, 384, 384, w2c,
                                                  b2 + 1 * D, b2 + 3 * D, af, 128, NGc);

    // out = g2 @ WpT^T + bp  via fp16 tensor GEMM
    dim3 grid((NIc + 127) / 128, (NGc + 127) / 128);
    gemm_f16<<<grid, 256, smemLin>>>(af, bf, bp, out, NGc, NIc);
}

// round 10
// speedup vs baseline: 2.6603x; 1.0071x over previous
#include <cuda_runtime.h>
#include <cuda_fp16.h>
#include <cstdint>

#define D    128
#define NGc  10000
#define NUc  100000
#define NIc  20000
#define EGIc 400000
#define EGUc 400000

// ---------------- scratch (device globals; no allocation allowed) -------------
struct ZeroRegion {
    int cnt_i[NGc];
    int cnt_u[NGc];
    int pos_i[NGc];
    int pos_u[NGc];
};
__device__ ZeroRegion g_zr;

__device__ int    g_off_i[NGc];
__device__ int    g_off_u[NGc];
__device__ int    g_nbr_i[EGIc];
__device__ int    g_nbr_u[EGUc];
__device__ __half g_embih[NIc * D];
__device__ __half g_embuh[NUc * D];
__device__ __half g_Wt[2 * D * D];      // Wr1[0]^T, Wr1[2]^T fp16
__device__ __half g_W1c[D * 256];       // [Wl1[1];Wl1[3]]^T
__device__ __half g_W2c[D * 384];       // [Wl2[1];Wl2[3];Wr2[1]+Wr2[3]]^T
__device__ __half g_X1[NGc * 256];      // [aggI, aggU] fp16
__device__ __half g_X2[NGc * 384];      // [agg2I, agg2U, g1] fp16
__device__ __half g_i1h[NIc * D];
__device__ __half g_u1h[NUc * D];
__device__ __half g_Af[NGc * D];        // g2 fp16
__device__ __half g_Bf[NIc * D];        // WpT fp16: [n][k]

// ---------------- helpers -------------------------------------------------------
__device__ __forceinline__ float4 h4_to_f4(uint2 r)
{
    __half2 a = *(__half2*)&r.x;
    __half2 b = *(__half2*)&r.y;
    float2 fa = __half22float2(a), fb = __half22float2(b);
    return make_float4(fa.x, fa.y, fb.x, fb.y);
}
__device__ __forceinline__ uint2 f4_to_h4(float4 v)
{
    __half2 a = __floats2half2_rn(v.x, v.y);
    __half2 b = __floats2half2_rn(v.z, v.w);
    uint2 r;
    r.x = *(uint32_t*)&a;
    r.y = *(uint32_t*)&b;
    return r;
}

// ================= fused prep: emb convert + hist + Wp^T + 7 weight^T ===========
#define PREP_EMB_BLK  ((NIc + NUc) * 32 / 256)          // 15000
#define PREP_HIST_BLK ((EGIc + EGUc + 255) / 256)       // 3125
#define PREP_WP_BLK   ((NIc / 32) * (D / 32))           // 2500
#define PREP_WB_BLK   (4 * 4 * 7)                       // 112
#define PREP_TOTAL    (PREP_EMB_BLK + PREP_HIST_BLK + PREP_WP_BLK + PREP_WB_BLK)

__global__ void prep_kernel(const float4* __restrict__ xi, const float4* __restrict__ xu,
                            uint2* __restrict__ yi, uint2* __restrict__ yu,
                            const int* __restrict__ gi_s, const int* __restrict__ gu_s,
                            int* __restrict__ cnt_i, int* __restrict__ cnt_u,
                            const float* __restrict__ Wp, __half* __restrict__ bf,
                            const float* __restrict__ Wr1, const float* __restrict__ Wl1,
                            const float* __restrict__ Wl2, const float* __restrict__ Wr2,
                            __half* __restrict__ wt, __half* __restrict__ w1c,
                            __half* __restrict__ w2c)
{
    __shared__ float t[32][33];
    int b = blockIdx.x;
    int tid = threadIdx.x;

    if (b < PREP_EMB_BLK) {
        // ---- emb fp32 -> fp16 ----
        int i = b * 256 + tid;
        const int NI4 = NIc * 32;
        if (i < NI4) yi[i] = f4_to_h4(xi[i]);
        else         yu[i - NI4] = f4_to_h4(xu[i - NI4]);
        return;
    }
    b -= PREP_EMB_BLK;
    if (b < PREP_HIST_BLK) {
        // ---- edge histogram ----
        int i = b * 256 + tid;
        if (i < EGIc) atomicAdd(cnt_i + __ldg(gi_s + i), 1);
        else if (i < EGIc + EGUc) atomicAdd(cnt_u + __ldg(gu_s + i - EGIc), 1);
        return;
    }
    b -= PREP_HIST_BLK;
    int tx = tid & 31, ty = tid >> 5;
    if (b < PREP_WP_BLK) {
        // ---- Wp [128,20000] -> WpT [20000,128] fp16 ----
        int n0 = (b % (NIc / 32)) * 32;
        int k0 = (b / (NIc / 32)) * 32;
#pragma unroll
        for (int r = ty; r < 32; r += 8)
            t[r][tx] = Wp[(size_t)(k0 + r) * NIc + n0 + tx];
        __syncthreads();
#pragma unroll
        for (int r = ty; r < 32; r += 8)
            bf[(size_t)(n0 + r) * D + k0 + tx] = __float2half_rn(t[tx][r]);
        return;
    }
    b -= PREP_WP_BLK;
    {
        // ---- 7 x 128x128 weight transposes ----
        int job = b >> 4;
        int cx = b & 3, cy = (b >> 2) & 3;
        const float* src = nullptr;
        const float* src2 = nullptr;
        __half* dst = nullptr;
        int ldw = 128, koff = 0;
        switch (job) {
            case 0: src = Wr1;               dst = wt;          ldw = 128; koff = 0;   break;
            case 1: src = Wr1 + 2 * D * D;   dst = wt + D * D;  ldw = 128; koff = 0;   break;
            case 2: src = Wl1 + 1 * D * D;   dst = w1c;         ldw = 256; koff = 0;   break;
            case 3: src = Wl1 + 3 * D * D;   dst = w1c;         ldw = 256; koff = 128; break;
            case 4: src = Wl2 + 1 * D * D;   dst = w2c;         ldw = 384; koff = 0;   break;
            case 5: src = Wl2 + 3 * D * D;   dst = w2c;         ldw = 384; koff = 128; break;
            default: src = Wr2 + 1 * D * D;  src2 = Wr2 + 3 * D * D; dst = w2c; ldw = 384; koff = 256; break;
        }
        int c0 = cx * 32, k0 = cy * 32;
#pragma unroll
        for (int r = ty; r < 32; r += 8) {
            float v = src[(k0 + r) * D + c0 + tx];
            if (src2) v += src2[(k0 + r) * D + c0 + tx];
            t[r][tx] = v;
        }
        __syncthreads();
#pragma unroll
        for (int r = ty; r < 32; r += 8)
            dst[(size_t)(c0 + r) * ldw + koff + k0 + tx] = __float2half_rn(t[tx][r]);
    }
}

// ================= CSR scan + fill ==============================================
__global__ void __launch_bounds__(1024, 1)
scan_kernel(const int* __restrict__ cnt_i, int* __restrict__ off_i,
            const int* __restrict__ cnt_u, int* __restrict__ off_u, int n)
{
    const int* cnt = blockIdx.x == 0 ? cnt_i : cnt_u;
    int* off = blockIdx.x == 0 ? off_i : off_u;
    __shared__ int sdata[1024];
    __shared__ int carry;
    int tid = threadIdx.x;
    if (tid == 0) carry = 0;
    __syncthreads();
    for (int base = 0; base < n; base += 1024) {
        int i = base + tid;
        int v = (i < n) ? cnt[i] : 0;
        sdata[tid] = v;
        __syncthreads();
        for (int s = 1; s < 1024; s <<= 1) {
            int t = (tid >= s) ? sdata[tid - s] : 0;
            __syncthreads();
            sdata[tid] += t;
            __syncthreads();
        }
        if (i < n) off[i] = carry + sdata[tid] - v;
        __syncthreads();
        if (tid == 1023) carry += sdata[1023];
        __syncthreads();
    }
}

__global__ void fill_kernel(const int* __restrict__ gi_s, const int* __restrict__ gi_d,
                            const int* __restrict__ gu_s, const int* __restrict__ gu_d,
                            const int* __restrict__ off_i, const int* __restrict__ off_u,
                            int* __restrict__ pos_i, int* __restrict__ pos_u,
                            int* __restrict__ nbr_i, int* __restrict__ nbr_u)
{
    int i = blockIdx.x * blockDim.x + threadIdx.x;
    if (i < EGIc) {
        int g = __ldg(gi_s + i);
        int p = atomicAdd(pos_i + g, 1);
        nbr_i[__ldg(off_i + g) + p] = __ldg(gi_d + i);
    } else if (i < EGIc + EGUc) {
        int e = i - EGIc;
        int g = __ldg(gu_s + e);
        int p = atomicAdd(pos_u + g, 1);
        nbr_u[__ldg(off_u + g) + p] = __ldg(gu_d + e);
    }
}

// ===== gather-aggregate: one warp per (group, relation); mean -> fp16 into X ====
__global__ void aggregate_kernel(const int* __restrict__ off_i, const int* __restrict__ nbr_i,
                                 const int* __restrict__ cnt_i, const uint2* __restrict__ fi,
                                 const int* __restrict__ off_u, const int* __restrict__ nbr_u,
                                 const int* __restrict__ cnt_u, const uint2* __restrict__ fu,
                                 __half* __restrict__ X, int ldx)
{
    int gw = (blockIdx.x * blockDim.x + threadIdx.x) >> 5;
    int lane = threadIdx.x & 31;
    if (gw >= 2 * NGc) return;
    bool isU = gw >= NGc;
    int g = isU ? gw - NGc : gw;
    const int* off = isU ? off_u : off_i;
    const int* nbr = isU ? nbr_u : nbr_i;
    const int* cnt = isU ? cnt_u : cnt_i;
    const uint2* f = isU ? fu : fi;

    int base = __ldg(off + g);
    int deg = __ldg(cnt + g);
    float4 acc = make_float4(0.f, 0.f, 0.f, 0.f);
    int j = 0;
    for (; j + 4 <= deg; j += 4) {
        int i0 = __ldg(nbr + base + j);
        int i1 = __ldg(nbr + base + j + 1);
        int i2 = __ldg(nbr + base + j + 2);
        int i3 = __ldg(nbr + base + j + 3);
        uint2 r0 = __ldg(f + (size_t)i0 * 32 + lane);
        uint2 r1 = __ldg(f + (size_t)i1 * 32 + lane);
        uint2 r2 = __ldg(f + (size_t)i2 * 32 + lane);
        uint2 r3 = __ldg(f + (size_t)i3 * 32 + lane);
        float4 v0 = h4_to_f4(r0), v1 = h4_to_f4(r1), v2 = h4_to_f4(r2), v3 = h4_to_f4(r3);
        acc.x += (v0.x + v1.x) + (v2.x + v3.x);
        acc.y += (v0.y + v1.y) + (v2.y + v3.y);
        acc.z += (v0.z + v1.z) + (v2.z + v3.z);
        acc.w += (v0.w + v1.w) + (v2.w + v3.w);
    }
    for (; j < deg; j++) {
        int i0 = __ldg(nbr + base + j);
        float4 v0 = h4_to_f4(__ldg(f + (size_t)i0 * 32 + lane));
        acc.x += v0.x; acc.y += v0.y; acc.z += v0.z; acc.w += v0.w;
    }
    float inv = 1.f / (float)max(deg, 1);
    acc.x *= inv; acc.y *= inv; acc.z *= inv; acc.w *= inv;
    *(uint2*)(X + (size_t)g * ldx + (isU ? 128 : 0) + lane * 4) = f4_to_h4(acc);
}

// ================= fp16 HMMA building block =====================================
__device__ __forceinline__ void mma16816(float* c, const uint32_t* a, const uint32_t* b)
{
    asm volatile(
        "mma.sync.aligned.m16n8k16.row.col.f32.f16.f16.f32 "
        "{%0,%1,%2,%3}, {%4,%5,%6,%7}, {%8,%9}, {%0,%1,%2,%3};\n"
        : "+f"(c[0]), "+f"(c[1]), "+f"(c[2]), "+f"(c[3])
        : "r"(a[0]), "r"(a[1]), "r"(a[2]), "r"(a[3]), "r"(b[0]), "r"(b[1]));
}

#define SMSTRIDE 136   // halves per smem row (padded)

// ------ generic: out[M,128] = relu(X[M,K] @ Wt[128,K]^T + ba + bb) in fp16 ------
__global__ void __launch_bounds__(256, 2)
gcat_gemm(const __half* __restrict__ X, int ldx, int K,
          const __half* __restrict__ Wt,
          const float* __restrict__ ba, const float* __restrict__ bb,
          __half* __restrict__ out, int ldo, int M)
{
    extern __shared__ __half sm[];
    __half* As = sm;                       // 64 x SMSTRIDE
    __half* Bs = As + 64 * SMSTRIDE;       // 128 x SMSTRIDE

    int tid = threadIdx.x;
    int m0 = blockIdx.x * 64;
    int lane = tid & 31, w = tid >> 5;
    int r = lane >> 2, c2 = (lane & 3) * 2;

    float acc[4][2][4];
#pragma unroll
    for (int i = 0; i < 4; i++)
#pragma unroll
        for (int j = 0; j < 2; j++)
#pragma unroll
            for (int q = 0; q < 4; q++) acc[i][j][q] = 0.f;

    uint4 zz = make_uint4(0, 0, 0, 0);
    for (int k0 = 0; k0 < K; k0 += 128) {
        __syncthreads();
#pragma unroll
        for (int it = 0; it < 4; it++) {
            int idx = tid + it * 256;
            int row = idx >> 4, c8 = (idx & 15) << 3;
            int gm = m0 + row;
            uint4 v = zz;
            if (gm < M) v = *(const uint4*)(X + (size_t)gm * ldx + k0 + c8);
            *(uint4*)(As + row * SMSTRIDE + c8) = v;
        }
#pragma unroll
        for (int it = 0; it < 8; it++) {
            int idx = tid + it * 256;
            int row = idx >> 4, c8 = (idx & 15) << 3;
            *(uint4*)(Bs + row * SMSTRIDE + c8) = *(const uint4*)(Wt + (size_t)row * K + k0 + c8);
        }
        __syncthreads();

#pragma unroll
        for (int ks = 0; ks < 8; ks++) {
            int kb = ks * 16 + c2;
            uint32_t a[4][4], b[2][2];
#pragma unroll
            for (int i = 0; i < 4; i++) {
                const __half* pa = As + (i * 16 + r) * SMSTRIDE + kb;
                a[i][0] = *(const uint32_t*)(pa);
                a[i][1] = *(const uint32_t*)(pa + 8 * SMSTRIDE);
                a[i][2] = *(const uint32_t*)(pa + 8);
                a[i][3] = *(const uint32_t*)(pa + 8 * SMSTRIDE + 8);
            }
#pragma unroll
            for (int j = 0; j < 2; j++) {
                const __half* pb = Bs + (w * 16 + j * 8 + r) * SMSTRIDE + kb;
                b[j][0] = *(const uint32_t*)(pb);
                b[j][1] = *(const uint32_t*)(pb + 8);
            }
#pragma unroll
            for (int i = 0; i < 4; i++)
#pragma unroll
                for (int j = 0; j < 2; j++)
                    mma16816(acc[i][j], a[i], b[j]);
        }
    }

#pragma unroll
    for (int i = 0; i < 4; i++) {
#pragma unroll
        for (int j = 0; j < 2; j++) {
            int m = m0 + i * 16 + r;
            int n = w * 16 + j * 8 + c2;
            float bx = __ldg(ba + n) + __ldg(bb + n);
            float by = __ldg(ba + n + 1) + __ldg(bb + n + 1);
            if (m < M) {
                __half2 h = __floats2half2_rn(fmaxf(acc[i][j][0] + bx, 0.f),
                                              fmaxf(acc[i][j][1] + by, 0.f));
                *(__half2*)(out + (size_t)m * ldo + n) = h;
            }
            if (m + 8 < M) {
                __half2 h = __floats2half2_rn(fmaxf(acc[i][j][2] + bx, 0.f),
                                              fmaxf(acc[i][j][3] + by, 0.f));
                *(__half2*)(out + (size_t)(m + 8) * ldo + n) = h;
            }
        }
    }
}

// ------- merged i1/u1: out = relu(X @ Wt^T + b) fp16, block range picks job -----
__global__ void __launch_bounds__(256, 2)
lin_pair_gemm(const __half* __restrict__ Xi, const __half* __restrict__ Wti,
              const float* __restrict__ bi, __half* __restrict__ outi, int Mi,
              const __half* __restrict__ Xu, const __half* __restrict__ Wtu,
              const float* __restrict__ bu, __half* __restrict__ outu, int Mu)
{
    extern __shared__ __half sm[];
    __half* As = sm;
    __half* Bs = As + 128 * SMSTRIDE;

    int nbI = (Mi + 127) / 128;
    const __half* X;
    const __half* Wt;
    const float* b;
    __half* out;
    int M, m0;
    if ((int)blockIdx.x < nbI) {
        X = Xi; Wt = Wti; b = bi; out = outi; M = Mi; m0 = blockIdx.x * 128;
    } else {
        X = Xu; Wt = Wtu; b = bu; out = outu; M = Mu; m0 = (blockIdx.x - nbI) * 128;
    }

    int tid = threadIdx.x;
    uint4 zz = make_uint4(0, 0, 0, 0);
    for (int idx = tid; idx < 2048; idx += 256) {
        int row = idx >> 4;
        int c8 = (idx & 15) << 3;
        int gm = m0 + row;
        uint4 va = zz;
        if (gm < M) va = *(const uint4*)(X + (size_t)gm * 128 + c8);
        *(uint4*)(As + row * SMSTRIDE + c8) = va;
        *(uint4*)(Bs + row * SMSTRIDE + c8) = *(const uint4*)(Wt + (size_t)row * 128 + c8);
    }
    __syncthreads();

    int lane = tid & 31, w = tid >> 5;
    int wm = w >> 2, wn = w & 3;
    int r = lane >> 2, c2 = (lane & 3) * 2;

    float acc[4][4][4];
#pragma unroll
    for (int i = 0; i < 4; i++)
#pragma unroll
        for (int j = 0; j < 4; j++)
#pragma unroll
            for (int q = 0; q < 4; q++) acc[i][j][q] = 0.f;

#pragma unroll
    for (int ks = 0; ks < 8; ks++) {
        int kb = ks * 16 + c2;
        uint32_t a[4][4], bb[4][2];
#pragma unroll
        for (int i = 0; i < 4; i++) {
            const __half* pa = As + (wm * 64 + i * 16 + r) * SMSTRIDE + kb;
            a[i][0] = *(const uint32_t*)(pa);
            a[i][1] = *(const uint32_t*)(pa + 8 * SMSTRIDE);
            a[i][2] = *(const uint32_t*)(pa + 8);
            a[i][3] = *(const uint32_t*)(pa + 8 * SMSTRIDE + 8);
        }
#pragma unroll
        for (int j = 0; j < 4; j++) {
            const __half* pb = Bs + (wn * 32 + j * 8 + r) * SMSTRIDE + kb;
            bb[j][0] = *(const uint32_t*)(pb);
            bb[j][1] = *(const uint32_t*)(pb + 8);
        }
#pragma unroll
        for (int i = 0; i < 4; i++)
#pragma unroll
            for (int j = 0; j < 4; j++)
                mma16816(acc[i][j], a[i], bb[j]);
    }

#pragma unroll
    for (int i = 0; i < 4; i++) {
#pragma unroll
        for (int j = 0; j < 4; j++) {
            int m = m0 + wm * 64 + i * 16 + r;
            int n = wn * 32 + j * 8 + c2;
            float bx = __ldg(b + n), by = __ldg(b + n + 1);
            if (m < M) {
                __half2 h = __floats2half2_rn(fmaxf(acc[i][j][0] + bx, 0.f),
                                              fmaxf(acc[i][j][1] + by, 0.f));
                *(__half2*)(out + (size_t)m * 128 + n) = h;
            }
            if (m + 8 < M) {
                __half2 h = __floats2half2_rn(fmaxf(acc[i][j][2] + bx, 0.f),
                                              fmaxf(acc[i][j][3] + by, 0.f));
                *(__half2*)(out + (size_t)(m + 8) * 128 + n) = h;
            }
        }
    }
}

// ---------------- fp16 tensor-core final GEMM: C = A @ B^T + bias ---------------
__global__ void __launch_bounds__(256, 2)
gemm_f16(const __half* __restrict__ A, const __half* __restrict__ B,
         const float* __restrict__ bias, float* __restrict__ C, int M, int N)
{
    extern __shared__ __half sm[];
    __half* As = sm;
    __half* Bs = As + 128 * SMSTRIDE;

    int tid = threadIdx.x;
    int m0 = blockIdx.y * 128, n0 = blockIdx.x * 128;

    uint4 zz = make_uint4(0, 0, 0, 0);
    for (int idx = tid; idx < 2048; idx += 256) {
        int row = idx >> 4;
        int c8 = (idx & 15) << 3;
        int gm = m0 + row;
        uint4 va = zz;
        if (gm < M) va = *(const uint4*)(A + (size_t)gm * 128 + c8);
        *(uint4*)(As + row * SMSTRIDE + c8) = va;
        int gn = n0 + row;
        uint4 vb = zz;
        if (gn < N) vb = *(const uint4*)(B + (size_t)gn * 128 + c8);
        *(uint4*)(Bs + row * SMSTRIDE + c8) = vb;
    }
    __syncthreads();

    int lane = tid & 31, w = tid >> 5;
    int wm = w >> 2, wn = w & 3;
    int r = lane >> 2, c2 = (lane & 3) * 2;

    float acc[4][4][4];
#pragma unroll
    for (int i = 0; i < 4; i++)
#pragma unroll
        for (int j = 0; j < 4; j++)
#pragma unroll
            for (int q = 0; q < 4; q++) acc[i][j][q] = 0.f;

#pragma unroll
    for (int ks = 0; ks < 8; ks++) {
        int kb = ks * 16 + c2;
        uint32_t a[4][4], b[4][2];
#pragma unroll
        for (int i = 0; i < 4; i++) {
            const __half* pa = As + (wm * 64 + i * 16 + r) * SMSTRIDE + kb;
            a[i][0] = *(const uint32_t*)(pa);
            a[i][1] = *(const uint32_t*)(pa + 8 * SMSTRIDE);
            a[i][2] = *(const uint32_t*)(pa + 8);
            a[i][3] = *(const uint32_t*)(pa + 8 * SMSTRIDE + 8);
        }
#pragma unroll
        for (int j = 0; j < 4; j++) {
            const __half* pb = Bs + (wn * 32 + j * 8 + r) * SMSTRIDE + kb;
            b[j][0] = *(const uint32_t*)(pb);
            b[j][1] = *(const uint32_t*)(pb + 8);
        }
#pragma unroll
        for (int i = 0; i < 4; i++)
#pragma unroll
            for (int j = 0; j < 4; j++)
                mma16816(acc[i][j], a[i], b[j]);
    }

#pragma unroll
    for (int i = 0; i < 4; i++) {
#pragma unroll
        for (int j = 0; j < 4; j++) {
            int m = m0 + wm * 64 + i * 16 + r;
            int n = n0 + wn * 32 + j * 8 + c2;
            if (n < N) {
                float bx = __ldg(bias + n), by = __ldg(bias + n + 1);
                if (m < M) {
                    float2 o = make_float2(acc[i][j][0] + bx, acc[i][j][1] + by);
                    *(float2*)(C + (size_t)m * N + n) = o;
                }
                if (m + 8 < M) {
                    float2 o = make_float2(acc[i][j][2] + bx, acc[i][j][3] + by);
                    *(float2*)(C + (size_t)(m + 8) * N + n) = o;
                }
            }
        }
    }
}

// ------------------------------ launcher ----------------------------------------
extern "C" void kernel_launch(void* const* d_in, const int* in_sizes, int n_in,
                              void* d_out, int out_size)
{
    const int*   gi_src  = (const int*)d_in[3];
    const int*   gi_dst  = (const int*)d_in[4];
    const int*   gu_src  = (const int*)d_in[5];
    const int*   gu_dst  = (const int*)d_in[6];
    const float* emb_u   = (const float*)d_in[8];
    const float* emb_i   = (const float*)d_in[9];
    const float* Wl1     = (const float*)d_in[10];
    const float* Wr1     = (const float*)d_in[11];
    const float* b1      = (const float*)d_in[12];
    const float* Wl2     = (const float*)d_in[13];
    const float* Wr2     = (const float*)d_in[14];
    const float* b2      = (const float*)d_in[15];
    const float* Wp      = (const float*)d_in[16];
    const float* bp      = (const float*)d_in[17];
    float*       out     = (float*)d_out;

    ZeroRegion* zr;
    int *off_i, *off_u, *nbr_i, *nbr_u;
    __half *embih, *embuh, *wt, *w1c, *w2c, *x1, *x2, *i1h, *u1h, *af, *bf;
    cudaGetSymbolAddress((void**)&zr,     g_zr);
    cudaGetSymbolAddress((void**)&off_i,  g_off_i);
    cudaGetSymbolAddress((void**)&off_u,  g_off_u);
    cudaGetSymbolAddress((void**)&nbr_i,  g_nbr_i);
    cudaGetSymbolAddress((void**)&nbr_u,  g_nbr_u);
    cudaGetSymbolAddress((void**)&embih,  g_embih);
    cudaGetSymbolAddress((void**)&embuh,  g_embuh);
    cudaGetSymbolAddress((void**)&wt,     g_Wt);
    cudaGetSymbolAddress((void**)&w1c,    g_W1c);
    cudaGetSymbolAddress((void**)&w2c,    g_W2c);
    cudaGetSymbolAddress((void**)&x1,     g_X1);
    cudaGetSymbolAddress((void**)&x2,     g_X2);
    cudaGetSymbolAddress((void**)&i1h,    g_i1h);
    cudaGetSymbolAddress((void**)&u1h,    g_u1h);
    cudaGetSymbolAddress((void**)&af,     g_Af);
    cudaGetSymbolAddress((void**)&bf,     g_Bf);

    int* cnt_i = zr->cnt_i;
    int* cnt_u = zr->cnt_u;
    int* pos_i = zr->pos_i;
    int* pos_u = zr->pos_u;

    cudaMemsetAsync(zr, 0, sizeof(ZeroRegion));

    int smemLin  = 2 * 128 * SMSTRIDE * sizeof(__half);
    int smemGcat = (64 + 128) * SMSTRIDE * sizeof(__half);
    cudaFuncSetAttribute(lin_pair_gemm, cudaFuncAttributeMaxDynamicSharedMemorySize, smemLin);
    cudaFuncSetAttribute(gemm_f16,      cudaFuncAttributeMaxDynamicSharedMemorySize, smemLin);
    cudaFuncSetAttribute(gcat_gemm,     cudaFuncAttributeMaxDynamicSharedMemorySize, smemGcat);

    // fused prep: emb->fp16, edge histogram, Wp^T, 7 weight transposes
    prep_kernel<<<PREP_TOTAL, 256>>>((const float4*)emb_i, (const float4*)emb_u,
                                     (uint2*)embih, (uint2*)embuh,
                                     gi_src, gu_src, cnt_i, cnt_u,
                                     Wp, bf, Wr1, Wl1, Wl2, Wr2, wt, w1c, w2c);

    // CSR scan + fill
    scan_kernel<<<2, 1024>>>(cnt_i, off_i, cnt_u, off_u, NGc);
    fill_kernel<<<(EGIc + EGUc + 255) / 256, 256>>>(gi_src, gi_dst, gu_src, gu_dst,
                                                    off_i, off_u, pos_i, pos_u, nbr_i, nbr_u);

    // i1 / u1 merged fp16 tensor GEMM (independent of CSR, after prep)
    int nbI = (NIc + 127) / 128, nbU = (NUc + 127) / 128;
    lin_pair_gemm<<<nbI + nbU, 256, smemLin>>>(embih, wt, b1 + 0 * D, i1h, NIc,
                                               embuh, wt + D * D, b1 + 2 * D, u1h, NUc);

    // layer-1 aggregate -> X1
    aggregate_kernel<<<(2 * NGc * 32 + 255) / 256, 256>>>(off_i, nbr_i, cnt_i, (const uint2*)embih,
                                                          off_u, nbr_u, cnt_u, (const uint2*)embuh,
                                                          x1, 256);

    // g1 = relu(X1 @ W1c^T + b) -> X2 cols 256..383
    gcat_gemm<<<(NGc + 63) / 64, 256, smemGcat>>>(x1, 256, 256, w1c,
                                                  b1 + 1 * D, b1 + 3 * D, x2 + 256, 384, NGc);

    // layer-2 aggregate -> X2 cols 0..255
    aggregate_kernel<<<(2 * NGc * 32 + 255) / 256, 256>>>(off_i, nbr_i, cnt_i, (const uint2*)i1h,
                                                          off_u, nbr_u, cnt_u, (const uint2*)u1h,
                                                          x2, 384);

    // g2 = relu(X2 @ W2c^T + b) -> af
    gcat_gemm<<<(NGc + 63) / 64, 256, smemGcat>>>(x2, 384, 384, w2c,
                                                  b2 + 1 * D, b2 + 3 * D, af, 128, NGc);

    // out = g2 @ WpT^T + bp  via fp16 tensor GEMM
    dim3 grid((NIc + 127) / 128, (NGc + 127) / 128);
    gemm_f16<<<grid, 256, smemLin>>>(af, bf, bp, out, NGc, NIc);
}

// round 11
// speedup vs baseline: 3.4674x; 1.3034x over previous
#include <cuda_runtime.h>
#include <cuda_fp16.h>
#include <cstdint>

#define D    128
#define NGc  10000
#define NUc  100000
#define NIc  20000
#define EGIc 400000
#define EGUc 400000

// ---------------- scratch (device globals; no allocation allowed) -------------
struct ZeroRegion {
    int cnt_i[NGc];
    int cnt_u[NGc];
    int pos_i[NGc];
    int pos_u[NGc];
};
__device__ ZeroRegion g_zr;

__device__ int    g_off_i[NGc];
__device__ int    g_off_u[NGc];
__device__ int    g_nbr_i[EGIc];
__device__ int    g_nbr_u[EGUc];
__device__ __half g_embih[NIc * D];
__device__ __half g_embuh[NUc * D];
__device__ __half g_Wt[2 * D * D];      // Wr1[0]^T, Wr1[2]^T fp16
__device__ __half g_W1c[D * 256];       // [Wl1[1];Wl1[3]]^T
__device__ __half g_W2c[D * 384];       // [Wl2[1];Wl2[3];Wr2[1]+Wr2[3]]^T
__device__ __half g_X1[NGc * 256];      // [aggI, aggU] fp16
__device__ __half g_X2[NGc * 384];      // [agg2I, agg2U, g1] fp16
__device__ __half g_i1h[NIc * D];
__device__ __half g_u1h[NUc * D];
__device__ __half g_Af[NGc * D];        // g2 fp16
__device__ __half g_Bf[NIc * D];        // WpT fp16: [n][k]

// ---------------- helpers -------------------------------------------------------
__device__ __forceinline__ float4 h4_to_f4(uint2 r)
{
    __half2 a = *(__half2*)&r.x;
    __half2 b = *(__half2*)&r.y;
    float2 fa = __half22float2(a), fb = __half22float2(b);
    return make_float4(fa.x, fa.y, fb.x, fb.y);
}
__device__ __forceinline__ uint2 f4_to_h4(float4 v)
{
    __half2 a = __floats2half2_rn(v.x, v.y);
    __half2 b = __floats2half2_rn(v.z, v.w);
    uint2 r;
    r.x = *(uint32_t*)&a;
    r.y = *(uint32_t*)&b;
    return r;
}

// ================= fused prep: emb convert + hist + Wp^T + 7 weight^T ===========
#define PREP_EMB_BLK  ((NIc + NUc) * 32 / 256)          // 15000
#define PREP_HIST_BLK ((EGIc + EGUc + 255) / 256)       // 3125
#define PREP_WP_BLK   ((NIc / 32) * (D / 32))           // 2500
#define PREP_WB_BLK   (4 * 4 * 7)                       // 112
#define PREP_TOTAL    (PREP_EMB_BLK + PREP_HIST_BLK + PREP_WP_BLK + PREP_WB_BLK)

__global__ void prep_kernel(const float4* __restrict__ xi, const float4* __restrict__ xu,
                            uint2* __restrict__ yi, uint2* __restrict__ yu,
                            const int* __restrict__ gi_s, const int* __restrict__ gu_s,
                            int* __restrict__ cnt_i, int* __restrict__ cnt_u,
                            const float* __restrict__ Wp, __half* __restrict__ bf,
                            const float* __restrict__ Wr1, const float* __restrict__ Wl1,
                            const float* __restrict__ Wl2, const float* __restrict__ Wr2,
                            __half* __restrict__ wt, __half* __restrict__ w1c,
                            __half* __restrict__ w2c)
{
    __shared__ float t[32][33];
    int b = blockIdx.x;
    int tid = threadIdx.x;

    if (b < PREP_EMB_BLK) {
        int i = b * 256 + tid;
        const int NI4 = NIc * 32;
        if (i < NI4) yi[i] = f4_to_h4(xi[i]);
        else         yu[i - NI4] = f4_to_h4(xu[i - NI4]);
        return;
    }
    b -= PREP_EMB_BLK;
    if (b < PREP_HIST_BLK) {
        int i = b * 256 + tid;
        if (i < EGIc) atomicAdd(cnt_i + __ldg(gi_s + i), 1);
        else if (i < EGIc + EGUc) atomicAdd(cnt_u + __ldg(gu_s + i - EGIc), 1);
        return;
    }
    b -= PREP_HIST_BLK;
    int tx = tid & 31, ty = tid >> 5;
    if (b < PREP_WP_BLK) {
        int n0 = (b % (NIc / 32)) * 32;
        int k0 = (b / (NIc / 32)) * 32;
#pragma unroll
        for (int r = ty; r < 32; r += 8)
            t[r][tx] = Wp[(size_t)(k0 + r) * NIc + n0 + tx];
        __syncthreads();
#pragma unroll
        for (int r = ty; r < 32; r += 8)
            bf[(size_t)(n0 + r) * D + k0 + tx] = __float2half_rn(t[tx][r]);
        return;
    }
    b -= PREP_WP_BLK;
    {
        int job = b >> 4;
        int cx = b & 3, cy = (b >> 2) & 3;
        const float* src = nullptr;
        const float* src2 = nullptr;
        __half* dst = nullptr;
        int ldw = 128, koff = 0;
        switch (job) {
            case 0: src = Wr1;               dst = wt;          ldw = 128; koff = 0;   break;
            case 1: src = Wr1 + 2 * D * D;   dst = wt + D * D;  ldw = 128; koff = 0;   break;
            case 2: src = Wl1 + 1 * D * D;   dst = w1c;         ldw = 256; koff = 0;   break;
            case 3: src = Wl1 + 3 * D * D;   dst = w1c;         ldw = 256; koff = 128; break;
            case 4: src = Wl2 + 1 * D * D;   dst = w2c;         ldw = 384; koff = 0;   break;
            case 5: src = Wl2 + 3 * D * D;   dst = w2c;         ldw = 384; koff = 128; break;
            default: src = Wr2 + 1 * D * D;  src2 = Wr2 + 3 * D * D; dst = w2c; ldw = 384; koff = 256; break;
        }
        int c0 = cx * 32, k0 = cy * 32;
#pragma unroll
        for (int r = ty; r < 32; r += 8) {
            float v = src[(k0 + r) * D + c0 + tx];
            if (src2) v += src2[(k0 + r) * D + c0 + tx];
            t[r][tx] = v;
        }
        __syncthreads();
#pragma unroll
        for (int r = ty; r < 32; r += 8)
            dst[(size_t)(c0 + r) * ldw + koff + k0 + tx] = __float2half_rn(t[tx][r]);
    }
}

// ================= CSR scan + fill ==============================================
__global__ void __launch_bounds__(1024, 1)
scan_kernel(const int* __restrict__ cnt_i, int* __restrict__ off_i,
            const int* __restrict__ cnt_u, int* __restrict__ off_u, int n)
{
    const int* cnt = blockIdx.x == 0 ? cnt_i : cnt_u;
    int* off = blockIdx.x == 0 ? off_i : off_u;
    __shared__ int sdata[1024];
    __shared__ int carry;
    int tid = threadIdx.x;
    if (tid == 0) carry = 0;
    __syncthreads();
    for (int base = 0; base < n; base += 1024) {
        int i = base + tid;
        int v = (i < n) ? cnt[i] : 0;
        sdata[tid] = v;
        __syncthreads();
        for (int s = 1; s < 1024; s <<= 1) {
            int t = (tid >= s) ? sdata[tid - s] : 0;
            __syncthreads();
            sdata[tid] += t;
            __syncthreads();
        }
        if (i < n) off[i] = carry + sdata[tid] - v;
        __syncthreads();
        if (tid == 1023) carry += sdata[1023];
        __syncthreads();
    }
}

__global__ void fill_kernel(const int* __restrict__ gi_s, const int* __restrict__ gi_d,
                            const int* __restrict__ gu_s, const int* __restrict__ gu_d,
                            const int* __restrict__ off_i, const int* __restrict__ off_u,
                            int* __restrict__ pos_i, int* __restrict__ pos_u,
                            int* __restrict__ nbr_i, int* __restrict__ nbr_u)
{
    int i = blockIdx.x * blockDim.x + threadIdx.x;
    if (i < EGIc) {
        int g = __ldg(gi_s + i);
        int p = atomicAdd(pos_i + g, 1);
        nbr_i[__ldg(off_i + g) + p] = __ldg(gi_d + i);
    } else if (i < EGIc + EGUc) {
        int e = i - EGIc;
        int g = __ldg(gu_s + e);
        int p = atomicAdd(pos_u + g, 1);
        nbr_u[__ldg(off_u + g) + p] = __ldg(gu_d + e);
    }
}

// ===== gather-aggregate: one warp per (group, relation); mean -> fp16 into X ====
__global__ void aggregate_kernel(const int* __restrict__ off_i, const int* __restrict__ nbr_i,
                                 const int* __restrict__ cnt_i, const uint2* __restrict__ fi,
                                 const int* __restrict__ off_u, const int* __restrict__ nbr_u,
                                 const int* __restrict__ cnt_u, const uint2* __restrict__ fu,
                                 __half* __restrict__ X, int ldx)
{
    int gw = (blockIdx.x * blockDim.x + threadIdx.x) >> 5;
    int lane = threadIdx.x & 31;
    if (gw >= 2 * NGc) return;
    bool isU = gw >= NGc;
    int g = isU ? gw - NGc : gw;
    const int* off = isU ? off_u : off_i;
    const int* nbr = isU ? nbr_u : nbr_i;
    const int* cnt = isU ? cnt_u : cnt_i;
    const uint2* f = isU ? fu : fi;

    int base = __ldg(off + g);
    int deg = __ldg(cnt + g);
    float4 acc = make_float4(0.f, 0.f, 0.f, 0.f);
    int j = 0;
    for (; j + 4 <= deg; j += 4) {
        int i0 = __ldg(nbr + base + j);
        int i1 = __ldg(nbr + base + j + 1);
        int i2 = __ldg(nbr + base + j + 2);
        int i3 = __ldg(nbr + base + j + 3);
        uint2 r0 = __ldg(f + (size_t)i0 * 32 + lane);
        uint2 r1 = __ldg(f + (size_t)i1 * 32 + lane);
        uint2 r2 = __ldg(f + (size_t)i2 * 32 + lane);
        uint2 r3 = __ldg(f + (size_t)i3 * 32 + lane);
        float4 v0 = h4_to_f4(r0), v1 = h4_to_f4(r1), v2 = h4_to_f4(r2), v3 = h4_to_f4(r3);
        acc.x += (v0.x + v1.x) + (v2.x + v3.x);
        acc.y += (v0.y + v1.y) + (v2.y + v3.y);
        acc.z += (v0.z + v1.z) + (v2.z + v3.z);
        acc.w += (v0.w + v1.w) + (v2.w + v3.w);
    }
    for (; j < deg; j++) {
        int i0 = __ldg(nbr + base + j);
        float4 v0 = h4_to_f4(__ldg(f + (size_t)i0 * 32 + lane));
        acc.x += v0.x; acc.y += v0.y; acc.z += v0.z; acc.w += v0.w;
    }
    float inv = 1.f / (float)max(deg, 1);
    acc.x *= inv; acc.y *= inv; acc.z *= inv; acc.w *= inv;
    *(uint2*)(X + (size_t)g * ldx + (isU ? 128 : 0) + lane * 4) = f4_to_h4(acc);
}

// ================= fp16 HMMA building blocks ====================================
__device__ __forceinline__ void mma16816(float* c, const uint32_t* a, const uint32_t* b)
{
    asm volatile(
        "mma.sync.aligned.m16n8k16.row.col.f32.f16.f16.f32 "
        "{%0,%1,%2,%3}, {%4,%5,%6,%7}, {%8,%9}, {%0,%1,%2,%3};\n"
        : "+f"(c[0]), "+f"(c[1]), "+f"(c[2]), "+f"(c[3])
        : "r"(a[0]), "r"(a[1]), "r"(a[2]), "r"(a[3]), "r"(b[0]), "r"(b[1]));
}
__device__ __forceinline__ void ldsm_x4(uint32_t* r, uint32_t addr)
{
    asm volatile("ldmatrix.sync.aligned.m8n8.x4.shared.b16 {%0,%1,%2,%3}, [%4];"
                 : "=r"(r[0]), "=r"(r[1]), "=r"(r[2]), "=r"(r[3]) : "r"(addr));
}
__device__ __forceinline__ void cp16(uint32_t dst, const void* src, bool pred)
{
    asm volatile("cp.async.ca.shared.global [%0], [%1], 16, %2;"
                 :: "r"(dst), "l"(src), "r"(pred ? 16 : 0));
}
#define CP_COMMIT() asm volatile("cp.async.commit_group;" ::: "memory")
#define CP_WAIT(n)  asm volatile("cp.async.wait_group %0;" :: "n"(n) : "memory")

#define SMSTRIDE 136   // halves per smem row (padded) — legacy kernels
#define CSTRIDE  72    // halves per row in pipelined chunk buffers (144B)

// ------ generic: out[M,128] = relu(X[M,K] @ Wt[128,K]^T + ba + bb) in fp16 ------
__global__ void __launch_bounds__(256, 2)
gcat_gemm(const __half* __restrict__ X, int ldx, int K,
          const __half* __restrict__ Wt,
          const float* __restrict__ ba, const float* __restrict__ bb,
          __half* __restrict__ out, int ldo, int M)
{
    extern __shared__ __half sm[];
    __half* As = sm;                       // 64 x SMSTRIDE
    __half* Bs = As + 64 * SMSTRIDE;       // 128 x SMSTRIDE

    int tid = threadIdx.x;
    int m0 = blockIdx.x * 64;
    int lane = tid & 31, w = tid >> 5;
    int r = lane >> 2, c2 = (lane & 3) * 2;

    float acc[4][2][4];
#pragma unroll
    for (int i = 0; i < 4; i++)
#pragma unroll
        for (int j = 0; j < 2; j++)
#pragma unroll
            for (int q = 0; q < 4; q++) acc[i][j][q] = 0.f;

    uint4 zz = make_uint4(0, 0, 0, 0);
    for (int k0 = 0; k0 < K; k0 += 128) {
        __syncthreads();
#pragma unroll
        for (int it = 0; it < 4; it++) {
            int idx = tid + it * 256;
            int row = idx >> 4, c8 = (idx & 15) << 3;
            int gm = m0 + row;
            uint4 v = zz;
            if (gm < M) v = *(const uint4*)(X + (size_t)gm * ldx + k0 + c8);
            *(uint4*)(As + row * SMSTRIDE + c8) = v;
        }
#pragma unroll
        for (int it = 0; it < 8; it++) {
            int idx = tid + it * 256;
            int row = idx >> 4, c8 = (idx & 15) << 3;
            *(uint4*)(Bs + row * SMSTRIDE + c8) = *(const uint4*)(Wt + (size_t)row * K + k0 + c8);
        }
        __syncthreads();

#pragma unroll
        for (int ks = 0; ks < 8; ks++) {
            int kb = ks * 16 + c2;
            uint32_t a[4][4], b[2][2];
#pragma unroll
            for (int i = 0; i < 4; i++) {
                const __half* pa = As + (i * 16 + r) * SMSTRIDE + kb;
                a[i][0] = *(const uint32_t*)(pa);
                a[i][1] = *(const uint32_t*)(pa + 8 * SMSTRIDE);
                a[i][2] = *(const uint32_t*)(pa + 8);
                a[i][3] = *(const uint32_t*)(pa + 8 * SMSTRIDE + 8);
            }
#pragma unroll
            for (int j = 0; j < 2; j++) {
                const __half* pb = Bs + (w * 16 + j * 8 + r) * SMSTRIDE + kb;
                b[j][0] = *(const uint32_t*)(pb);
                b[j][1] = *(const uint32_t*)(pb + 8);
            }
#pragma unroll
            for (int i = 0; i < 4; i++)
#pragma unroll
                for (int j = 0; j < 2; j++)
                    mma16816(acc[i][j], a[i], b[j]);
        }
    }

#pragma unroll
    for (int i = 0; i < 4; i++) {
#pragma unroll
        for (int j = 0; j < 2; j++) {
            int m = m0 + i * 16 + r;
            int n = w * 16 + j * 8 + c2;
            float bx = __ldg(ba + n) + __ldg(bb + n);
            float by = __ldg(ba + n + 1) + __ldg(bb + n + 1);
            if (m < M) {
                __half2 h = __floats2half2_rn(fmaxf(acc[i][j][0] + bx, 0.f),
                                              fmaxf(acc[i][j][1] + by, 0.f));
                *(__half2*)(out + (size_t)m * ldo + n) = h;
            }
            if (m + 8 < M) {
                __half2 h = __floats2half2_rn(fmaxf(acc[i][j][2] + bx, 0.f),
                                              fmaxf(acc[i][j][3] + by, 0.f));
                *(__half2*)(out + (size_t)(m + 8) * ldo + n) = h;
            }
        }
    }
}

// ------- merged i1/u1: out = relu(X @ Wt^T + b) fp16, block range picks job -----
__global__ void __launch_bounds__(256, 2)
lin_pair_gemm(const __half* __restrict__ Xi, const __half* __restrict__ Wti,
              const float* __restrict__ bi, __half* __restrict__ outi, int Mi,
              const __half* __restrict__ Xu, const __half* __restrict__ Wtu,
              const float* __restrict__ bu, __half* __restrict__ outu, int Mu)
{
    extern __shared__ __half sm[];
    __half* As = sm;
    __half* Bs = As + 128 * SMSTRIDE;

    int nbI = (Mi + 127) / 128;
    const __half* X;
    const __half* Wt;
    const float* b;
    __half* out;
    int M, m0;
    if ((int)blockIdx.x < nbI) {
        X = Xi; Wt = Wti; b = bi; out = outi; M = Mi; m0 = blockIdx.x * 128;
    } else {
        X = Xu; Wt = Wtu; b = bu; out = outu; M = Mu; m0 = (blockIdx.x - nbI) * 128;
    }

    int tid = threadIdx.x;
    uint4 zz = make_uint4(0, 0, 0, 0);
    for (int idx = tid; idx < 2048; idx += 256) {
        int row = idx >> 4;
        int c8 = (idx & 15) << 3;
        int gm = m0 + row;
        uint4 va = zz;
        if (gm < M) va = *(const uint4*)(X + (size_t)gm * 128 + c8);
        *(uint4*)(As + row * SMSTRIDE + c8) = va;
        *(uint4*)(Bs + row * SMSTRIDE + c8) = *(const uint4*)(Wt + (size_t)row * 128 + c8);
    }
    __syncthreads();

    int lane = tid & 31, w = tid >> 5;
    int wm = w >> 2, wn = w & 3;
    int r = lane >> 2, c2 = (lane & 3) * 2;

    float acc[4][4][4];
#pragma unroll
    for (int i = 0; i < 4; i++)
#pragma unroll
        for (int j = 0; j < 4; j++)
#pragma unroll
            for (int q = 0; q < 4; q++) acc[i][j][q] = 0.f;

#pragma unroll
    for (int ks = 0; ks < 8; ks++) {
        int kb = ks * 16 + c2;
        uint32_t a[4][4], bb[4][2];
#pragma unroll
        for (int i = 0; i < 4; i++) {
            const __half* pa = As + (wm * 64 + i * 16 + r) * SMSTRIDE + kb;
            a[i][0] = *(const uint32_t*)(pa);
            a[i][1] = *(const uint32_t*)(pa + 8 * SMSTRIDE);
            a[i][2] = *(const uint32_t*)(pa + 8);
            a[i][3] = *(const uint32_t*)(pa + 8 * SMSTRIDE + 8);
        }
#pragma unroll
        for (int j = 0; j < 4; j++) {
            const __half* pb = Bs + (wn * 32 + j * 8 + r) * SMSTRIDE + kb;
            bb[j][0] = *(const uint32_t*)(pb);
            bb[j][1] = *(const uint32_t*)(pb + 8);
        }
#pragma unroll
        for (int i = 0; i < 4; i++)
#pragma unroll
            for (int j = 0; j < 4; j++)
                mma16816(acc[i][j], a[i], bb[j]);
    }

#pragma unroll
    for (int i = 0; i < 4; i++) {
#pragma unroll
        for (int j = 0; j < 4; j++) {
            int m = m0 + wm * 64 + i * 16 + r;
            int n = wn * 32 + j * 8 + c2;
            float bx = __ldg(b + n), by = __ldg(b + n + 1);
            if (m < M) {
                __half2 h = __floats2half2_rn(fmaxf(acc[i][j][0] + bx, 0.f),
                                              fmaxf(acc[i][j][1] + by, 0.f));
                *(__half2*)(out + (size_t)m * 128 + n) = h;
            }
            if (m + 8 < M) {
                __half2 h = __floats2half2_rn(fmaxf(acc[i][j][2] + bx, 0.f),
                                              fmaxf(acc[i][j][3] + by, 0.f));
                *(__half2*)(out + (size_t)(m + 8) * 128 + n) = h;
            }
        }
    }
}

// ====== final GEMM: cp.async double-buffered K-split + ldmatrix fragments =======
// C[M,N] = A[M,128] @ B[N,128]^T + bias.  Tile 128x128, K in 2 chunks of 64.
__global__ void __launch_bounds__(256, 2)
gemm_f16(const __half* __restrict__ A, const __half* __restrict__ B,
         const float* __restrict__ bias, float* __restrict__ C, int M, int N)
{
    extern __shared__ __half sm[];
    // layout: A0 | A1 | B0 | B1, each 128 x CSTRIDE halves
    int tid = threadIdx.x;
    int m0 = blockIdx.y * 128, n0 = blockIdx.x * 128;
    uint32_t smb = (uint32_t)__cvta_generic_to_shared(sm);
    const uint32_t BUF = 128 * CSTRIDE * 2;   // bytes per buffer

    // ---- prefetch both K-chunks (chunk kc -> buffer kc) ----
#pragma unroll
    for (int kc = 0; kc < 2; kc++) {
        uint32_t aB = smb + kc * BUF;
        uint32_t bB = smb + (2 + kc) * BUF;
#pragma unroll
        for (int it = 0; it < 4; it++) {
            int idx = tid + it * 256;          // 0..1023
            int row = idx >> 3, c16 = idx & 7;
            int gm = m0 + row;
            bool ok = gm < M;
            const __half* src = A + (size_t)(ok ? gm : 0) * 128 + kc * 64 + c16 * 8;
            cp16(aB + row * (CSTRIDE * 2) + c16 * 16, src, ok);
        }
#pragma unroll
        for (int it = 0; it < 4; it++) {
            int idx = tid + it * 256;
            int row = idx >> 3, c16 = idx & 7;
            int gn = n0 + row;
            bool ok = gn < N;
            const __half* src = B + (size_t)(ok ? gn : 0) * 128 + kc * 64 + c16 * 8;
            cp16(bB + row * (CSTRIDE * 2) + c16 * 16, src, ok);
        }
        CP_COMMIT();
    }

    int lane = tid & 31, w = tid >> 5;
    int wm = w >> 2, wn = w & 3;               // 2 x 4 warps; warp tile 64 x 32
    int r = lane >> 2, c2 = (lane & 3) * 2;
    int aRow = lane & 15, aKh = lane >> 4;                  // ldmatrix A selectors
    int bRow = ((lane >> 4) & 1) * 8 + (lane & 7);          // ldmatrix B selectors
    int bKh = (lane >> 3) & 1;

    float acc[4][4][4];
#pragma unroll
    for (int i = 0; i < 4; i++)
#pragma unroll
        for (int j = 0; j < 4; j++)
#pragma unroll
            for (int q = 0; q < 4; q++) acc[i][j][q] = 0.f;

#pragma unroll
    for (int kc = 0; kc < 2; kc++) {
        if (kc == 0) CP_WAIT(1);
        else         CP_WAIT(0);
        __syncthreads();

        uint32_t aB = smb + kc * BUF;
        uint32_t bB = smb + (2 + kc) * BUF;
#pragma unroll
        for (int ks = 0; ks < 4; ks++) {
            uint32_t a[4][4], b[4][2];
#pragma unroll
            for (int i = 0; i < 4; i++) {
                uint32_t addr = aB + ((wm * 64 + i * 16 + aRow) * CSTRIDE + ks * 16 + aKh * 8) * 2;
                ldsm_x4(a[i], addr);
            }
#pragma unroll
            for (int jp = 0; jp < 2; jp++) {
                uint32_t addr = bB + ((wn * 32 + jp * 16 + bRow) * CSTRIDE + ks * 16 + bKh * 8) * 2;
                uint32_t rr[4];
                ldsm_x4(rr, addr);
                b[jp * 2][0] = rr[0]; b[jp * 2][1] = rr[1];
                b[jp * 2 + 1][0] = rr[2]; b[jp * 2 + 1][1] = rr[3];
            }
#pragma unroll
            for (int i = 0; i < 4; i++)
#pragma unroll
                for (int j = 0; j < 4; j++)
                    mma16816(acc[i][j], a[i], b[j]);
        }
        if (kc == 0) __syncthreads();   // keep buffers stable until all warps done? buffers disjoint -> not needed, but cheap
    }

#pragma unroll
    for (int i = 0; i < 4; i++) {
#pragma unroll
        for (int j = 0; j < 4; j++) {
            int m = m0 + wm * 64 + i * 16 + r;
            int n = n0 + wn * 32 + j * 8 + c2;
            if (n < N) {
                float bx = __ldg(bias + n), by = __ldg(bias + n + 1);
                if (m < M) {
                    float2 o = make_float2(acc[i][j][0] + bx, acc[i][j][1] + by);
                    *(float2*)(C + (size_t)m * N + n) = o;
                }
                if (m + 8 < M) {
                    float2 o = make_float2(acc[i][j][2] + bx, acc[i][j][3] + by);
                    *(float2*)(C + (size_t)(m + 8) * N + n) = o;
                }
            }
        }
    }
}

// ------------------------------ launcher ----------------------------------------
extern "C" void kernel_launch(void* const* d_in, const int* in_sizes, int n_in,
                              void* d_out, int out_size)
{
    const int*   gi_src  = (const int*)d_in[3];
    const int*   gi_dst  = (const int*)d_in[4];
    const int*   gu_src  = (const int*)d_in[5];
    const int*   gu_dst  = (const int*)d_in[6];
    const float* emb_u   = (const float*)d_in[8];
    const float* emb_i   = (const float*)d_in[9];
    const float* Wl1     = (const float*)d_in[10];
    const float* Wr1     = (const float*)d_in[11];
    const float* b1      = (const float*)d_in[12];
    const float* Wl2     = (const float*)d_in[13];
    const float* Wr2     = (const float*)d_in[14];
    const float* b2      = (const float*)d_in[15];
    const float* Wp      = (const float*)d_in[16];
    const float* bp      = (const float*)d_in[17];
    float*       out     = (float*)d_out;

    ZeroRegion* zr;
    int *off_i, *off_u, *nbr_i, *nbr_u;
    __half *embih, *embuh, *wt, *w1c, *w2c, *x1, *x2, *i1h, *u1h, *af, *bf;
    cudaGetSymbolAddress((void**)&zr,     g_zr);
    cudaGetSymbolAddress((void**)&off_i,  g_off_i);
    cudaGetSymbolAddress((void**)&off_u,  g_off_u);
    cudaGetSymbolAddress((void**)&nbr_i,  g_nbr_i);
    cudaGetSymbolAddress((void**)&nbr_u,  g_nbr_u);
    cudaGetSymbolAddress((void**)&embih,  g_embih);
    cudaGetSymbolAddress((void**)&embuh,  g_embuh);
    cudaGetSymbolAddress((void**)&wt,     g_Wt);
    cudaGetSymbolAddress((void**)&w1c,    g_W1c);
    cudaGetSymbolAddress((void**)&w2c,    g_W2c);
    cudaGetSymbolAddress((void**)&x1,     g_X1);
    cudaGetSymbolAddress((void**)&x2,     g_X2);
    cudaGetSymbolAddress((void**)&i1h,    g_i1h);
    cudaGetSymbolAddress((void**)&u1h,    g_u1h);
    cudaGetSymbolAddress((void**)&af,     g_Af);
    cudaGetSymbolAddress((void**)&bf,     g_Bf);

    int* cnt_i = zr->cnt_i;
    int* cnt_u = zr->cnt_u;
    int* pos_i = zr->pos_i;
    int* pos_u = zr->pos_u;

    cudaMemsetAsync(zr, 0, sizeof(ZeroRegion));

    int smemLin  = 2 * 128 * SMSTRIDE * sizeof(__half);
    int smemGcat = (64 + 128) * SMSTRIDE * sizeof(__half);
    int smemGemm = 4 * 128 * CSTRIDE * sizeof(__half);   // 73728
    cudaFuncSetAttribute(lin_pair_gemm, cudaFuncAttributeMaxDynamicSharedMemorySize, smemLin);
    cudaFuncSetAttribute(gemm_f16,      cudaFuncAttributeMaxDynamicSharedMemorySize, smemGemm);
    cudaFuncSetAttribute(gcat_gemm,     cudaFuncAttributeMaxDynamicSharedMemorySize, smemGcat);

    // fused prep: emb->fp16, edge histogram, Wp^T, 7 weight transposes
    prep_kernel<<<PREP_TOTAL, 256>>>((const float4*)emb_i, (const float4*)emb_u,
                                     (uint2*)embih, (uint2*)embuh,
                                     gi_src, gu_src, cnt_i, cnt_u,
                                     Wp, bf, Wr1, Wl1, Wl2, Wr2, wt, w1c, w2c);

    // CSR scan + fill
    scan_kernel<<<2, 1024>>>(cnt_i, off_i, cnt_u, off_u, NGc);
    fill_kernel<<<(EGIc + EGUc + 255) / 256, 256>>>(gi_src, gi_dst, gu_src, gu_dst,
                                                    off_i, off_u, pos_i, pos_u, nbr_i, nbr_u);

    // i1 / u1 merged fp16 tensor GEMM
    int nbI = (NIc + 127) / 128, nbU = (NUc + 127) / 128;
    lin_pair_gemm<<<nbI + nbU, 256, smemLin>>>(embih, wt, b1 + 0 * D, i1h, NIc,
                                               embuh, wt + D * D, b1 + 2 * D, u1h, NUc);

    // layer-1 aggregate -> X1
    aggregate_kernel<<<(2 * NGc * 32 + 255) / 256, 256>>>(off_i, nbr_i, cnt_i, (const uint2*)embih,
                                                          off_u, nbr_u, cnt_u, (const uint2*)embuh,
                                                          x1, 256);

    // g1 = relu(X1 @ W1c^T + b) -> X2 cols 256..383
    gcat_gemm<<<(NGc + 63) / 64, 256, smemGcat>>>(x1, 256, 256, w1c,
                                                  b1 + 1 * D, b1 + 3 * D, x2 + 256, 384, NGc);

    // layer-2 aggregate -> X2 cols 0..255
    aggregate_kernel<<<(2 * NGc * 32 + 255) / 256, 256>>>(off_i, nbr_i, cnt_i, (const uint2*)i1h,
                                                          off_u, nbr_u, cnt_u, (const uint2*)u1h,
                                                          x2, 384);

    // g2 = relu(X2 @ W2c^T + b) -> af
    gcat_gemm<<<(NGc + 63) / 64, 256, smemGcat>>>(x2, 384, 384, w2c,
                                                  b2 + 1 * D, b2 + 3 * D, af, 128, NGc);

    // out = g2 @ WpT^T + bp  via pipelined fp16 tensor GEMM
    dim3 grid((NIc + 127) / 128, (NGc + 127) / 128);
    gemm_f16<<<grid, 256, smemGemm>>>(af, bf, bp, out, NGc, NIc);
}

// round 12
// speedup vs baseline: 3.5972x; 1.0374x over previous
#include <cuda_runtime.h>
#include <cuda_fp16.h>
#include <cstdint>

#define D    128
#define NGc  10000
#define NUc  100000
#define NIc  20000
#define EGIc 400000
#define EGUc 400000

// ---------------- scratch (device globals; no allocation allowed) -------------
struct ZeroRegion {
    int cnt_i[NGc];
    int cnt_u[NGc];
    int pos_i[NGc];
    int pos_u[NGc];
};
__device__ ZeroRegion g_zr;

__device__ int    g_off_i[NGc];
__device__ int    g_off_u[NGc];
__device__ int    g_nbr_i[EGIc];
__device__ int    g_nbr_u[EGUc];
__device__ __half g_embih[NIc * D];
__device__ __half g_embuh[NUc * D];
__device__ __half g_Wt[2 * D * D];      // Wr1[0]^T, Wr1[2]^T fp16
__device__ __half g_W1c[D * 256];       // [Wl1[1];Wl1[3]]^T
__device__ __half g_W2c[D * 384];       // [Wl2[1];Wl2[3];Wr2[1]+Wr2[3]]^T
__device__ __half g_X1[NGc * 256];      // [aggI, aggU] fp16
__device__ __half g_X2[NGc * 384];      // [agg2I, agg2U, g1] fp16
__device__ __half g_i1h[NIc * D];
__device__ __half g_u1h[NUc * D];
__device__ __half g_Af[NGc * D];        // g2 fp16
__device__ __half g_Bf[NIc * D];        // WpT fp16: [n][k]

// ---------------- helpers -------------------------------------------------------
__device__ __forceinline__ float4 h4_to_f4(uint2 r)
{
    __half2 a = *(__half2*)&r.x;
    __half2 b = *(__half2*)&r.y;
    float2 fa = __half22float2(a), fb = __half22float2(b);
    return make_float4(fa.x, fa.y, fb.x, fb.y);
}
__device__ __forceinline__ uint2 f4_to_h4(float4 v)
{
    __half2 a = __floats2half2_rn(v.x, v.y);
    __half2 b = __floats2half2_rn(v.z, v.w);
    uint2 r;
    r.x = *(uint32_t*)&a;
    r.y = *(uint32_t*)&b;
    return r;
}

// ================= fused prep: emb convert + hist + Wp^T + 7 weight^T ===========
#define PREP_EMB_BLK  ((NIc + NUc) * 32 / 256)          // 15000
#define PREP_HIST_BLK ((EGIc + EGUc + 255) / 256)       // 3125
#define PREP_WP_BLK   ((NIc / 32) * (D / 32))           // 2500
#define PREP_WB_BLK   (4 * 4 * 7)                       // 112
#define PREP_TOTAL    (PREP_EMB_BLK + PREP_HIST_BLK + PREP_WP_BLK + PREP_WB_BLK)

__global__ void prep_kernel(const float4* __restrict__ xi, const float4* __restrict__ xu,
                            uint2* __restrict__ yi, uint2* __restrict__ yu,
                            const int* __restrict__ gi_s, const int* __restrict__ gu_s,
                            int* __restrict__ cnt_i, int* __restrict__ cnt_u,
                            const float* __restrict__ Wp, __half* __restrict__ bf,
                            const float* __restrict__ Wr1, const float* __restrict__ Wl1,
                            const float* __restrict__ Wl2, const float* __restrict__ Wr2,
                            __half* __restrict__ wt, __half* __restrict__ w1c,
                            __half* __restrict__ w2c)
{
    __shared__ float t[32][33];
    int b = blockIdx.x;
    int tid = threadIdx.x;

    if (b < PREP_EMB_BLK) {
        int i = b * 256 + tid;
        const int NI4 = NIc * 32;
        if (i < NI4) yi[i] = f4_to_h4(xi[i]);
        else         yu[i - NI4] = f4_to_h4(xu[i - NI4]);
        return;
    }
    b -= PREP_EMB_BLK;
    if (b < PREP_HIST_BLK) {
        int i = b * 256 + tid;
        if (i < EGIc) atomicAdd(cnt_i + __ldg(gi_s + i), 1);
        else if (i < EGIc + EGUc) atomicAdd(cnt_u + __ldg(gu_s + i - EGIc), 1);
        return;
    }
    b -= PREP_HIST_BLK;
    int tx = tid & 31, ty = tid >> 5;
    if (b < PREP_WP_BLK) {
        int n0 = (b % (NIc / 32)) * 32;
        int k0 = (b / (NIc / 32)) * 32;
#pragma unroll
        for (int r = ty; r < 32; r += 8)
            t[r][tx] = Wp[(size_t)(k0 + r) * NIc + n0 + tx];
        __syncthreads();
#pragma unroll
        for (int r = ty; r < 32; r += 8)
            bf[(size_t)(n0 + r) * D + k0 + tx] = __float2half_rn(t[tx][r]);
        return;
    }
    b -= PREP_WP_BLK;
    {
        int job = b >> 4;
        int cx = b & 3, cy = (b >> 2) & 3;
        const float* src = nullptr;
        const float* src2 = nullptr;
        __half* dst = nullptr;
        int ldw = 128, koff = 0;
        switch (job) {
            case 0: src = Wr1;               dst = wt;          ldw = 128; koff = 0;   break;
            case 1: src = Wr1 + 2 * D * D;   dst = wt + D * D;  ldw = 128; koff = 0;   break;
            case 2: src = Wl1 + 1 * D * D;   dst = w1c;         ldw = 256; koff = 0;   break;
            case 3: src = Wl1 + 3 * D * D;   dst = w1c;         ldw = 256; koff = 128; break;
            case 4: src = Wl2 + 1 * D * D;   dst = w2c;         ldw = 384; koff = 0;   break;
            case 5: src = Wl2 + 3 * D * D;   dst = w2c;         ldw = 384; koff = 128; break;
            default: src = Wr2 + 1 * D * D;  src2 = Wr2 + 3 * D * D; dst = w2c; ldw = 384; koff = 256; break;
        }
        int c0 = cx * 32, k0 = cy * 32;
#pragma unroll
        for (int r = ty; r < 32; r += 8) {
            float v = src[(k0 + r) * D + c0 + tx];
            if (src2) v += src2[(k0 + r) * D + c0 + tx];
            t[r][tx] = v;
        }
        __syncthreads();
#pragma unroll
        for (int r = ty; r < 32; r += 8)
            dst[(size_t)(c0 + r) * ldw + koff + k0 + tx] = __float2half_rn(t[tx][r]);
    }
}

// ================= CSR scan + fill ==============================================
__global__ void __launch_bounds__(1024, 1)
scan_kernel(const int* __restrict__ cnt_i, int* __restrict__ off_i,
            const int* __restrict__ cnt_u, int* __restrict__ off_u, int n)
{
    const int* cnt = blockIdx.x == 0 ? cnt_i : cnt_u;
    int* off = blockIdx.x == 0 ? off_i : off_u;
    __shared__ int sdata[1024];
    __shared__ int carry;
    int tid = threadIdx.x;
    if (tid == 0) carry = 0;
    __syncthreads();
    for (int base = 0; base < n; base += 1024) {
        int i = base + tid;
        int v = (i < n) ? cnt[i] : 0;
        sdata[tid] = v;
        __syncthreads();
        for (int s = 1; s < 1024; s <<= 1) {
            int t = (tid >= s) ? sdata[tid - s] : 0;
            __syncthreads();
            sdata[tid] += t;
            __syncthreads();
        }
        if (i < n) off[i] = carry + sdata[tid] - v;
        __syncthreads();
        if (tid == 1023) carry += sdata[1023];
        __syncthreads();
    }
}

__global__ void fill_kernel(const int* __restrict__ gi_s, const int* __restrict__ gi_d,
                            const int* __restrict__ gu_s, const int* __restrict__ gu_d,
                            const int* __restrict__ off_i, const int* __restrict__ off_u,
                            int* __restrict__ pos_i, int* __restrict__ pos_u,
                            int* __restrict__ nbr_i, int* __restrict__ nbr_u)
{
    int i = blockIdx.x * blockDim.x + threadIdx.x;
    if (i < EGIc) {
        int g = __ldg(gi_s + i);
        int p = atomicAdd(pos_i + g, 1);
        nbr_i[__ldg(off_i + g) + p] = __ldg(gi_d + i);
    } else if (i < EGIc + EGUc) {
        int e = i - EGIc;
        int g = __ldg(gu_s + e);
        int p = atomicAdd(pos_u + g, 1);
        nbr_u[__ldg(off_u + g) + p] = __ldg(gu_d + e);
    }
}

// ===== gather-aggregate: one warp per (group, relation); mean -> fp16 into X ====
__global__ void aggregate_kernel(const int* __restrict__ off_i, const int* __restrict__ nbr_i,
                                 const int* __restrict__ cnt_i, const uint2* __restrict__ fi,
                                 const int* __restrict__ off_u, const int* __restrict__ nbr_u,
                                 const int* __restrict__ cnt_u, const uint2* __restrict__ fu,
                                 __half* __restrict__ X, int ldx)
{
    int gw = (blockIdx.x * blockDim.x + threadIdx.x) >> 5;
    int lane = threadIdx.x & 31;
    if (gw >= 2 * NGc) return;
    bool isU = gw >= NGc;
    int g = isU ? gw - NGc : gw;
    const int* off = isU ? off_u : off_i;
    const int* nbr = isU ? nbr_u : nbr_i;
    const int* cnt = isU ? cnt_u : cnt_i;
    const uint2* f = isU ? fu : fi;

    int base = __ldg(off + g);
    int deg = __ldg(cnt + g);
    float4 acc = make_float4(0.f, 0.f, 0.f, 0.f);
    int j = 0;
    for (; j + 8 <= deg; j += 8) {
        int ii[8];
#pragma unroll
        for (int t = 0; t < 8; t++) ii[t] = __ldg(nbr + base + j + t);
        uint2 rr[8];
#pragma unroll
        for (int t = 0; t < 8; t++) rr[t] = __ldg(f + (size_t)ii[t] * 32 + lane);
#pragma unroll
        for (int t = 0; t < 8; t++) {
            float4 v = h4_to_f4(rr[t]);
            acc.x += v.x; acc.y += v.y; acc.z += v.z; acc.w += v.w;
        }
    }
    for (; j < deg; j++) {
        int i0 = __ldg(nbr + base + j);
        float4 v0 = h4_to_f4(__ldg(f + (size_t)i0 * 32 + lane));
        acc.x += v0.x; acc.y += v0.y; acc.z += v0.z; acc.w += v0.w;
    }
    float inv = 1.f / (float)max(deg, 1);
    acc.x *= inv; acc.y *= inv; acc.z *= inv; acc.w *= inv;
    *(uint2*)(X + (size_t)g * ldx + (isU ? 128 : 0) + lane * 4) = f4_to_h4(acc);
}

// ================= fp16 HMMA building blocks ====================================
__device__ __forceinline__ void mma16816(float* c, const uint32_t* a, const uint32_t* b)
{
    asm volatile(
        "mma.sync.aligned.m16n8k16.row.col.f32.f16.f16.f32 "
        "{%0,%1,%2,%3}, {%4,%5,%6,%7}, {%8,%9}, {%0,%1,%2,%3};\n"
        : "+f"(c[0]), "+f"(c[1]), "+f"(c[2]), "+f"(c[3])
        : "r"(a[0]), "r"(a[1]), "r"(a[2]), "r"(a[3]), "r"(b[0]), "r"(b[1]));
}
__device__ __forceinline__ void ldsm_x4(uint32_t* r, uint32_t addr)
{
    asm volatile("ldmatrix.sync.aligned.m8n8.x4.shared.b16 {%0,%1,%2,%3}, [%4];"
                 : "=r"(r[0]), "=r"(r[1]), "=r"(r[2]), "=r"(r[3]) : "r"(addr));
}
__device__ __forceinline__ void cp16(uint32_t dst, const void* src, bool pred)
{
    asm volatile("cp.async.ca.shared.global [%0], [%1], 16, %2;"
                 :: "r"(dst), "l"(src), "r"(pred ? 16 : 0));
}
#define CP_COMMIT() asm volatile("cp.async.commit_group;" ::: "memory")
#define CP_WAIT(n)  asm volatile("cp.async.wait_group %0;" :: "n"(n) : "memory")

#define SMSTRIDE 136   // halves per smem row (padded) — gcat
#define CSTRIDE  72    // halves per row in pipelined chunk buffers (144B)

// ------ generic: out[M,128] = relu(X[M,K] @ Wt[128,K]^T + ba + bb) in fp16 ------
__global__ void __launch_bounds__(256, 2)
gcat_gemm(const __half* __restrict__ X, int ldx, int K,
          const __half* __restrict__ Wt,
          const float* __restrict__ ba, const float* __restrict__ bb,
          __half* __restrict__ out, int ldo, int M)
{
    extern __shared__ __half sm[];
    __half* As = sm;                       // 64 x SMSTRIDE
    __half* Bs = As + 64 * SMSTRIDE;       // 128 x SMSTRIDE

    int tid = threadIdx.x;
    int m0 = blockIdx.x * 64;
    int lane = tid & 31, w = tid >> 5;
    int r = lane >> 2, c2 = (lane & 3) * 2;

    float acc[4][2][4];
#pragma unroll
    for (int i = 0; i < 4; i++)
#pragma unroll
        for (int j = 0; j < 2; j++)
#pragma unroll
            for (int q = 0; q < 4; q++) acc[i][j][q] = 0.f;

    uint4 zz = make_uint4(0, 0, 0, 0);
    for (int k0 = 0; k0 < K; k0 += 128) {
        __syncthreads();
#pragma unroll
        for (int it = 0; it < 4; it++) {
            int idx = tid + it * 256;
            int row = idx >> 4, c8 = (idx & 15) << 3;
            int gm = m0 + row;
            uint4 v = zz;
            if (gm < M) v = *(const uint4*)(X + (size_t)gm * ldx + k0 + c8);
            *(uint4*)(As + row * SMSTRIDE + c8) = v;
        }
#pragma unroll
        for (int it = 0; it < 8; it++) {
            int idx = tid + it * 256;
            int row = idx >> 4, c8 = (idx & 15) << 3;
            *(uint4*)(Bs + row * SMSTRIDE + c8) = *(const uint4*)(Wt + (size_t)row * K + k0 + c8);
        }
        __syncthreads();

#pragma unroll
        for (int ks = 0; ks < 8; ks++) {
            int kb = ks * 16 + c2;
            uint32_t a[4][4], b[2][2];
#pragma unroll
            for (int i = 0; i < 4; i++) {
                const __half* pa = As + (i * 16 + r) * SMSTRIDE + kb;
                a[i][0] = *(const uint32_t*)(pa);
                a[i][1] = *(const uint32_t*)(pa + 8 * SMSTRIDE);
                a[i][2] = *(const uint32_t*)(pa + 8);
                a[i][3] = *(const uint32_t*)(pa + 8 * SMSTRIDE + 8);
            }
#pragma unroll
            for (int j = 0; j < 2; j++) {
                const __half* pb = Bs + (w * 16 + j * 8 + r) * SMSTRIDE + kb;
                b[j][0] = *(const uint32_t*)(pb);
                b[j][1] = *(const uint32_t*)(pb + 8);
            }
#pragma unroll
            for (int i = 0; i < 4; i++)
#pragma unroll
                for (int j = 0; j < 2; j++)
                    mma16816(acc[i][j], a[i], b[j]);
        }
    }

#pragma unroll
    for (int i = 0; i < 4; i++) {
#pragma unroll
        for (int j = 0; j < 2; j++) {
            int m = m0 + i * 16 + r;
            int n = w * 16 + j * 8 + c2;
            float bx = __ldg(ba + n) + __ldg(bb + n);
            float by = __ldg(ba + n + 1) + __ldg(bb + n + 1);
            if (m < M) {
                __half2 h = __floats2half2_rn(fmaxf(acc[i][j][0] + bx, 0.f),
                                              fmaxf(acc[i][j][1] + by, 0.f));
                *(__half2*)(out + (size_t)m * ldo + n) = h;
            }
            if (m + 8 < M) {
                __half2 h = __floats2half2_rn(fmaxf(acc[i][j][2] + bx, 0.f),
                                              fmaxf(acc[i][j][3] + by, 0.f));
                *(__half2*)(out + (size_t)(m + 8) * ldo + n) = h;
            }
        }
    }
}

// ==== merged i1/u1: pipelined cp.async + ldmatrix; out = relu(X @ Wt^T + b) =====
__global__ void __launch_bounds__(256, 2)
lin_pair_gemm(const __half* __restrict__ Xi, const __half* __restrict__ Wti,
              const float* __restrict__ bi, __half* __restrict__ outi, int Mi,
              const __half* __restrict__ Xu, const __half* __restrict__ Wtu,
              const float* __restrict__ bu, __half* __restrict__ outu, int Mu)
{
    extern __shared__ __half sm[];
    int tid = threadIdx.x;
    int nbI = (Mi + 127) / 128;
    const __half* X;
    const __half* Wt;
    const float* b;
    __half* out;
    int M, m0;
    if ((int)blockIdx.x < nbI) {
        X = Xi; Wt = Wti; b = bi; out = outi; M = Mi; m0 = blockIdx.x * 128;
    } else {
        X = Xu; Wt = Wtu; b = bu; out = outu; M = Mu; m0 = (blockIdx.x - nbI) * 128;
    }

    uint32_t smb = (uint32_t)__cvta_generic_to_shared(sm);
    const uint32_t BUF = 128 * CSTRIDE * 2;

    // prefetch both K-chunks of X and Wt
#pragma unroll
    for (int kc = 0; kc < 2; kc++) {
        uint32_t aB = smb + kc * BUF;
        uint32_t bB = smb + (2 + kc) * BUF;
#pragma unroll
        for (int it = 0; it < 4; it++) {
            int idx = tid + it * 256;
            int row = idx >> 3, c16 = idx & 7;
            int gm = m0 + row;
            bool ok = gm < M;
            const __half* src = X + (size_t)(ok ? gm : 0) * 128 + kc * 64 + c16 * 8;
            cp16(aB + row * (CSTRIDE * 2) + c16 * 16, src, ok);
        }
#pragma unroll
        for (int it = 0; it < 4; it++) {
            int idx = tid + it * 256;
            int row = idx >> 3, c16 = idx & 7;
            const __half* src = Wt + (size_t)row * 128 + kc * 64 + c16 * 8;
            cp16(bB + row * (CSTRIDE * 2) + c16 * 16, src, true);
        }
        CP_COMMIT();
    }

    int lane = tid & 31, w = tid >> 5;
    int wm = w >> 2, wn = w & 3;
    int r = lane >> 2, c2 = (lane & 3) * 2;
    int aRow = lane & 15, aKh = lane >> 4;
    int bRow = ((lane >> 4) & 1) * 8 + (lane & 7);
    int bKh = (lane >> 3) & 1;

    float acc[4][4][4];
#pragma unroll
    for (int i = 0; i < 4; i++)
#pragma unroll
        for (int j = 0; j < 4; j++)
#pragma unroll
            for (int q = 0; q < 4; q++) acc[i][j][q] = 0.f;

#pragma unroll
    for (int kc = 0; kc < 2; kc++) {
        if (kc == 0) CP_WAIT(1);
        else         CP_WAIT(0);
        __syncthreads();

        uint32_t aB = smb + kc * BUF;
        uint32_t bB = smb + (2 + kc) * BUF;
#pragma unroll
        for (int ks = 0; ks < 4; ks++) {
            uint32_t a[4][4], bb[4][2];
#pragma unroll
            for (int i = 0; i < 4; i++) {
                uint32_t addr = aB + ((wm * 64 + i * 16 + aRow) * CSTRIDE + ks * 16 + aKh * 8) * 2;
                ldsm_x4(a[i], addr);
            }
#pragma unroll
            for (int jp = 0; jp < 2; jp++) {
                uint32_t addr = bB + ((wn * 32 + jp * 16 + bRow) * CSTRIDE + ks * 16 + bKh * 8) * 2;
                uint32_t rr[4];
                ldsm_x4(rr, addr);
                bb[jp * 2][0] = rr[0]; bb[jp * 2][1] = rr[1];
                bb[jp * 2 + 1][0] = rr[2]; bb[jp * 2 + 1][1] = rr[3];
            }
#pragma unroll
            for (int i = 0; i < 4; i++)
#pragma unroll
                for (int j = 0; j < 4; j++)
                    mma16816(acc[i][j], a[i], bb[j]);
        }
        if (kc == 0) __syncthreads();
    }

#pragma unroll
    for (int i = 0; i < 4; i++) {
#pragma unroll
        for (int j = 0; j < 4; j++) {
            int m = m0 + wm * 64 + i * 16 + r;
            int n = wn * 32 + j * 8 + c2;
            float bx = __ldg(b + n), by = __ldg(b + n + 1);
            if (m < M) {
                __half2 h = __floats2half2_rn(fmaxf(acc[i][j][0] + bx, 0.f),
                                              fmaxf(acc[i][j][1] + by, 0.f));
                *(__half2*)(out + (size_t)m * 128 + n) = h;
            }
            if (m + 8 < M) {
                __half2 h = __floats2half2_rn(fmaxf(acc[i][j][2] + bx, 0.f),
                                              fmaxf(acc[i][j][3] + by, 0.f));
                *(__half2*)(out + (size_t)(m + 8) * 128 + n) = h;
            }
        }
    }
}

// ====== final GEMM: cp.async double-buffered K-split + ldmatrix fragments =======
__global__ void __launch_bounds__(256, 2)
gemm_f16(const __half* __restrict__ A, const __half* __restrict__ B,
         const float* __restrict__ bias, float* __restrict__ C, int M, int N)
{
    extern __shared__ __half sm[];
    int tid = threadIdx.x;
    int m0 = blockIdx.y * 128, n0 = blockIdx.x * 128;
    uint32_t smb = (uint32_t)__cvta_generic_to_shared(sm);
    const uint32_t BUF = 128 * CSTRIDE * 2;

#pragma unroll
    for (int kc = 0; kc < 2; kc++) {
        uint32_t aB = smb + kc * BUF;
        uint32_t bB = smb + (2 + kc) * BUF;
#pragma unroll
        for (int it = 0; it < 4; it++) {
            int idx = tid + it * 256;
            int row = idx >> 3, c16 = idx & 7;
            int gm = m0 + row;
            bool ok = gm < M;
            const __half* src = A + (size_t)(ok ? gm : 0) * 128 + kc * 64 + c16 * 8;
            cp16(aB + row * (CSTRIDE * 2) + c16 * 16, src, ok);
        }
#pragma unroll
        for (int it = 0; it < 4; it++) {
            int idx = tid + it * 256;
            int row = idx >> 3, c16 = idx & 7;
            int gn = n0 + row;
            bool ok = gn < N;
            const __half* src = B + (size_t)(ok ? gn : 0) * 128 + kc * 64 + c16 * 8;
            cp16(bB + row * (CSTRIDE * 2) + c16 * 16, src, ok);
        }
        CP_COMMIT();
    }

    int lane = tid & 31, w = tid >> 5;
    int wm = w >> 2, wn = w & 3;
    int r = lane >> 2, c2 = (lane & 3) * 2;
    int aRow = lane & 15, aKh = lane >> 4;
    int bRow = ((lane >> 4) & 1) * 8 + (lane & 7);
    int bKh = (lane >> 3) & 1;

    float acc[4][4][4];
#pragma unroll
    for (int i = 0; i < 4; i++)
#pragma unroll
        for (int j = 0; j < 4; j++)
#pragma unroll
            for (int q = 0; q < 4; q++) acc[i][j][q] = 0.f;

#pragma unroll
    for (int kc = 0; kc < 2; kc++) {
        if (kc == 0) CP_WAIT(1);
        else         CP_WAIT(0);
        __syncthreads();

        uint32_t aB = smb + kc * BUF;
        uint32_t bB = smb + (2 + kc) * BUF;
#pragma unroll
        for (int ks = 0; ks < 4; ks++) {
            uint32_t a[4][4], b[4][2];
#pragma unroll
            for (int i = 0; i < 4; i++) {
                uint32_t addr = aB + ((wm * 64 + i * 16 + aRow) * CSTRIDE + ks * 16 + aKh * 8) * 2;
                ldsm_x4(a[i], addr);
            }
#pragma unroll
            for (int jp = 0; jp < 2; jp++) {
                uint32_t addr = bB + ((wn * 32 + jp * 16 + bRow) * CSTRIDE + ks * 16 + bKh * 8) * 2;
                uint32_t rr[4];
                ldsm_x4(rr, addr);
                b[jp * 2][0] = rr[0]; b[jp * 2][1] = rr[1];
                b[jp * 2 + 1][0] = rr[2]; b[jp * 2 + 1][1] = rr[3];
            }
#pragma unroll
            for (int i = 0; i < 4; i++)
#pragma unroll
                for (int j = 0; j < 4; j++)
                    mma16816(acc[i][j], a[i], b[j]);
        }
        if (kc == 0) __syncthreads();
    }

#pragma unroll
    for (int i = 0; i < 4; i++) {
#pragma unroll
        for (int j = 0; j < 4; j++) {
            int m = m0 + wm * 64 + i * 16 + r;
            int n = n0 + wn * 32 + j * 8 + c2;
            if (n < N) {
                float bx = __ldg(bias + n), by = __ldg(bias + n + 1);
                if (m < M) {
                    float2 o = make_float2(acc[i][j][0] + bx, acc[i][j][1] + by);
                    *(float2*)(C + (size_t)m * N + n) = o;
                }
                if (m + 8 < M) {
                    float2 o = make_float2(acc[i][j][2] + bx, acc[i][j][3] + by);
                    *(float2*)(C + (size_t)(m + 8) * N + n) = o;
                }
            }
        }
    }
}

// ------------------------------ launcher ----------------------------------------
extern "C" void kernel_launch(void* const* d_in, const int* in_sizes, int n_in,
                              void* d_out, int out_size)
{
    const int*   gi_src  = (const int*)d_in[3];
    const int*   gi_dst  = (const int*)d_in[4];
    const int*   gu_src  = (const int*)d_in[5];
    const int*   gu_dst  = (const int*)d_in[6];
    const float* emb_u   = (const float*)d_in[8];
    const float* emb_i   = (const float*)d_in[9];
    const float* Wl1     = (const float*)d_in[10];
    const float* Wr1     = (const float*)d_in[11];
    const float* b1      = (const float*)d_in[12];
    const float* Wl2     = (const float*)d_in[13];
    const float* Wr2     = (const float*)d_in[14];
    const float* b2      = (const float*)d_in[15];
    const float* Wp      = (const float*)d_in[16];
    const float* bp      = (const float*)d_in[17];
    float*       out     = (float*)d_out;

    ZeroRegion* zr;
    int *off_i, *off_u, *nbr_i, *nbr_u;
    __half *embih, *embuh, *wt, *w1c, *w2c, *x1, *x2, *i1h, *u1h, *af, *bf;
    cudaGetSymbolAddress((void**)&zr,     g_zr);
    cudaGetSymbolAddress((void**)&off_i,  g_off_i);
    cudaGetSymbolAddress((void**)&off_u,  g_off_u);
    cudaGetSymbolAddress((void**)&nbr_i,  g_nbr_i);
    cudaGetSymbolAddress((void**)&nbr_u,  g_nbr_u);
    cudaGetSymbolAddress((void**)&embih,  g_embih);
    cudaGetSymbolAddress((void**)&embuh,  g_embuh);
    cudaGetSymbolAddress((void**)&wt,     g_Wt);
    cudaGetSymbolAddress((void**)&w1c,    g_W1c);
    cudaGetSymbolAddress((void**)&w2c,    g_W2c);
    cudaGetSymbolAddress((void**)&x1,     g_X1);
    cudaGetSymbolAddress((void**)&x2,     g_X2);
    cudaGetSymbolAddress((void**)&i1h,    g_i1h);
    cudaGetSymbolAddress((void**)&u1h,    g_u1h);
    cudaGetSymbolAddress((void**)&af,     g_Af);
    cudaGetSymbolAddress((void**)&bf,     g_Bf);

    int* cnt_i = zr->cnt_i;
    int* cnt_u = zr->cnt_u;
    int* pos_i = zr->pos_i;
    int* pos_u = zr->pos_u;

    cudaMemsetAsync(zr, 0, sizeof(ZeroRegion));

    int smemGcat = (64 + 128) * SMSTRIDE * sizeof(__half);
    int smemPipe = 4 * 128 * CSTRIDE * sizeof(__half);   // 73728
    cudaFuncSetAttribute(lin_pair_gemm, cudaFuncAttributeMaxDynamicSharedMemorySize, smemPipe);
    cudaFuncSetAttribute(gemm_f16,      cudaFuncAttributeMaxDynamicSharedMemorySize, smemPipe);
    cudaFuncSetAttribute(gcat_gemm,     cudaFuncAttributeMaxDynamicSharedMemorySize, smemGcat);

    // fused prep: emb->fp16, edge histogram, Wp^T, 7 weight transposes
    prep_kernel<<<PREP_TOTAL, 256>>>((const float4*)emb_i, (const float4*)emb_u,
                                     (uint2*)embih, (uint2*)embuh,
                                     gi_src, gu_src, cnt_i, cnt_u,
                                     Wp, bf, Wr1, Wl1, Wl2, Wr2, wt, w1c, w2c);

    // CSR scan + fill
    scan_kernel<<<2, 1024>>>(cnt_i, off_i, cnt_u, off_u, NGc);
    fill_kernel<<<(EGIc + EGUc + 255) / 256, 256>>>(gi_src, gi_dst, gu_src, gu_dst,
                                                    off_i, off_u, pos_i, pos_u, nbr_i, nbr_u);

    // i1 / u1 merged pipelined fp16 tensor GEMM
    int nbI = (NIc + 127) / 128, nbU = (NUc + 127) / 128;
    lin_pair_gemm<<<nbI + nbU, 256, smemPipe>>>(embih, wt, b1 + 0 * D, i1h, NIc,
                                                embuh, wt + D * D, b1 + 2 * D, u1h, NUc);

    // layer-1 aggregate -> X1
    aggregate_kernel<<<(2 * NGc * 32 + 255) / 256, 256>>>(off_i, nbr_i, cnt_i, (const uint2*)embih,
                                                          off_u, nbr_u, cnt_u, (const uint2*)embuh,
                                                          x1, 256);

    // g1 = relu(X1 @ W1c^T + b) -> X2 cols 256..383
    gcat_gemm<<<(NGc + 63) / 64, 256, smemGcat>>>(x1, 256, 256, w1c,
                                                  b1 + 1 * D, b1 + 3 * D, x2 + 256, 384, NGc);

    // layer-2 aggregate -> X2 cols 0..255
    aggregate_kernel<<<(2 * NGc * 32 + 255) / 256, 256>>>(off_i, nbr_i, cnt_i, (const uint2*)i1h,
                                                          off_u, nbr_u, cnt_u, (const uint2*)u1h,
                                                          x2, 384);

    // g2 = relu(X2 @ W2c^T + b) -> af
    gcat_gemm<<<(NGc + 63) / 64, 256, smemGcat>>>(x2, 384, 384, w2c,
                                                  b2 + 1 * D, b2 + 3 * D, af, 128, NGc);

    // out = g2 @ WpT^T + bp  via pipelined fp16 tensor GEMM
    dim3 grid((NIc + 127) / 128, (NGc + 127) / 128);
    gemm_f16<<<grid, 256, smemPipe>>>(af, bf, bp, out, NGc, NIc);
}